// round 4
// baseline (speedup 1.0000x reference)
#include <cuda_runtime.h>

// Shapes (fixed for this problem)
#define BB   16
#define CC   128
#define HIDD 256
#define HH   80
#define WW   80
#define PP   6400      // HH*WW
#define NGG  8
#define EPSV 1e-5f

// ---------------- device scratch (static: allocation-free) ----------------
__device__ float g_s[(size_t)BB * CC * PP];        // conv3x3 output (pre-BN)
__device__ float g_h[(size_t)BB * HIDD * PP];      // expert hidden (pre-GN1)
__device__ float g_y[(size_t)BB * CC * PP];        // expert out (pre-GN2)

__device__ float g_bn_sum[CC], g_bn_sq[CC];
__device__ float g_bn_scale[CC], g_bn_shift[CC];
__device__ float g_gn1_sum[BB * NGG], g_gn1_sq[BB * NGG];
__device__ float g_gn1_mr[BB * NGG * 2];           // mean, rstd interleaved
__device__ float g_gn2_sum[BB * NGG], g_gn2_sq[BB * NGG];
__device__ float g_gn2_mr[BB * NGG * 2];

// ---------------- K0: zero accumulators (graph replays must be deterministic) ----
__global__ void k_zero() {
    int t = threadIdx.x;
    if (t < CC) { g_bn_sum[t] = 0.f; g_bn_sq[t] = 0.f; }
    if (t < BB * NGG) {
        g_gn1_sum[t] = 0.f; g_gn1_sq[t] = 0.f;
        g_gn2_sum[t] = 0.f; g_gn2_sq[t] = 0.f;
    }
}

// ---------------- K1: conv3x3 (SAME pad) + BN partial sums --------------------
// Tile: 64 out-channels x (8 rows x 16 cols) pixels. 256 threads,
// each thread computes 4 oc x 8 px. K loop over input channels in chunks of 8.
__global__ __launch_bounds__(256) void k_conv(const float* __restrict__ x,
                                              const float* __restrict__ w) {
    __shared__ float xs[8 * 190];        // [cc][10 rows][19 pad cols] (18 used)
    __shared__ float ws[8 * 9 * 64];     // [cc][tap][oc64]
    __shared__ float ssum[64], ssq[64];

    const int tid  = threadIdx.x;
    const int b    = blockIdx.z;
    const int oc0  = blockIdx.x * 64;
    const int ty   = blockIdx.y / 5, tx = blockIdx.y % 5;
    const int row0 = ty * 8, col0 = tx * 16;
    const int ocg  = tid >> 4;           // 0..15
    const int pg   = tid & 15;
    const int prow = pg >> 1;            // 0..7
    const int pcol = (pg & 1) * 8;       // 0 or 8

    if (tid < 64) { ssum[tid] = 0.f; ssq[tid] = 0.f; }

    float acc[4][8];
#pragma unroll
    for (int o = 0; o < 4; o++)
#pragma unroll
        for (int j = 0; j < 8; j++) acc[o][j] = 0.f;

    const float* xb = x + (size_t)b * CC * PP;

    for (int c0 = 0; c0 < CC; c0 += 8) {
        // stage input halo tile: 8 ch x 10 x 18
        for (int i = tid; i < 8 * 10 * 18; i += 256) {
            int cc  = i / 180;
            int rem = i - cc * 180;
            int r   = rem / 18;
            int col = rem - r * 18;
            int gr = row0 + r - 1, gc = col0 + col - 1;
            float v = 0.f;
            if ((unsigned)gr < 80u && (unsigned)gc < 80u)
                v = xb[(size_t)(c0 + cc) * PP + gr * 80 + gc];
            xs[cc * 190 + r * 19 + col] = v;
        }
        // stage weights: 8 ch x 9 taps x 64 oc (oc contiguous for float4)
        for (int i = tid; i < 8 * 9 * 64; i += 256) {
            int cc  = i / 576;
            int rem = i - cc * 576;
            int t   = rem >> 6;
            int o   = rem & 63;
            ws[cc * 576 + t * 64 + o] = w[((size_t)(oc0 + o) * CC + c0 + cc) * 9 + t];
        }
        __syncthreads();

        for (int cc = 0; cc < 8; cc++) {
#pragma unroll
            for (int kh = 0; kh < 3; kh++) {
                float xr[10];
#pragma unroll
                for (int j = 0; j < 10; j++)
                    xr[j] = xs[cc * 190 + (prow + kh) * 19 + pcol + j];
#pragma unroll
                for (int kw = 0; kw < 3; kw++) {
                    float4 wv = *(const float4*)&ws[cc * 576 + (kh * 3 + kw) * 64 + ocg * 4];
#pragma unroll
                    for (int j = 0; j < 8; j++) {
                        acc[0][j] = fmaf(wv.x, xr[j + kw], acc[0][j]);
                        acc[1][j] = fmaf(wv.y, xr[j + kw], acc[1][j]);
                        acc[2][j] = fmaf(wv.z, xr[j + kw], acc[2][j]);
                        acc[3][j] = fmaf(wv.w, xr[j + kw], acc[3][j]);
                    }
                }
            }
        }
        __syncthreads();
    }

    // store s + block-level BN partial sums
    const int row = row0 + prow, col = col0 + pcol;
#pragma unroll
    for (int o = 0; o < 4; o++) {
        int oc = oc0 + ocg * 4 + o;
        float* sp = g_s + ((size_t)b * CC + oc) * PP + row * 80 + col;
        *(float4*)sp       = make_float4(acc[o][0], acc[o][1], acc[o][2], acc[o][3]);
        *(float4*)(sp + 4) = make_float4(acc[o][4], acc[o][5], acc[o][6], acc[o][7]);
        float s = 0.f, q = 0.f;
#pragma unroll
        for (int j = 0; j < 8; j++) { s += acc[o][j]; q += acc[o][j] * acc[o][j]; }
        atomicAdd(&ssum[ocg * 4 + o], s);
        atomicAdd(&ssq[ocg * 4 + o], q);
    }
    __syncthreads();
    if (tid < 64) {
        atomicAdd(&g_bn_sum[oc0 + tid], ssum[tid]);
        atomicAdd(&g_bn_sq[oc0 + tid], ssq[tid]);
    }
}

// ---------------- stat finalize kernels ----------------
__global__ void k_fin_bn(const float* __restrict__ gamma, const float* __restrict__ beta) {
    int t = threadIdx.x; // 128
    const float inv = 1.f / (float)(BB * PP);
    float m = g_bn_sum[t] * inv;
    float v = g_bn_sq[t] * inv - m * m;
    float r = rsqrtf(v + EPSV);
    float sc = gamma[t] * r;
    g_bn_scale[t] = sc;
    g_bn_shift[t] = beta[t] - m * sc;
}

__global__ void k_fin_gn1() {
    int t = threadIdx.x; // 128 = BB*NGG
    const float inv = 1.f / (float)((HIDD / NGG) * PP); // 32*6400
    float m = g_gn1_sum[t] * inv;
    float v = g_gn1_sq[t] * inv - m * m;
    g_gn1_mr[2 * t]     = m;
    g_gn1_mr[2 * t + 1] = rsqrtf(v + EPSV);
}

__global__ void k_fin_gn2() {
    int t = threadIdx.x; // 128
    const float inv = 1.f / (float)((CC / NGG) * PP); // 16*6400
    float m = g_gn2_sum[t] * inv;
    float v = g_gn2_sq[t] * inv - m * m;
    g_gn2_mr[2 * t]     = m;
    g_gn2_mr[2 * t + 1] = rsqrtf(v + EPSV);
}

// ---------------- K3: expert GEMM1 (h = w1[e] @ x_b) + GN1 partial sums -------
// Per-batch dynamic expert: block early-exits if indices[b]==0.
// Tile 64 M x 128 N, K chunk 16. 256 threads, each 4x8.
__global__ __launch_bounds__(256) void k_gemm1(const float* __restrict__ x,
                                               const int* __restrict__ indices,
                                               const float* __restrict__ w1) {
    const int b = blockIdx.z;
    const int idx = indices[b];
    if (idx == 0) return;
    const int e = idx - 1;

    __shared__ float As[16 * 68];   // [k][m64] padded
    __shared__ float Bs[16 * 128];  // [k][n128]
    __shared__ float gsum[2], gsq[2];

    const int tid = threadIdx.x;
    const int mg = tid >> 4, ng = tid & 15;
    const int m0 = blockIdx.y * 64;
    const int nb = blockIdx.x * 128;
    if (tid < 2) { gsum[tid] = 0.f; gsq[tid] = 0.f; }

    float acc[4][8];
#pragma unroll
    for (int o = 0; o < 4; o++)
#pragma unroll
        for (int j = 0; j < 8; j++) acc[o][j] = 0.f;

    const float* wbase = w1 + (size_t)e * HIDD * CC;
    const float* xb    = x + (size_t)b * CC * PP;

    for (int k0 = 0; k0 < CC; k0 += 16) {
        for (int i = tid; i < 1024; i += 256) {
            int m = i >> 4, kk = i & 15;
            As[kk * 68 + m] = wbase[(size_t)(m0 + m) * CC + k0 + kk];
        }
        for (int i = tid; i < 2048; i += 256) {
            int kk = i >> 7, n = i & 127;
            Bs[kk * 128 + n] = xb[(size_t)(k0 + kk) * PP + nb + n];
        }
        __syncthreads();
#pragma unroll
        for (int kk = 0; kk < 16; kk++) {
            float4 av  = *(const float4*)&As[kk * 68 + mg * 4];
            float4 bv0 = *(const float4*)&Bs[kk * 128 + ng * 8];
            float4 bv1 = *(const float4*)&Bs[kk * 128 + ng * 8 + 4];
            float a[4]  = {av.x, av.y, av.z, av.w};
            float bb[8] = {bv0.x, bv0.y, bv0.z, bv0.w, bv1.x, bv1.y, bv1.z, bv1.w};
#pragma unroll
            for (int o = 0; o < 4; o++)
#pragma unroll
                for (int j = 0; j < 8; j++)
                    acc[o][j] = fmaf(a[o], bb[j], acc[o][j]);
        }
        __syncthreads();
    }

    // store h + GN1 stats (raw h; GN normalizes raw values)
    float lsum = 0.f, lsq = 0.f;
#pragma unroll
    for (int o = 0; o < 4; o++) {
        float* hp = g_h + ((size_t)b * HIDD + m0 + mg * 4 + o) * PP + nb + ng * 8;
        *(float4*)hp       = make_float4(acc[o][0], acc[o][1], acc[o][2], acc[o][3]);
        *(float4*)(hp + 4) = make_float4(acc[o][4], acc[o][5], acc[o][6], acc[o][7]);
#pragma unroll
        for (int j = 0; j < 8; j++) { lsum += acc[o][j]; lsq += acc[o][j] * acc[o][j]; }
    }
#pragma unroll
    for (int off = 16; off > 0; off >>= 1) {
        lsum += __shfl_down_sync(0xffffffffu, lsum, off);
        lsq  += __shfl_down_sync(0xffffffffu, lsq, off);
    }
    if ((tid & 31) == 0) {
        int grel = (mg * 4) >> 5;  // uniform within warp
        atomicAdd(&gsum[grel], lsum);
        atomicAdd(&gsq[grel], lsq);
    }
    __syncthreads();
    if (tid < 2) {
        int g = (m0 >> 5) + tid;
        atomicAdd(&g_gn1_sum[b * NGG + g], gsum[tid]);
        atomicAdd(&g_gn1_sq[b * NGG + g], gsq[tid]);
    }
}

// ---------------- K5: expert GEMM2 (y = w2[e] @ silu(GN1(h))) + GN2 sums ------
__global__ __launch_bounds__(256) void k_gemm2(const int* __restrict__ indices,
                                               const float* __restrict__ w2,
                                               const float* __restrict__ g1,
                                               const float* __restrict__ b1) {
    const int b = blockIdx.z;
    const int idx = indices[b];
    if (idx == 0) return;
    const int e = idx - 1;

    __shared__ float As[16 * 68];
    __shared__ float Bs[16 * 128];
    __shared__ float sa[HIDD], sb[HIDD];
    __shared__ float gsum[4], gsq[4];

    const int tid = threadIdx.x;
    const int mg = tid >> 4, ng = tid & 15;
    const int m0 = blockIdx.y * 64;
    const int nb = blockIdx.x * 128;

    { // per-k GN1 affine coefficients (fold mean/rstd/gamma/beta)
        int k = tid;            // 256 threads == HIDD
        int gg = k >> 5;
        float mean = g_gn1_mr[(b * NGG + gg) * 2];
        float rstd = g_gn1_mr[(b * NGG + gg) * 2 + 1];
        float a = rstd * g1[e * HIDD + k];
        sa[k] = a;
        sb[k] = b1[e * HIDD + k] - mean * a;
    }
    if (tid < 4) { gsum[tid] = 0.f; gsq[tid] = 0.f; }
    __syncthreads();

    float acc[4][8];
#pragma unroll
    for (int o = 0; o < 4; o++)
#pragma unroll
        for (int j = 0; j < 8; j++) acc[o][j] = 0.f;

    const float* wbase = w2 + (size_t)e * CC * HIDD;
    const float* hb    = g_h + (size_t)b * HIDD * PP;

    for (int k0 = 0; k0 < HIDD; k0 += 16) {
        for (int i = tid; i < 1024; i += 256) {
            int m = i >> 4, kk = i & 15;
            As[kk * 68 + m] = wbase[(size_t)(m0 + m) * HIDD + k0 + kk];
        }
        for (int i = tid; i < 2048; i += 256) {
            int kk = i >> 7, n = i & 127;
            int kg = k0 + kk;
            float t = fmaf(hb[(size_t)kg * PP + nb + n], sa[kg], sb[kg]);
            Bs[kk * 128 + n] = t / (1.f + expf(-t));   // SiLU
        }
        __syncthreads();
#pragma unroll
        for (int kk = 0; kk < 16; kk++) {
            float4 av  = *(const float4*)&As[kk * 68 + mg * 4];
            float4 bv0 = *(const float4*)&Bs[kk * 128 + ng * 8];
            float4 bv1 = *(const float4*)&Bs[kk * 128 + ng * 8 + 4];
            float a[4]  = {av.x, av.y, av.z, av.w};
            float bb[8] = {bv0.x, bv0.y, bv0.z, bv0.w, bv1.x, bv1.y, bv1.z, bv1.w};
#pragma unroll
            for (int o = 0; o < 4; o++)
#pragma unroll
                for (int j = 0; j < 8; j++)
                    acc[o][j] = fmaf(a[o], bb[j], acc[o][j]);
        }
        __syncthreads();
    }

    float lsum = 0.f, lsq = 0.f;
#pragma unroll
    for (int o = 0; o < 4; o++) {
        float* yp = g_y + ((size_t)b * CC + m0 + mg * 4 + o) * PP + nb + ng * 8;
        *(float4*)yp       = make_float4(acc[o][0], acc[o][1], acc[o][2], acc[o][3]);
        *(float4*)(yp + 4) = make_float4(acc[o][4], acc[o][5], acc[o][6], acc[o][7]);
#pragma unroll
        for (int j = 0; j < 8; j++) { lsum += acc[o][j]; lsq += acc[o][j] * acc[o][j]; }
    }
#pragma unroll
    for (int off = 16; off > 0; off >>= 1) {
        lsum += __shfl_down_sync(0xffffffffu, lsum, off);
        lsq  += __shfl_down_sync(0xffffffffu, lsq, off);
    }
    if ((tid & 31) == 0) {
        int grel = mg >> 2;   // 16-channel groups; uniform within warp
        atomicAdd(&gsum[grel], lsum);
        atomicAdd(&gsq[grel], lsq);
    }
    __syncthreads();
    if (tid < 4) {
        int g = (m0 >> 4) + tid;
        atomicAdd(&g_gn2_sum[b * NGG + g], gsum[tid]);
        atomicAdd(&g_gn2_sq[b * NGG + g], gsq[tid]);
    }
}

// ---------------- K7: combine: out = silu(BN(s)) + w_b * (GN2(y) or x) --------
__global__ __launch_bounds__(256) void k_combine(const float* __restrict__ x,
                                                 const float* __restrict__ weights,
                                                 const int* __restrict__ indices,
                                                 const float* __restrict__ g2,
                                                 const float* __restrict__ b2,
                                                 float* __restrict__ out) {
    const int blk = blockIdx.x;
    const int b = blk >> 7, c = blk & 127;
    const int idx = indices[b];
    const float wb = weights[b];
    const float sc = g_bn_scale[c], sh = g_bn_shift[c];

    float a2, c2;
    if (idx > 0) {
        int e = idx - 1;
        int g = c >> 4;
        float mean = g_gn2_mr[(b * NGG + g) * 2];
        float rstd = g_gn2_mr[(b * NGG + g) * 2 + 1];
        float ga = rstd * g2[e * CC + c];
        a2 = ga * wb;
        c2 = (b2[e * CC + c] - mean * ga) * wb;
    } else {
        a2 = wb;   // identity expert
        c2 = 0.f;
    }

    const size_t base = ((size_t)b * CC + c) * PP;
    const float4* sp = (const float4*)(g_s + base);
    const float4* rp = (idx > 0) ? (const float4*)(g_y + base) : (const float4*)(x + base);
    float4* op = (float4*)(out + base);

    for (int i = threadIdx.x; i < PP / 4; i += 256) {
        float4 sv = sp[i];
        float4 rv = rp[i];
        float4 o;
        float t;
        t = fmaf(sv.x, sc, sh); o.x = t / (1.f + expf(-t)) + fmaf(rv.x, a2, c2);
        t = fmaf(sv.y, sc, sh); o.y = t / (1.f + expf(-t)) + fmaf(rv.y, a2, c2);
        t = fmaf(sv.z, sc, sh); o.z = t / (1.f + expf(-t)) + fmaf(rv.z, a2, c2);
        t = fmaf(sv.w, sc, sh); o.w = t / (1.f + expf(-t)) + fmaf(rv.w, a2, c2);
        op[i] = o;
    }
}

// ---------------- launch ----------------
extern "C" void kernel_launch(void* const* d_in, const int* in_sizes, int n_in,
                              void* d_out, int out_size) {
    const float* x        = (const float*)d_in[0];   // [16,128,80,80]
    const float* weights  = (const float*)d_in[1];   // [16]
    const int*   indices  = (const int*)d_in[2];     // [16]
    const float* shared_w = (const float*)d_in[3];   // [128,128,3,3]
    const float* bn_gamma = (const float*)d_in[4];   // [128]
    const float* bn_beta  = (const float*)d_in[5];   // [128]
    const float* w1       = (const float*)d_in[6];   // [3,256,128]
    const float* g1       = (const float*)d_in[7];   // [3,256]
    const float* b1       = (const float*)d_in[8];   // [3,256]
    const float* w2       = (const float*)d_in[9];   // [3,128,256]
    const float* g2       = (const float*)d_in[10];  // [3,128]
    const float* b2       = (const float*)d_in[11];  // [3,128]
    float* out = (float*)d_out;

    k_zero<<<1, 256>>>();
    k_conv<<<dim3(2, 50, BB), 256>>>(x, shared_w);
    k_gemm1<<<dim3(50, 4, BB), 256>>>(x, indices, w1);
    k_fin_bn<<<1, 128>>>(bn_gamma, bn_beta);
    k_fin_gn1<<<1, 128>>>();
    k_gemm2<<<dim3(50, 2, BB), 256>>>(indices, w2, g1, b1);
    k_fin_gn2<<<1, 128>>>();
    k_combine<<<BB * CC, 256>>>(x, weights, indices, g2, b2, out);
}

// round 5
// speedup vs baseline: 1.0021x; 1.0021x over previous
#include <cuda_runtime.h>

// Shapes (fixed for this problem)
#define BB   16
#define CC   128
#define HIDD 256
#define HH   80
#define WW   80
#define PP   6400      // HH*WW
#define NGG  8
#define EPSV 1e-5f

// ---------------- device scratch (static: allocation-free) ----------------
__device__ float g_s[(size_t)BB * CC * PP];        // conv3x3 output (pre-BN)
__device__ float g_h[(size_t)BB * HIDD * PP];      // expert hidden (pre-GN1)
__device__ float g_y[(size_t)BB * CC * PP];        // expert out (pre-GN2)

__device__ float g_bn_sum[CC], g_bn_sq[CC];
__device__ float g_bn_scale[CC], g_bn_shift[CC];
__device__ float g_gn1_sum[BB * NGG], g_gn1_sq[BB * NGG];
__device__ float g_gn1_mr[BB * NGG * 2];           // mean, rstd interleaved
__device__ float g_gn2_sum[BB * NGG], g_gn2_sq[BB * NGG];
__device__ float g_gn2_mr[BB * NGG * 2];

// ---------------- K0: zero accumulators (graph replays must be deterministic) ----
__global__ void k_zero() {
    int t = threadIdx.x;
    if (t < CC) { g_bn_sum[t] = 0.f; g_bn_sq[t] = 0.f; }
    if (t < BB * NGG) {
        g_gn1_sum[t] = 0.f; g_gn1_sq[t] = 0.f;
        g_gn2_sum[t] = 0.f; g_gn2_sq[t] = 0.f;
    }
}

// ---------------- K1: conv3x3 (SAME pad) + BN partial sums --------------------
// Tile: 64 out-channels x (8 rows x 16 cols) pixels. 256 threads,
// each thread computes 4 oc x 8 px. K loop over input channels in chunks of 8.
__global__ __launch_bounds__(256) void k_conv(const float* __restrict__ x,
                                              const float* __restrict__ w) {
    __shared__ float xs[8 * 190];        // [cc][10 rows][19 pad cols] (18 used)
    __shared__ float ws[8 * 9 * 64];     // [cc][tap][oc64]
    __shared__ float ssum[64], ssq[64];

    const int tid  = threadIdx.x;
    const int b    = blockIdx.z;
    const int oc0  = blockIdx.x * 64;
    const int ty   = blockIdx.y / 5, tx = blockIdx.y % 5;
    const int row0 = ty * 8, col0 = tx * 16;
    const int ocg  = tid >> 4;           // 0..15
    const int pg   = tid & 15;
    const int prow = pg >> 1;            // 0..7
    const int pcol = (pg & 1) * 8;       // 0 or 8

    if (tid < 64) { ssum[tid] = 0.f; ssq[tid] = 0.f; }

    float acc[4][8];
#pragma unroll
    for (int o = 0; o < 4; o++)
#pragma unroll
        for (int j = 0; j < 8; j++) acc[o][j] = 0.f;

    const float* xb = x + (size_t)b * CC * PP;

    for (int c0 = 0; c0 < CC; c0 += 8) {
        // stage input halo tile: 8 ch x 10 x 18
        for (int i = tid; i < 8 * 10 * 18; i += 256) {
            int cc  = i / 180;
            int rem = i - cc * 180;
            int r   = rem / 18;
            int col = rem - r * 18;
            int gr = row0 + r - 1, gc = col0 + col - 1;
            float v = 0.f;
            if ((unsigned)gr < 80u && (unsigned)gc < 80u)
                v = xb[(size_t)(c0 + cc) * PP + gr * 80 + gc];
            xs[cc * 190 + r * 19 + col] = v;
        }
        // stage weights: 8 ch x 9 taps x 64 oc (oc contiguous for float4)
        for (int i = tid; i < 8 * 9 * 64; i += 256) {
            int cc  = i / 576;
            int rem = i - cc * 576;
            int t   = rem >> 6;
            int o   = rem & 63;
            ws[cc * 576 + t * 64 + o] = w[((size_t)(oc0 + o) * CC + c0 + cc) * 9 + t];
        }
        __syncthreads();

        for (int cc = 0; cc < 8; cc++) {
#pragma unroll
            for (int kh = 0; kh < 3; kh++) {
                float xr[10];
#pragma unroll
                for (int j = 0; j < 10; j++)
                    xr[j] = xs[cc * 190 + (prow + kh) * 19 + pcol + j];
#pragma unroll
                for (int kw = 0; kw < 3; kw++) {
                    float4 wv = *(const float4*)&ws[cc * 576 + (kh * 3 + kw) * 64 + ocg * 4];
#pragma unroll
                    for (int j = 0; j < 8; j++) {
                        acc[0][j] = fmaf(wv.x, xr[j + kw], acc[0][j]);
                        acc[1][j] = fmaf(wv.y, xr[j + kw], acc[1][j]);
                        acc[2][j] = fmaf(wv.z, xr[j + kw], acc[2][j]);
                        acc[3][j] = fmaf(wv.w, xr[j + kw], acc[3][j]);
                    }
                }
            }
        }
        __syncthreads();
    }

    // store s + block-level BN partial sums
    const int row = row0 + prow, col = col0 + pcol;
#pragma unroll
    for (int o = 0; o < 4; o++) {
        int oc = oc0 + ocg * 4 + o;
        float* sp = g_s + ((size_t)b * CC + oc) * PP + row * 80 + col;
        *(float4*)sp       = make_float4(acc[o][0], acc[o][1], acc[o][2], acc[o][3]);
        *(float4*)(sp + 4) = make_float4(acc[o][4], acc[o][5], acc[o][6], acc[o][7]);
        float s = 0.f, q = 0.f;
#pragma unroll
        for (int j = 0; j < 8; j++) { s += acc[o][j]; q += acc[o][j] * acc[o][j]; }
        atomicAdd(&ssum[ocg * 4 + o], s);
        atomicAdd(&ssq[ocg * 4 + o], q);
    }
    __syncthreads();
    if (tid < 64) {
        atomicAdd(&g_bn_sum[oc0 + tid], ssum[tid]);
        atomicAdd(&g_bn_sq[oc0 + tid], ssq[tid]);
    }
}

// ---------------- stat finalize kernels ----------------
__global__ void k_fin_bn(const float* __restrict__ gamma, const float* __restrict__ beta) {
    int t = threadIdx.x; // 128
    const float inv = 1.f / (float)(BB * PP);
    float m = g_bn_sum[t] * inv;
    float v = g_bn_sq[t] * inv - m * m;
    float r = rsqrtf(v + EPSV);
    float sc = gamma[t] * r;
    g_bn_scale[t] = sc;
    g_bn_shift[t] = beta[t] - m * sc;
}

__global__ void k_fin_gn1() {
    int t = threadIdx.x; // 128 = BB*NGG
    const float inv = 1.f / (float)((HIDD / NGG) * PP); // 32*6400
    float m = g_gn1_sum[t] * inv;
    float v = g_gn1_sq[t] * inv - m * m;
    g_gn1_mr[2 * t]     = m;
    g_gn1_mr[2 * t + 1] = rsqrtf(v + EPSV);
}

__global__ void k_fin_gn2() {
    int t = threadIdx.x; // 128
    const float inv = 1.f / (float)((CC / NGG) * PP); // 16*6400
    float m = g_gn2_sum[t] * inv;
    float v = g_gn2_sq[t] * inv - m * m;
    g_gn2_mr[2 * t]     = m;
    g_gn2_mr[2 * t + 1] = rsqrtf(v + EPSV);
}

// ---------------- K3: expert GEMM1 (h = w1[e] @ x_b) + GN1 partial sums -------
// Per-batch dynamic expert: block early-exits if indices[b]==0.
// Tile 64 M x 128 N, K chunk 16. 256 threads, each 4x8.
__global__ __launch_bounds__(256) void k_gemm1(const float* __restrict__ x,
                                               const int* __restrict__ indices,
                                               const float* __restrict__ w1) {
    const int b = blockIdx.z;
    const int idx = indices[b];
    if (idx == 0) return;
    const int e = idx - 1;

    __shared__ float As[16 * 68];   // [k][m64] padded
    __shared__ float Bs[16 * 128];  // [k][n128]
    __shared__ float gsum[2], gsq[2];

    const int tid = threadIdx.x;
    const int mg = tid >> 4, ng = tid & 15;
    const int m0 = blockIdx.y * 64;
    const int nb = blockIdx.x * 128;
    if (tid < 2) { gsum[tid] = 0.f; gsq[tid] = 0.f; }

    float acc[4][8];
#pragma unroll
    for (int o = 0; o < 4; o++)
#pragma unroll
        for (int j = 0; j < 8; j++) acc[o][j] = 0.f;

    const float* wbase = w1 + (size_t)e * HIDD * CC;
    const float* xb    = x + (size_t)b * CC * PP;

    for (int k0 = 0; k0 < CC; k0 += 16) {
        for (int i = tid; i < 1024; i += 256) {
            int m = i >> 4, kk = i & 15;
            As[kk * 68 + m] = wbase[(size_t)(m0 + m) * CC + k0 + kk];
        }
        for (int i = tid; i < 2048; i += 256) {
            int kk = i >> 7, n = i & 127;
            Bs[kk * 128 + n] = xb[(size_t)(k0 + kk) * PP + nb + n];
        }
        __syncthreads();
#pragma unroll
        for (int kk = 0; kk < 16; kk++) {
            float4 av  = *(const float4*)&As[kk * 68 + mg * 4];
            float4 bv0 = *(const float4*)&Bs[kk * 128 + ng * 8];
            float4 bv1 = *(const float4*)&Bs[kk * 128 + ng * 8 + 4];
            float a[4]  = {av.x, av.y, av.z, av.w};
            float bb[8] = {bv0.x, bv0.y, bv0.z, bv0.w, bv1.x, bv1.y, bv1.z, bv1.w};
#pragma unroll
            for (int o = 0; o < 4; o++)
#pragma unroll
                for (int j = 0; j < 8; j++)
                    acc[o][j] = fmaf(a[o], bb[j], acc[o][j]);
        }
        __syncthreads();
    }

    // store h + GN1 stats (raw h; GN normalizes raw values)
    float lsum = 0.f, lsq = 0.f;
#pragma unroll
    for (int o = 0; o < 4; o++) {
        float* hp = g_h + ((size_t)b * HIDD + m0 + mg * 4 + o) * PP + nb + ng * 8;
        *(float4*)hp       = make_float4(acc[o][0], acc[o][1], acc[o][2], acc[o][3]);
        *(float4*)(hp + 4) = make_float4(acc[o][4], acc[o][5], acc[o][6], acc[o][7]);
#pragma unroll
        for (int j = 0; j < 8; j++) { lsum += acc[o][j]; lsq += acc[o][j] * acc[o][j]; }
    }
#pragma unroll
    for (int off = 16; off > 0; off >>= 1) {
        lsum += __shfl_down_sync(0xffffffffu, lsum, off);
        lsq  += __shfl_down_sync(0xffffffffu, lsq, off);
    }
    if ((tid & 31) == 0) {
        int grel = (mg * 4) >> 5;  // uniform within warp
        atomicAdd(&gsum[grel], lsum);
        atomicAdd(&gsq[grel], lsq);
    }
    __syncthreads();
    if (tid < 2) {
        int g = (m0 >> 5) + tid;
        atomicAdd(&g_gn1_sum[b * NGG + g], gsum[tid]);
        atomicAdd(&g_gn1_sq[b * NGG + g], gsq[tid]);
    }
}

// ---------------- K5: expert GEMM2 (y = w2[e] @ silu(GN1(h))) + GN2 sums ------
__global__ __launch_bounds__(256) void k_gemm2(const int* __restrict__ indices,
                                               const float* __restrict__ w2,
                                               const float* __restrict__ g1,
                                               const float* __restrict__ b1) {
    const int b = blockIdx.z;
    const int idx = indices[b];
    if (idx == 0) return;
    const int e = idx - 1;

    __shared__ float As[16 * 68];
    __shared__ float Bs[16 * 128];
    __shared__ float sa[HIDD], sb[HIDD];
    __shared__ float gsum[4], gsq[4];

    const int tid = threadIdx.x;
    const int mg = tid >> 4, ng = tid & 15;
    const int m0 = blockIdx.y * 64;
    const int nb = blockIdx.x * 128;

    { // per-k GN1 affine coefficients (fold mean/rstd/gamma/beta)
        int k = tid;            // 256 threads == HIDD
        int gg = k >> 5;
        float mean = g_gn1_mr[(b * NGG + gg) * 2];
        float rstd = g_gn1_mr[(b * NGG + gg) * 2 + 1];
        float a = rstd * g1[e * HIDD + k];
        sa[k] = a;
        sb[k] = b1[e * HIDD + k] - mean * a;
    }
    if (tid < 4) { gsum[tid] = 0.f; gsq[tid] = 0.f; }
    __syncthreads();

    float acc[4][8];
#pragma unroll
    for (int o = 0; o < 4; o++)
#pragma unroll
        for (int j = 0; j < 8; j++) acc[o][j] = 0.f;

    const float* wbase = w2 + (size_t)e * CC * HIDD;
    const float* hb    = g_h + (size_t)b * HIDD * PP;

    for (int k0 = 0; k0 < HIDD; k0 += 16) {
        for (int i = tid; i < 1024; i += 256) {
            int m = i >> 4, kk = i & 15;
            As[kk * 68 + m] = wbase[(size_t)(m0 + m) * HIDD + k0 + kk];
        }
        for (int i = tid; i < 2048; i += 256) {
            int kk = i >> 7, n = i & 127;
            int kg = k0 + kk;
            float t = fmaf(hb[(size_t)kg * PP + nb + n], sa[kg], sb[kg]);
            Bs[kk * 128 + n] = t / (1.f + expf(-t));   // SiLU
        }
        __syncthreads();
#pragma unroll
        for (int kk = 0; kk < 16; kk++) {
            float4 av  = *(const float4*)&As[kk * 68 + mg * 4];
            float4 bv0 = *(const float4*)&Bs[kk * 128 + ng * 8];
            float4 bv1 = *(const float4*)&Bs[kk * 128 + ng * 8 + 4];
            float a[4]  = {av.x, av.y, av.z, av.w};
            float bb[8] = {bv0.x, bv0.y, bv0.z, bv0.w, bv1.x, bv1.y, bv1.z, bv1.w};
#pragma unroll
            for (int o = 0; o < 4; o++)
#pragma unroll
                for (int j = 0; j < 8; j++)
                    acc[o][j] = fmaf(a[o], bb[j], acc[o][j]);
        }
        __syncthreads();
    }

    float lsum = 0.f, lsq = 0.f;
#pragma unroll
    for (int o = 0; o < 4; o++) {
        float* yp = g_y + ((size_t)b * CC + m0 + mg * 4 + o) * PP + nb + ng * 8;
        *(float4*)yp       = make_float4(acc[o][0], acc[o][1], acc[o][2], acc[o][3]);
        *(float4*)(yp + 4) = make_float4(acc[o][4], acc[o][5], acc[o][6], acc[o][7]);
#pragma unroll
        for (int j = 0; j < 8; j++) { lsum += acc[o][j]; lsq += acc[o][j] * acc[o][j]; }
    }
#pragma unroll
    for (int off = 16; off > 0; off >>= 1) {
        lsum += __shfl_down_sync(0xffffffffu, lsum, off);
        lsq  += __shfl_down_sync(0xffffffffu, lsq, off);
    }
    if ((tid & 31) == 0) {
        int grel = mg >> 2;   // 16-channel groups; uniform within warp
        atomicAdd(&gsum[grel], lsum);
        atomicAdd(&gsq[grel], lsq);
    }
    __syncthreads();
    if (tid < 4) {
        int g = (m0 >> 4) + tid;
        atomicAdd(&g_gn2_sum[b * NGG + g], gsum[tid]);
        atomicAdd(&g_gn2_sq[b * NGG + g], gsq[tid]);
    }
}

// ---------------- K7: combine: out = silu(BN(s)) + w_b * (GN2(y) or x) --------
__global__ __launch_bounds__(256) void k_combine(const float* __restrict__ x,
                                                 const float* __restrict__ weights,
                                                 const int* __restrict__ indices,
                                                 const float* __restrict__ g2,
                                                 const float* __restrict__ b2,
                                                 float* __restrict__ out) {
    const int blk = blockIdx.x;
    const int b = blk >> 7, c = blk & 127;
    const int idx = indices[b];
    const float wb = weights[b];
    const float sc = g_bn_scale[c], sh = g_bn_shift[c];

    float a2, c2;
    if (idx > 0) {
        int e = idx - 1;
        int g = c >> 4;
        float mean = g_gn2_mr[(b * NGG + g) * 2];
        float rstd = g_gn2_mr[(b * NGG + g) * 2 + 1];
        float ga = rstd * g2[e * CC + c];
        a2 = ga * wb;
        c2 = (b2[e * CC + c] - mean * ga) * wb;
    } else {
        a2 = wb;   // identity expert
        c2 = 0.f;
    }

    const size_t base = ((size_t)b * CC + c) * PP;
    const float4* sp = (const float4*)(g_s + base);
    const float4* rp = (idx > 0) ? (const float4*)(g_y + base) : (const float4*)(x + base);
    float4* op = (float4*)(out + base);

    for (int i = threadIdx.x; i < PP / 4; i += 256) {
        float4 sv = sp[i];
        float4 rv = rp[i];
        float4 o;
        float t;
        t = fmaf(sv.x, sc, sh); o.x = t / (1.f + expf(-t)) + fmaf(rv.x, a2, c2);
        t = fmaf(sv.y, sc, sh); o.y = t / (1.f + expf(-t)) + fmaf(rv.y, a2, c2);
        t = fmaf(sv.z, sc, sh); o.z = t / (1.f + expf(-t)) + fmaf(rv.z, a2, c2);
        t = fmaf(sv.w, sc, sh); o.w = t / (1.f + expf(-t)) + fmaf(rv.w, a2, c2);
        op[i] = o;
    }
}

// ---------------- launch ----------------
extern "C" void kernel_launch(void* const* d_in, const int* in_sizes, int n_in,
                              void* d_out, int out_size) {
    const float* x        = (const float*)d_in[0];   // [16,128,80,80]
    const float* weights  = (const float*)d_in[1];   // [16]
    const int*   indices  = (const int*)d_in[2];     // [16]
    const float* shared_w = (const float*)d_in[3];   // [128,128,3,3]
    const float* bn_gamma = (const float*)d_in[4];   // [128]
    const float* bn_beta  = (const float*)d_in[5];   // [128]
    const float* w1       = (const float*)d_in[6];   // [3,256,128]
    const float* g1       = (const float*)d_in[7];   // [3,256]
    const float* b1       = (const float*)d_in[8];   // [3,256]
    const float* w2       = (const float*)d_in[9];   // [3,128,256]
    const float* g2       = (const float*)d_in[10];  // [3,128]
    const float* b2       = (const float*)d_in[11];  // [3,128]
    float* out = (float*)d_out;

    k_zero<<<1, 256>>>();
    k_conv<<<dim3(2, 50, BB), 256>>>(x, shared_w);
    k_gemm1<<<dim3(50, 4, BB), 256>>>(x, indices, w1);
    k_fin_bn<<<1, 128>>>(bn_gamma, bn_beta);
    k_fin_gn1<<<1, 128>>>();
    k_gemm2<<<dim3(50, 2, BB), 256>>>(indices, w2, g1, b1);
    k_fin_gn2<<<1, 128>>>();
    k_combine<<<BB * CC, 256>>>(x, weights, indices, g2, b2, out);
}

// round 7
// speedup vs baseline: 1.7548x; 1.7512x over previous
#include <cuda_runtime.h>
#include <cuda_bf16.h>
#include <cstdint>

// ---------------- shapes ----------------
#define BB    16
#define CC    128
#define HIDD  256
#define PP    6400
#define NGG   8
#define EPSV  1e-5f

#define NPAD  6724      // 82*82
#define NPADT 6784      // 53 tiles * 128
#define GUARD 128
#define XROWS 7040      // GUARD + NPADT + GUARD

// smem tile geometry: [128 rows][136 bf16] = 272 B/row (17*16B: 16B-aligned, conflict-free ldmatrix)
#define TROW   272
#define TILEB  34816    // 128*272
#define BUFB   69632    // A tile + B tile
#define SMEMB  139264   // double buffered

// ---------------- device scratch (static; allocation-free) ----------------
__device__ __align__(16) float g_s[(size_t)BB * CC * PP];
__device__ __align__(16) float g_y[(size_t)BB * CC * PP];
__device__ __align__(16) float g_h[(size_t)BB * NPADT * HIDD];

__device__ uint4 g_xp_hi[(size_t)BB * XROWS * 16];   // [b][row][128 ci] bf16, 256B rows
__device__ uint4 g_xp_lo[(size_t)BB * XROWS * 16];
__device__ uint4 g_hp_hi[(size_t)BB * NPADT * 32];   // [b][pos][256 hid] bf16, 512B rows
__device__ uint4 g_hp_lo[(size_t)BB * NPADT * 32];

__device__ uint4 g_wt_hi[9 * 128 * 16];              // [tap][oc][128 ci]
__device__ uint4 g_wt_lo[9 * 128 * 16];
__device__ uint4 g_w1_hi[3 * 256 * 16];              // [e][m256][k128]
__device__ uint4 g_w1_lo[3 * 256 * 16];
__device__ uint4 g_w2_hi[3 * 128 * 32];              // [e][oc128][k256]
__device__ uint4 g_w2_lo[3 * 128 * 32];

__device__ float g_bn_sum[CC], g_bn_sq[CC];
__device__ float g_bn_scale[CC], g_bn_shift[CC];
__device__ float g_gn1_sum[BB * NGG], g_gn1_sq[BB * NGG];
__device__ float g_gn1_mr[BB * NGG * 2];
__device__ float g_gn2_sum[BB * NGG], g_gn2_sq[BB * NGG];
__device__ float g_gn2_mr[BB * NGG * 2];

// ---------------- helpers ----------------
__device__ __forceinline__ uint32_t smem_u32(const void* p) {
    uint32_t a;
    asm("{ .reg .u64 t; cvta.to.shared.u64 t, %1; cvt.u32.u64 %0, t; }" : "=r"(a) : "l"(p));
    return a;
}

// FMA-only sigmoid (no MUFU)
__device__ __forceinline__ float fast_sigmoid(float t) {
    float z = -t * 1.442695041f;
    z = fminf(fmaxf(z, -60.f), 60.f);
    float fl = floorf(z);
    float f = z - fl;
    float p = 1.5403530e-4f;
    p = fmaf(p, f, 1.3333558e-3f);
    p = fmaf(p, f, 9.6181291e-3f);
    p = fmaf(p, f, 5.5504109e-2f);
    p = fmaf(p, f, 2.4022651e-1f);
    p = fmaf(p, f, 6.9314718e-1f);
    float two_f = fmaf(p, f, 1.0f);
    float ex = __int_as_float((127 + (int)fl) << 23) * two_f;   // exp(-t)
    float d = 1.f + ex;
    float r = __int_as_float(0x7EF311C3 - __float_as_int(d));
    r = r * (2.f - d * r);
    r = r * (2.f - d * r);
    r = r * (2.f - d * r);
    return r;
}

// stage one [128 rows][256B used] tile into smem [128][272B] via cp.async (16B ops)
__device__ __forceinline__ void stage_cp(uint32_t s_dst, const char* src, int rowStride, int tid) {
#pragma unroll
    for (int it = 0; it < 8; it++) {
        int idx = it * 256 + tid;          // 0..2047
        int r = idx >> 4, c = idx & 15;
        uint32_t d = s_dst + (uint32_t)(r * TROW + c * 16);
        const char* s = src + (size_t)r * rowStride + c * 16;
        asm volatile("cp.async.cg.shared.global [%0], [%1], 16;" :: "r"(d), "l"(s));
    }
}

// ---------------- small kernels ----------------
__global__ void k_zero() {
    int t = threadIdx.x;
    if (t < CC) { g_bn_sum[t] = 0.f; g_bn_sq[t] = 0.f; }
    if (t < BB * NGG) {
        g_gn1_sum[t] = 0.f; g_gn1_sq[t] = 0.f;
        g_gn2_sum[t] = 0.f; g_gn2_sq[t] = 0.f;
    }
}

__global__ void k_zero_xp() {
    int ro = blockIdx.x * 256 + threadIdx.x;
    if (ro >= XROWS) return;
    int b = blockIdx.y;
    int pos = ro - GUARD;
    bool interior = false;
    if (pos >= 0 && pos < NPAD) {
        int r = pos / 82, q = pos - r * 82;
        interior = (r >= 1 && r <= 80 && q >= 1 && q <= 80);
    }
    if (!interior) {
        uint4 z = make_uint4(0, 0, 0, 0);
        size_t base = ((size_t)b * XROWS + ro) * 16;
#pragma unroll
        for (int j = 0; j < 16; j++) { g_xp_hi[base + j] = z; g_xp_lo[base + j] = z; }
    }
}

__global__ __launch_bounds__(256) void k_pack_x(const float* __restrict__ x) {
    __shared__ float t[128 * 33];
    int tid = threadIdx.x, b = blockIdx.y, p0 = blockIdx.x * 32;
    const float* xb = x + (size_t)b * CC * PP;
#pragma unroll
    for (int i = 0; i < 16; i++) {
        int lin = i * 256 + tid;
        int c = lin >> 5, px = lin & 31;
        t[c * 33 + px] = xb[(size_t)c * PP + p0 + px];
    }
    __syncthreads();
    __nv_bfloat16* hiA = (__nv_bfloat16*)g_xp_hi;
    __nv_bfloat16* loA = (__nv_bfloat16*)g_xp_lo;
#pragma unroll
    for (int i = 0; i < 16; i++) {
        int lin = i * 256 + tid;
        int c = tid & 127, px = (lin >> 7) & 31;
        float v = t[c * 33 + px];
        int p = p0 + px;
        int r = p / 80, q = p - r * 80;
        int pos = (r + 1) * 82 + (q + 1);
        size_t a = ((size_t)b * XROWS + GUARD + pos) * 128 + c;
        __nv_bfloat16 hi = __float2bfloat16(v);
        hiA[a] = hi;
        loA[a] = __float2bfloat16(v - __bfloat162float(hi));
    }
}

__global__ void k_pack_w(const float* __restrict__ w,
                         const float* __restrict__ w1,
                         const float* __restrict__ w2) {
    int idx = blockIdx.x * 256 + threadIdx.x;   // 0..344063
    if (idx >= 344064) return;
    float v; __nv_bfloat16 *dh, *dl; int di;
    if (idx < 147456) {                          // conv: [t][oc][ci] <- w[oc][ci][t]
        int t = idx / 16384, rem = idx - t * 16384;
        int oc = rem >> 7, ci = rem & 127;
        v = w[((size_t)oc * 128 + ci) * 9 + t];
        dh = (__nv_bfloat16*)g_wt_hi; dl = (__nv_bfloat16*)g_wt_lo; di = idx;
    } else if (idx < 245760) {
        di = idx - 147456; v = w1[di];
        dh = (__nv_bfloat16*)g_w1_hi; dl = (__nv_bfloat16*)g_w1_lo;
    } else {
        di = idx - 245760; v = w2[di];
        dh = (__nv_bfloat16*)g_w2_hi; dl = (__nv_bfloat16*)g_w2_lo;
    }
    __nv_bfloat16 hi = __float2bfloat16(v);
    dh[di] = hi;
    dl[di] = __float2bfloat16(v - __bfloat162float(hi));
}

__global__ void k_fin_bn(const float* __restrict__ gamma, const float* __restrict__ beta) {
    int t = threadIdx.x;
    const float inv = 1.f / (float)(BB * PP);
    float m = g_bn_sum[t] * inv;
    float v = g_bn_sq[t] * inv - m * m;
    float sc = gamma[t] * rsqrtf(v + EPSV);
    g_bn_scale[t] = sc;
    g_bn_shift[t] = beta[t] - m * sc;
}
__global__ void k_fin_gn1() {
    int t = threadIdx.x;
    const float inv = 1.f / (float)((HIDD / NGG) * PP);
    float m = g_gn1_sum[t] * inv;
    float v = g_gn1_sq[t] * inv - m * m;
    g_gn1_mr[2 * t] = m;
    g_gn1_mr[2 * t + 1] = rsqrtf(v + EPSV);
}
__global__ void k_fin_gn2() {
    int t = threadIdx.x;
    const float inv = 1.f / (float)((CC / NGG) * PP);
    float m = g_gn2_sum[t] * inv;
    float v = g_gn2_sq[t] * inv - m * m;
    g_gn2_mr[2 * t] = m;
    g_gn2_mr[2 * t + 1] = rsqrtf(v + EPSV);
}

__global__ __launch_bounds__(256) void k_prep_h(const int* __restrict__ indices,
                                                const float* __restrict__ g1,
                                                const float* __restrict__ b1) {
    int b = blockIdx.y;
    int id = indices[b];
    if (id == 0) return;
    int e = id - 1;
    __shared__ float sa[256], sc[256];
    int tid = threadIdx.x;
    {
        int gg = tid >> 5;
        float mean = g_gn1_mr[(b * 8 + gg) * 2];
        float rstd = g_gn1_mr[(b * 8 + gg) * 2 + 1];
        float a = rstd * g1[e * 256 + tid];
        sa[tid] = a;
        sc[tid] = b1[e * 256 + tid] - mean * a;
    }
    __syncthreads();
    size_t base = (size_t)b * NPADT * 256;
    __nv_bfloat16* hiA = (__nv_bfloat16*)g_hp_hi;
    __nv_bfloat16* loA = (__nv_bfloat16*)g_hp_lo;
#pragma unroll
    for (int it = 0; it < 8; it++) {
        size_t l = (size_t)blockIdx.x * 2048 + it * 256 + tid;
        float v = g_h[base + l];
        int hid = (int)(l & 255);
        float t = fmaf(v, sa[hid], sc[hid]);
        float s = t * fast_sigmoid(t);
        __nv_bfloat16 hi = __float2bfloat16(s);
        hiA[base + l] = hi;
        loA[base + l] = __float2bfloat16(s - __bfloat162float(hi));
    }
}

// ---------------- chunk source resolver ----------------
template<int MODE>
__device__ __forceinline__ void chunk_src(int c, int b, int e, int p0, int m0,
                                          const char** as, int* astr,
                                          const char** bs, int* bstr) {
    if (MODE == 0) {
        int t = c / 3, part = c - t * 3;
        int kh = t / 3, kw = t - kh * 3;
        int tapoff = (kh - 1) * 82 + (kw - 1);
        *as = (const char*)(part == 2 ? g_wt_lo : g_wt_hi) + (size_t)t * 32768;
        *astr = 256;
        *bs = (const char*)(part == 1 ? g_xp_lo : g_xp_hi)
            + ((size_t)b * XROWS + GUARD + p0 + tapoff) * 256;
        *bstr = 256;
    } else if (MODE == 1) {
        int part = c;
        *as = (const char*)(part == 2 ? g_w1_lo : g_w1_hi)
            + (size_t)e * 65536 + (size_t)m0 * 256;
        *astr = 256;
        *bs = (const char*)(part == 1 ? g_xp_lo : g_xp_hi)
            + ((size_t)b * XROWS + GUARD + p0) * 256;
        *bstr = 256;
    } else {
        int part = c >> 1, kh = c & 1;
        *as = (const char*)(part == 2 ? g_w2_lo : g_w2_hi)
            + (size_t)e * 65536 + (size_t)kh * 256;
        *astr = 512;
        *bs = (const char*)(part == 1 ? g_hp_lo : g_hp_hi)
            + ((size_t)b * NPADT + p0) * 512 + (size_t)kh * 256;
        *bstr = 512;
    }
}

// ---------------- unified warp-MMA GEMM kernel ----------------
// MODE 0: conv3x3 (27 chunks of K=128) -> g_s + BN stats
// MODE 1: gemm1 w1@x (3 chunks)        -> g_h + GN1 stats
// MODE 2: gemm2 w2@hp (6 chunks)       -> g_y + GN2 stats
template<int MODE>
__global__ __launch_bounds__(256) void k_mma(const int* __restrict__ indices) {
    extern __shared__ __align__(16) char smem[];
    __shared__ float ssum[128], ssq[128];

    const int tid = threadIdx.x, wid = tid >> 5, l = tid & 31;
    const int b = blockIdx.z;
    int e = 0;
    if (MODE != 0) {
        int id = indices[b];
        if (id == 0) return;
        e = id - 1;
    }
    const int p0 = blockIdx.x * 128;
    const int m0 = blockIdx.y * 128;

    if (tid < 128) { ssum[tid] = 0.f; ssq[tid] = 0.f; }

    const uint32_t sbase = smem_u32(smem);
    const int warp_m0 = (wid & 3) * 32;
    const int warp_n0 = (wid >> 2) * 64;
    const int quad = l >> 2, qt = l & 3;

    // ldmatrix byte offsets within a tile
    uint32_t aoff[2], boff[4];
    {
        int rowA = l & 15, colA = l >> 4;
        aoff[0] = (uint32_t)((warp_m0 + rowA) * TROW + colA * 16);
        aoff[1] = aoff[0] + 16 * TROW;
        int rowB = ((l >> 4) << 3) + (l & 7);
        int colB = (l >> 3) & 1;
#pragma unroll
        for (int g = 0; g < 4; g++)
            boff[g] = (uint32_t)((warp_n0 + g * 16 + rowB) * TROW + colB * 16);
    }

    float d[2][8][4];
#pragma unroll
    for (int i = 0; i < 2; i++)
#pragma unroll
        for (int j = 0; j < 8; j++)
#pragma unroll
            for (int k = 0; k < 4; k++) d[i][j][k] = 0.f;

    const int NC = (MODE == 0) ? 27 : (MODE == 1 ? 3 : 6);

    // preload chunk 0
    {
        const char *as, *bs; int astr, bstr;
        chunk_src<MODE>(0, b, e, p0, m0, &as, &astr, &bs, &bstr);
        stage_cp(sbase, as, astr, tid);
        stage_cp(sbase + TILEB, bs, bstr, tid);
        asm volatile("cp.async.commit_group;" ::: "memory");
    }

    for (int c = 0; c < NC; c++) {
        if (c + 1 < NC) {
            const char *as, *bs; int astr, bstr;
            chunk_src<MODE>(c + 1, b, e, p0, m0, &as, &astr, &bs, &bstr);
            uint32_t nb = sbase + (uint32_t)(((c + 1) & 1) * BUFB);
            stage_cp(nb, as, astr, tid);
            stage_cp(nb + TILEB, bs, bstr, tid);
            asm volatile("cp.async.commit_group;" ::: "memory");
            asm volatile("cp.async.wait_group 1;" ::: "memory");
        } else {
            asm volatile("cp.async.wait_group 0;" ::: "memory");
        }
        __syncthreads();

        const uint32_t sA = sbase + (uint32_t)((c & 1) * BUFB);
        const uint32_t sB = sA + TILEB;

#pragma unroll
        for (int ks = 0; ks < 8; ks++) {
            uint32_t af[2][4], bf[4][4];
#pragma unroll
            for (int i = 0; i < 2; i++)
                asm volatile("ldmatrix.sync.aligned.m8n8.x4.shared.b16 {%0,%1,%2,%3}, [%4];"
                    : "=r"(af[i][0]), "=r"(af[i][1]), "=r"(af[i][2]), "=r"(af[i][3])
                    : "r"(sA + aoff[i] + ks * 32));
#pragma unroll
            for (int g = 0; g < 4; g++)
                asm volatile("ldmatrix.sync.aligned.m8n8.x4.shared.b16 {%0,%1,%2,%3}, [%4];"
                    : "=r"(bf[g][0]), "=r"(bf[g][1]), "=r"(bf[g][2]), "=r"(bf[g][3])
                    : "r"(sB + boff[g] + ks * 32));
#pragma unroll
            for (int i = 0; i < 2; i++)
#pragma unroll
                for (int j = 0; j < 8; j++) {
                    int g = j >> 1, s = (j & 1) * 2;
                    asm volatile(
                        "mma.sync.aligned.m16n8k16.row.col.f32.bf16.bf16.f32 "
                        "{%0,%1,%2,%3}, {%4,%5,%6,%7}, {%8,%9}, {%0,%1,%2,%3};"
                        : "+f"(d[i][j][0]), "+f"(d[i][j][1]), "+f"(d[i][j][2]), "+f"(d[i][j][3])
                        : "r"(af[i][0]), "r"(af[i][1]), "r"(af[i][2]), "r"(af[i][3]),
                          "r"(bf[g][s]), "r"(bf[g][s + 1]));
                }
        }
        __syncthreads();
    }

    // ---------------- epilogue ----------------
    if (MODE == 1) {
        float* hb = g_h + (size_t)b * NPADT * 256;
#pragma unroll
        for (int i = 0; i < 2; i++)
#pragma unroll
            for (int rh = 0; rh < 2; rh++) {
                int m = warp_m0 + 16 * i + quad + rh * 8;
                float ps = 0.f, pq = 0.f;
#pragma unroll
                for (int j = 0; j < 8; j++) {
                    float v0 = d[i][j][rh * 2], v1 = d[i][j][rh * 2 + 1];
                    int n = warp_n0 + 8 * j + 2 * qt;
                    int pos = p0 + n;
                    hb[(size_t)pos * 256 + m0 + m] = v0;
                    hb[(size_t)(pos + 1) * 256 + m0 + m] = v1;
                    int r = pos / 82, q = pos - r * 82;
                    bool in0 = (pos < NPAD) && r >= 1 && r <= 80 && q >= 1 && q <= 80;
                    bool in1 = (pos + 1 < NPAD) && r >= 1 && r <= 80 && (q + 1) >= 1 && (q + 1) <= 80;
                    if (in0) { ps += v0; pq += v0 * v0; }
                    if (in1) { ps += v1; pq += v1 * v1; }
                }
                ps += __shfl_down_sync(0xffffffffu, ps, 2);
                pq += __shfl_down_sync(0xffffffffu, pq, 2);
                ps += __shfl_down_sync(0xffffffffu, ps, 1);
                pq += __shfl_down_sync(0xffffffffu, pq, 1);
                if (qt == 0) { atomicAdd(&ssum[m], ps); atomicAdd(&ssq[m], pq); }
            }
    } else {
        float* dst = (MODE == 0 ? g_s : g_y) + (size_t)b * CC * PP;
#pragma unroll
        for (int i = 0; i < 2; i++)
#pragma unroll
            for (int rh = 0; rh < 2; rh++) {
                int m = warp_m0 + 16 * i + quad + rh * 8;
                float ps = 0.f, pq = 0.f;
#pragma unroll
                for (int j = 0; j < 8; j++) {
                    float v0 = d[i][j][rh * 2], v1 = d[i][j][rh * 2 + 1];
                    int n = warp_n0 + 8 * j + 2 * qt;
                    int pos = p0 + n;
                    int r = pos / 82, q = pos - r * 82;
                    bool in0 = (pos < NPAD) && r >= 1 && r <= 80 && q >= 1 && q <= 80;
                    bool in1 = (pos + 1 < NPAD) && r >= 1 && r <= 80 && (q + 1) >= 1 && (q + 1) <= 80;
                    if (in0) { dst[(size_t)m * PP + (r - 1) * 80 + (q - 1)] = v0; ps += v0; pq += v0 * v0; }
                    if (in1) { dst[(size_t)m * PP + (r - 1) * 80 + q] = v1; ps += v1; pq += v1 * v1; }
                }
                ps += __shfl_down_sync(0xffffffffu, ps, 2);
                pq += __shfl_down_sync(0xffffffffu, pq, 2);
                ps += __shfl_down_sync(0xffffffffu, ps, 1);
                pq += __shfl_down_sync(0xffffffffu, pq, 1);
                if (qt == 0) { atomicAdd(&ssum[m], ps); atomicAdd(&ssq[m], pq); }
            }
    }

    __syncthreads();
    if (tid < 128) {
        if (MODE == 0) {
            atomicAdd(&g_bn_sum[tid], ssum[tid]);
            atomicAdd(&g_bn_sq[tid], ssq[tid]);
        } else if (MODE == 1) {
            atomicAdd(&g_gn1_sum[b * NGG + ((m0 + tid) >> 5)], ssum[tid]);
            atomicAdd(&g_gn1_sq[b * NGG + ((m0 + tid) >> 5)], ssq[tid]);
        } else {
            atomicAdd(&g_gn2_sum[b * NGG + (tid >> 4)], ssum[tid]);
            atomicAdd(&g_gn2_sq[b * NGG + (tid >> 4)], ssq[tid]);
        }
    }
}

// ---------------- combine ----------------
__global__ __launch_bounds__(256) void k_combine(const float* __restrict__ x,
                                                 const float* __restrict__ weights,
                                                 const int* __restrict__ indices,
                                                 const float* __restrict__ g2,
                                                 const float* __restrict__ b2,
                                                 float* __restrict__ out) {
    const int blk = blockIdx.x;
    const int b = blk >> 7, c = blk & 127;
    const int idx = indices[b];
    const float wb = weights[b];
    const float sc = g_bn_scale[c], sh = g_bn_shift[c];

    float a2, c2;
    if (idx > 0) {
        int e = idx - 1;
        int g = c >> 4;
        float mean = g_gn2_mr[(b * NGG + g) * 2];
        float rstd = g_gn2_mr[(b * NGG + g) * 2 + 1];
        float ga = rstd * g2[e * CC + c];
        a2 = ga * wb;
        c2 = (b2[e * CC + c] - mean * ga) * wb;
    } else {
        a2 = wb;
        c2 = 0.f;
    }

    const size_t base = ((size_t)b * CC + c) * PP;
    const float4* sp = (const float4*)(g_s + base);
    const float4* rp = (idx > 0) ? (const float4*)(g_y + base) : (const float4*)(x + base);
    float4* op = (float4*)(out + base);

    for (int i = threadIdx.x; i < PP / 4; i += 256) {
        float4 sv = sp[i];
        float4 rv = rp[i];
        float4 o;
        float t;
        t = fmaf(sv.x, sc, sh); o.x = t * fast_sigmoid(t) + fmaf(rv.x, a2, c2);
        t = fmaf(sv.y, sc, sh); o.y = t * fast_sigmoid(t) + fmaf(rv.y, a2, c2);
        t = fmaf(sv.z, sc, sh); o.z = t * fast_sigmoid(t) + fmaf(rv.z, a2, c2);
        t = fmaf(sv.w, sc, sh); o.w = t * fast_sigmoid(t) + fmaf(rv.w, a2, c2);
        op[i] = o;
    }
}

// ---------------- launch ----------------
extern "C" void kernel_launch(void* const* d_in, const int* in_sizes, int n_in,
                              void* d_out, int out_size) {
    const float* x        = (const float*)d_in[0];
    const float* weights  = (const float*)d_in[1];
    const int*   indices  = (const int*)d_in[2];
    const float* shared_w = (const float*)d_in[3];
    const float* bn_gamma = (const float*)d_in[4];
    const float* bn_beta  = (const float*)d_in[5];
    const float* w1       = (const float*)d_in[6];
    const float* g1       = (const float*)d_in[7];
    const float* b1       = (const float*)d_in[8];
    const float* w2       = (const float*)d_in[9];
    const float* g2       = (const float*)d_in[10];
    const float* b2       = (const float*)d_in[11];
    float* out = (float*)d_out;

    static bool attr_set = false;
    if (!attr_set) {
        cudaFuncSetAttribute(k_mma<0>, cudaFuncAttributeMaxDynamicSharedMemorySize, SMEMB);
        cudaFuncSetAttribute(k_mma<1>, cudaFuncAttributeMaxDynamicSharedMemorySize, SMEMB);
        cudaFuncSetAttribute(k_mma<2>, cudaFuncAttributeMaxDynamicSharedMemorySize, SMEMB);
        attr_set = true;
    }

    k_zero<<<1, 256>>>();
    k_zero_xp<<<dim3(28, BB), 256>>>();
    k_pack_x<<<dim3(200, BB), 256>>>(x);
    k_pack_w<<<1344, 256>>>(shared_w, w1, w2);

    k_mma<0><<<dim3(53, 1, BB), 256, SMEMB>>>(indices);   // conv3x3 + BN stats
    k_mma<1><<<dim3(53, 2, BB), 256, SMEMB>>>(indices);   // gemm1 + GN1 stats
    k_fin_bn<<<1, 128>>>(bn_gamma, bn_beta);
    k_fin_gn1<<<1, 128>>>();
    k_prep_h<<<dim3(848, BB), 256>>>(indices, g1, b1);
    k_mma<2><<<dim3(53, 1, BB), 256, SMEMB>>>(indices);   // gemm2 + GN2 stats
    k_fin_gn2<<<1, 128>>>();
    k_combine<<<BB * CC, 256>>>(x, weights, indices, g2, b2, out);
}

// round 8
// speedup vs baseline: 1.8538x; 1.0564x over previous
#include <cuda_runtime.h>
#include <cuda_bf16.h>
#include <cstdint>

// ---------------- shapes ----------------
#define BB    16
#define CC    128
#define HIDD  256
#define PP    6400
#define NGG   8
#define EPSV  1e-5f

#define NPAD  6724      // 82*82
#define NPADT 6784      // 53 tiles * 128
#define GUARD 128
#define XROWS 7040      // GUARD + NPADT + GUARD

// smem tile geometry: [128 rows][136 bf16] = 272 B/row (16B-aligned, conflict-free ldmatrix)
#define TROW   272
#define TILEB  34816    // 128*272
#define BUFB   69632    // A tile + B tile
#define SMEMB  139264   // double buffered (gemm1/gemm2 kernels)

// conv halo-window smem layout
#define XW_ROWS 294     // rows p0-83 .. p0+210
#define XW_BYTES (XW_ROWS * TROW)      // 79968
#define WOFF     (2 * XW_BYTES)        // 159936
#define SMEM_CONV (WOFF + 2 * TILEB)   // 229568

// ---------------- device scratch (static; allocation-free) ----------------
__device__ __align__(16) float g_s[(size_t)BB * CC * PP];
__device__ __align__(16) float g_y[(size_t)BB * CC * PP];
__device__ __align__(16) float g_h[(size_t)BB * NPADT * HIDD];

__device__ uint4 g_xp_hi[(size_t)BB * XROWS * 16];   // [b][row][128 ci] bf16, 256B rows
__device__ uint4 g_xp_lo[(size_t)BB * XROWS * 16];
__device__ uint4 g_hp_hi[(size_t)BB * NPADT * 32];   // [b][pos][256 hid] bf16, 512B rows
__device__ uint4 g_hp_lo[(size_t)BB * NPADT * 32];

__device__ uint4 g_wt_hi[9 * 128 * 16];              // [tap][oc][128 ci]
__device__ uint4 g_wt_lo[9 * 128 * 16];
__device__ uint4 g_w1_hi[3 * 256 * 16];              // [e][m256][k128]
__device__ uint4 g_w1_lo[3 * 256 * 16];
__device__ uint4 g_w2_hi[3 * 128 * 32];              // [e][oc128][k256]
__device__ uint4 g_w2_lo[3 * 128 * 32];

__device__ float g_bn_sum[CC], g_bn_sq[CC];
__device__ float g_bn_scale[CC], g_bn_shift[CC];
__device__ float g_gn1_sum[BB * NGG], g_gn1_sq[BB * NGG];
__device__ float g_gn1_mr[BB * NGG * 2];
__device__ float g_gn2_sum[BB * NGG], g_gn2_sq[BB * NGG];
__device__ float g_gn2_mr[BB * NGG * 2];

// ---------------- helpers ----------------
__device__ __forceinline__ uint32_t smem_u32(const void* p) {
    uint32_t a;
    asm("{ .reg .u64 t; cvta.to.shared.u64 t, %1; cvt.u32.u64 %0, t; }" : "=r"(a) : "l"(p));
    return a;
}

// FMA-only sigmoid (no MUFU)
__device__ __forceinline__ float fast_sigmoid(float t) {
    float z = -t * 1.442695041f;
    z = fminf(fmaxf(z, -60.f), 60.f);
    float fl = floorf(z);
    float f = z - fl;
    float p = 1.5403530e-4f;
    p = fmaf(p, f, 1.3333558e-3f);
    p = fmaf(p, f, 9.6181291e-3f);
    p = fmaf(p, f, 5.5504109e-2f);
    p = fmaf(p, f, 2.4022651e-1f);
    p = fmaf(p, f, 6.9314718e-1f);
    float two_f = fmaf(p, f, 1.0f);
    float ex = __int_as_float((127 + (int)fl) << 23) * two_f;   // exp(-t)
    float d = 1.f + ex;
    float r = __int_as_float(0x7EF311C3 - __float_as_int(d));
    r = r * (2.f - d * r);
    r = r * (2.f - d * r);
    r = r * (2.f - d * r);
    return r;
}

// stage one [128 rows][256B used] tile into smem [128][272B] via cp.async (16B ops)
__device__ __forceinline__ void stage_cp(uint32_t s_dst, const char* src, int rowStride, int tid) {
#pragma unroll
    for (int it = 0; it < 8; it++) {
        int idx = it * 256 + tid;          // 0..2047
        int r = idx >> 4, c = idx & 15;
        uint32_t d = s_dst + (uint32_t)(r * TROW + c * 16);
        const char* s = src + (size_t)r * rowStride + c * 16;
        asm volatile("cp.async.cg.shared.global [%0], [%1], 16;" :: "r"(d), "l"(s));
    }
}

// ---------------- small kernels ----------------
__global__ void k_zero() {
    int t = threadIdx.x;
    if (t < CC) { g_bn_sum[t] = 0.f; g_bn_sq[t] = 0.f; }
    if (t < BB * NGG) {
        g_gn1_sum[t] = 0.f; g_gn1_sq[t] = 0.f;
        g_gn2_sum[t] = 0.f; g_gn2_sq[t] = 0.f;
    }
}

__global__ void k_zero_xp() {
    int ro = blockIdx.x * 256 + threadIdx.x;
    if (ro >= XROWS) return;
    int b = blockIdx.y;
    int pos = ro - GUARD;
    bool interior = false;
    if (pos >= 0 && pos < NPAD) {
        int r = pos / 82, q = pos - r * 82;
        interior = (r >= 1 && r <= 80 && q >= 1 && q <= 80);
    }
    if (!interior) {
        uint4 z = make_uint4(0, 0, 0, 0);
        size_t base = ((size_t)b * XROWS + ro) * 16;
#pragma unroll
        for (int j = 0; j < 16; j++) { g_xp_hi[base + j] = z; g_xp_lo[base + j] = z; }
    }
}

__global__ __launch_bounds__(256) void k_pack_x(const float* __restrict__ x) {
    __shared__ float t[128 * 33];
    int tid = threadIdx.x, b = blockIdx.y, p0 = blockIdx.x * 32;
    const float* xb = x + (size_t)b * CC * PP;
#pragma unroll
    for (int i = 0; i < 16; i++) {
        int lin = i * 256 + tid;
        int c = lin >> 5, px = lin & 31;
        t[c * 33 + px] = xb[(size_t)c * PP + p0 + px];
    }
    __syncthreads();
    __nv_bfloat16* hiA = (__nv_bfloat16*)g_xp_hi;
    __nv_bfloat16* loA = (__nv_bfloat16*)g_xp_lo;
#pragma unroll
    for (int i = 0; i < 16; i++) {
        int lin = i * 256 + tid;
        int c = tid & 127, px = (lin >> 7) & 31;
        float v = t[c * 33 + px];
        int p = p0 + px;
        int r = p / 80, q = p - r * 80;
        int pos = (r + 1) * 82 + (q + 1);
        size_t a = ((size_t)b * XROWS + GUARD + pos) * 128 + c;
        __nv_bfloat16 hi = __float2bfloat16(v);
        hiA[a] = hi;
        loA[a] = __float2bfloat16(v - __bfloat162float(hi));
    }
}

__global__ void k_pack_w(const float* __restrict__ w,
                         const float* __restrict__ w1,
                         const float* __restrict__ w2) {
    int idx = blockIdx.x * 256 + threadIdx.x;   // 0..344063
    if (idx >= 344064) return;
    float v; __nv_bfloat16 *dh, *dl; int di;
    if (idx < 147456) {                          // conv: [t][oc][ci] <- w[oc][ci][t]
        int t = idx / 16384, rem = idx - t * 16384;
        int oc = rem >> 7, ci = rem & 127;
        v = w[((size_t)oc * 128 + ci) * 9 + t];
        dh = (__nv_bfloat16*)g_wt_hi; dl = (__nv_bfloat16*)g_wt_lo; di = idx;
    } else if (idx < 245760) {
        di = idx - 147456; v = w1[di];
        dh = (__nv_bfloat16*)g_w1_hi; dl = (__nv_bfloat16*)g_w1_lo;
    } else {
        di = idx - 245760; v = w2[di];
        dh = (__nv_bfloat16*)g_w2_hi; dl = (__nv_bfloat16*)g_w2_lo;
    }
    __nv_bfloat16 hi = __float2bfloat16(v);
    dh[di] = hi;
    dl[di] = __float2bfloat16(v - __bfloat162float(hi));
}

__global__ void k_fin_bn(const float* __restrict__ gamma, const float* __restrict__ beta) {
    int t = threadIdx.x;
    const float inv = 1.f / (float)(BB * PP);
    float m = g_bn_sum[t] * inv;
    float v = g_bn_sq[t] * inv - m * m;
    float sc = gamma[t] * rsqrtf(v + EPSV);
    g_bn_scale[t] = sc;
    g_bn_shift[t] = beta[t] - m * sc;
}
__global__ void k_fin_gn1() {
    int t = threadIdx.x;
    const float inv = 1.f / (float)((HIDD / NGG) * PP);
    float m = g_gn1_sum[t] * inv;
    float v = g_gn1_sq[t] * inv - m * m;
    g_gn1_mr[2 * t] = m;
    g_gn1_mr[2 * t + 1] = rsqrtf(v + EPSV);
}
__global__ void k_fin_gn2() {
    int t = threadIdx.x;
    const float inv = 1.f / (float)((CC / NGG) * PP);
    float m = g_gn2_sum[t] * inv;
    float v = g_gn2_sq[t] * inv - m * m;
    g_gn2_mr[2 * t] = m;
    g_gn2_mr[2 * t + 1] = rsqrtf(v + EPSV);
}

__global__ __launch_bounds__(256) void k_prep_h(const int* __restrict__ indices,
                                                const float* __restrict__ g1,
                                                const float* __restrict__ b1) {
    int b = blockIdx.y;
    int id = indices[b];
    if (id == 0) return;
    int e = id - 1;
    __shared__ float sa[256], sc[256];
    int tid = threadIdx.x;
    {
        int gg = tid >> 5;
        float mean = g_gn1_mr[(b * 8 + gg) * 2];
        float rstd = g_gn1_mr[(b * 8 + gg) * 2 + 1];
        float a = rstd * g1[e * 256 + tid];
        sa[tid] = a;
        sc[tid] = b1[e * 256 + tid] - mean * a;
    }
    __syncthreads();
    size_t base = (size_t)b * NPADT * 256;
    __nv_bfloat16* hiA = (__nv_bfloat16*)g_hp_hi;
    __nv_bfloat16* loA = (__nv_bfloat16*)g_hp_lo;
#pragma unroll
    for (int it = 0; it < 8; it++) {
        size_t l = (size_t)blockIdx.x * 2048 + it * 256 + tid;
        float v = g_h[base + l];
        int hid = (int)(l & 255);
        float t = fmaf(v, sa[hid], sc[hid]);
        float s = t * fast_sigmoid(t);
        __nv_bfloat16 hi = __float2bfloat16(s);
        hiA[base + l] = hi;
        loA[base + l] = __float2bfloat16(s - __bfloat162float(hi));
    }
}

// ============================================================================
// k_conv: conv3x3 as 27 accumulating warp-MMA passes over a SHARED halo window
// smem: [xwin_hi 294x272][xwin_lo 294x272][wbuf0 128x272][wbuf1 128x272]
// weight tiles ti=0..17: tap=ti>>1, islo=ti&1. wh tile -> passes (B=xh, B=xl);
// wl tile -> pass (B=xh).
// ============================================================================
__global__ __launch_bounds__(256) void k_conv() {
    extern __shared__ __align__(16) char smem[];
    const int tid = threadIdx.x, wid = tid >> 5, l = tid & 31;
    const int b = blockIdx.z;
    const int p0 = blockIdx.x * 128;

    const uint32_t sbase = smem_u32(smem);
    const int warp_m0 = (wid & 3) * 32;
    const int warp_n0 = (wid >> 2) * 64;
    const int quad = l >> 2, qt = l & 3;

    uint32_t aoff[2], boffr[4];
    {
        int rowA = l & 15, colA = l >> 4;
        aoff[0] = (uint32_t)((warp_m0 + rowA) * TROW + colA * 16);
        aoff[1] = aoff[0] + 16 * TROW;
        int rowB = ((l >> 4) << 3) + (l & 7);
        int colB = (l >> 3) & 1;
#pragma unroll
        for (int g = 0; g < 4; g++)
            boffr[g] = (uint32_t)((warp_n0 + g * 16 + rowB) * TROW + colB * 16);
    }

    float d[2][8][4];
#pragma unroll
    for (int i = 0; i < 2; i++)
#pragma unroll
        for (int j = 0; j < 8; j++)
#pragma unroll
            for (int k = 0; k < 4; k++) d[i][j][k] = 0.f;

    // stage x halo windows (once) + weight tile 0
    {
        const size_t g0 = (size_t)b * XROWS + GUARD + p0 - 83;
        const char* xh = (const char*)g_xp_hi + g0 * 256;
        const char* xl = (const char*)g_xp_lo + g0 * 256;
        for (int i = tid; i < XW_ROWS * 16; i += 256) {
            int r = i >> 4, c = i & 15;
            uint32_t dof = (uint32_t)(r * TROW + c * 16);
            const size_t sof = (size_t)r * 256 + c * 16;
            asm volatile("cp.async.cg.shared.global [%0], [%1], 16;"
                         :: "r"(sbase + dof), "l"(xh + sof));
            asm volatile("cp.async.cg.shared.global [%0], [%1], 16;"
                         :: "r"(sbase + XW_BYTES + dof), "l"(xl + sof));
        }
        stage_cp(sbase + WOFF, (const char*)g_wt_hi, 256, tid);
        asm volatile("cp.async.commit_group;" ::: "memory");
    }

    for (int ti = 0; ti < 18; ti++) {
        if (ti < 17) {
            int ntap = (ti + 1) >> 1, nlo = (ti + 1) & 1;
            const char* ws = (const char*)(nlo ? g_wt_lo : g_wt_hi) + (size_t)ntap * 32768;
            stage_cp(sbase + WOFF + (uint32_t)(((ti + 1) & 1) * TILEB), ws, 256, tid);
            asm volatile("cp.async.commit_group;" ::: "memory");
            asm volatile("cp.async.wait_group 1;" ::: "memory");
        } else {
            asm volatile("cp.async.wait_group 0;" ::: "memory");
        }
        __syncthreads();

        const int tap = ti >> 1, islo = ti & 1;
        const int kh = tap / 3, kw = tap - kh * 3;
        const uint32_t winbase = (uint32_t)(((kh - 1) * 82 + (kw - 1) + 83) * TROW);
        const uint32_t sA = sbase + WOFF + (uint32_t)((ti & 1) * TILEB);
        const int npass = islo ? 1 : 2;

#pragma unroll
        for (int ks = 0; ks < 8; ks++) {
            uint32_t af[2][4];
#pragma unroll
            for (int i = 0; i < 2; i++)
                asm volatile("ldmatrix.sync.aligned.m8n8.x4.shared.b16 {%0,%1,%2,%3}, [%4];"
                    : "=r"(af[i][0]), "=r"(af[i][1]), "=r"(af[i][2]), "=r"(af[i][3])
                    : "r"(sA + aoff[i] + ks * 32));
            for (int ps = 0; ps < npass; ps++) {
                const uint32_t xwb = sbase + (ps ? XW_BYTES : 0u) + winbase;
                uint32_t bf[4][4];
#pragma unroll
                for (int g = 0; g < 4; g++)
                    asm volatile("ldmatrix.sync.aligned.m8n8.x4.shared.b16 {%0,%1,%2,%3}, [%4];"
                        : "=r"(bf[g][0]), "=r"(bf[g][1]), "=r"(bf[g][2]), "=r"(bf[g][3])
                        : "r"(xwb + boffr[g] + ks * 32));
#pragma unroll
                for (int i = 0; i < 2; i++)
#pragma unroll
                    for (int j = 0; j < 8; j++) {
                        int g = j >> 1, s = (j & 1) * 2;
                        asm volatile(
                            "mma.sync.aligned.m16n8k16.row.col.f32.bf16.bf16.f32 "
                            "{%0,%1,%2,%3}, {%4,%5,%6,%7}, {%8,%9}, {%0,%1,%2,%3};"
                            : "+f"(d[i][j][0]), "+f"(d[i][j][1]), "+f"(d[i][j][2]), "+f"(d[i][j][3])
                            : "r"(af[i][0]), "r"(af[i][1]), "r"(af[i][2]), "r"(af[i][3]),
                              "r"(bf[g][s]), "r"(bf[g][s + 1]));
                    }
            }
        }
        __syncthreads();
    }

    // epilogue: write g_s (interior only) + BN partial stats (alias dead wbuf)
    float* ssum = (float*)(smem + WOFF);
    float* ssq  = ssum + 128;
    if (tid < 128) { ssum[tid] = 0.f; ssq[tid] = 0.f; }
    __syncthreads();

    float* dst = g_s + (size_t)b * CC * PP;
#pragma unroll
    for (int i = 0; i < 2; i++)
#pragma unroll
        for (int rh = 0; rh < 2; rh++) {
            int m = warp_m0 + 16 * i + quad + rh * 8;
            float ps = 0.f, pq = 0.f;
#pragma unroll
            for (int j = 0; j < 8; j++) {
                float v0 = d[i][j][rh * 2], v1 = d[i][j][rh * 2 + 1];
                int n = warp_n0 + 8 * j + 2 * qt;
                int pos = p0 + n;
                int r = pos / 82, q = pos - r * 82;
                bool in0 = (pos < NPAD) && r >= 1 && r <= 80 && q >= 1 && q <= 80;
                bool in1 = (pos + 1 < NPAD) && r >= 1 && r <= 80 && (q + 1) >= 1 && (q + 1) <= 80;
                if (in0) { dst[(size_t)m * PP + (r - 1) * 80 + (q - 1)] = v0; ps += v0; pq += v0 * v0; }
                if (in1) { dst[(size_t)m * PP + (r - 1) * 80 + q] = v1; ps += v1; pq += v1 * v1; }
            }
            ps += __shfl_down_sync(0xffffffffu, ps, 2);
            pq += __shfl_down_sync(0xffffffffu, pq, 2);
            ps += __shfl_down_sync(0xffffffffu, ps, 1);
            pq += __shfl_down_sync(0xffffffffu, pq, 1);
            if (qt == 0) { atomicAdd(&ssum[m], ps); atomicAdd(&ssq[m], pq); }
        }

    __syncthreads();
    if (tid < 128) {
        atomicAdd(&g_bn_sum[tid], ssum[tid]);
        atomicAdd(&g_bn_sq[tid], ssq[tid]);
    }
}

// ---------------- chunk source resolver (gemm1/gemm2) ----------------
template<int MODE>
__device__ __forceinline__ void chunk_src(int c, int b, int e, int p0, int m0,
                                          const char** as, int* astr,
                                          const char** bs, int* bstr) {
    if (MODE == 1) {
        int part = c;
        *as = (const char*)(part == 2 ? g_w1_lo : g_w1_hi)
            + (size_t)e * 65536 + (size_t)m0 * 256;
        *astr = 256;
        *bs = (const char*)(part == 1 ? g_xp_lo : g_xp_hi)
            + ((size_t)b * XROWS + GUARD + p0) * 256;
        *bstr = 256;
    } else {
        int part = c >> 1, kh = c & 1;
        *as = (const char*)(part == 2 ? g_w2_lo : g_w2_hi)
            + (size_t)e * 65536 + (size_t)kh * 256;
        *astr = 512;
        *bs = (const char*)(part == 1 ? g_hp_lo : g_hp_hi)
            + ((size_t)b * NPADT + p0) * 512 + (size_t)kh * 256;
        *bstr = 512;
    }
}

// ---------------- warp-MMA GEMM kernel (gemm1 / gemm2) ----------------
// MODE 1: gemm1 w1@x (3 chunks)  -> g_h + GN1 stats
// MODE 2: gemm2 w2@hp (6 chunks) -> g_y + GN2 stats
template<int MODE>
__global__ __launch_bounds__(256) void k_mma(const int* __restrict__ indices) {
    extern __shared__ __align__(16) char smem[];
    __shared__ float ssum[128], ssq[128];

    const int tid = threadIdx.x, wid = tid >> 5, l = tid & 31;
    const int b = blockIdx.z;
    int id = indices[b];
    if (id == 0) return;
    int e = id - 1;
    const int p0 = blockIdx.x * 128;
    const int m0 = blockIdx.y * 128;

    if (tid < 128) { ssum[tid] = 0.f; ssq[tid] = 0.f; }

    const uint32_t sbase = smem_u32(smem);
    const int warp_m0 = (wid & 3) * 32;
    const int warp_n0 = (wid >> 2) * 64;
    const int quad = l >> 2, qt = l & 3;

    uint32_t aoff[2], boff[4];
    {
        int rowA = l & 15, colA = l >> 4;
        aoff[0] = (uint32_t)((warp_m0 + rowA) * TROW + colA * 16);
        aoff[1] = aoff[0] + 16 * TROW;
        int rowB = ((l >> 4) << 3) + (l & 7);
        int colB = (l >> 3) & 1;
#pragma unroll
        for (int g = 0; g < 4; g++)
            boff[g] = (uint32_t)((warp_n0 + g * 16 + rowB) * TROW + colB * 16);
    }

    float d[2][8][4];
#pragma unroll
    for (int i = 0; i < 2; i++)
#pragma unroll
        for (int j = 0; j < 8; j++)
#pragma unroll
            for (int k = 0; k < 4; k++) d[i][j][k] = 0.f;

    const int NC = (MODE == 1) ? 3 : 6;

    {
        const char *as, *bs; int astr, bstr;
        chunk_src<MODE>(0, b, e, p0, m0, &as, &astr, &bs, &bstr);
        stage_cp(sbase, as, astr, tid);
        stage_cp(sbase + TILEB, bs, bstr, tid);
        asm volatile("cp.async.commit_group;" ::: "memory");
    }

    for (int c = 0; c < NC; c++) {
        if (c + 1 < NC) {
            const char *as, *bs; int astr, bstr;
            chunk_src<MODE>(c + 1, b, e, p0, m0, &as, &astr, &bs, &bstr);
            uint32_t nb = sbase + (uint32_t)(((c + 1) & 1) * BUFB);
            stage_cp(nb, as, astr, tid);
            stage_cp(nb + TILEB, bs, bstr, tid);
            asm volatile("cp.async.commit_group;" ::: "memory");
            asm volatile("cp.async.wait_group 1;" ::: "memory");
        } else {
            asm volatile("cp.async.wait_group 0;" ::: "memory");
        }
        __syncthreads();

        const uint32_t sA = sbase + (uint32_t)((c & 1) * BUFB);
        const uint32_t sB = sA + TILEB;

#pragma unroll
        for (int ks = 0; ks < 8; ks++) {
            uint32_t af[2][4], bf[4][4];
#pragma unroll
            for (int i = 0; i < 2; i++)
                asm volatile("ldmatrix.sync.aligned.m8n8.x4.shared.b16 {%0,%1,%2,%3}, [%4];"
                    : "=r"(af[i][0]), "=r"(af[i][1]), "=r"(af[i][2]), "=r"(af[i][3])
                    : "r"(sA + aoff[i] + ks * 32));
#pragma unroll
            for (int g = 0; g < 4; g++)
                asm volatile("ldmatrix.sync.aligned.m8n8.x4.shared.b16 {%0,%1,%2,%3}, [%4];"
                    : "=r"(bf[g][0]), "=r"(bf[g][1]), "=r"(bf[g][2]), "=r"(bf[g][3])
                    : "r"(sB + boff[g] + ks * 32));
#pragma unroll
            for (int i = 0; i < 2; i++)
#pragma unroll
                for (int j = 0; j < 8; j++) {
                    int g = j >> 1, s = (j & 1) * 2;
                    asm volatile(
                        "mma.sync.aligned.m16n8k16.row.col.f32.bf16.bf16.f32 "
                        "{%0,%1,%2,%3}, {%4,%5,%6,%7}, {%8,%9}, {%0,%1,%2,%3};"
                        : "+f"(d[i][j][0]), "+f"(d[i][j][1]), "+f"(d[i][j][2]), "+f"(d[i][j][3])
                        : "r"(af[i][0]), "r"(af[i][1]), "r"(af[i][2]), "r"(af[i][3]),
                          "r"(bf[g][s]), "r"(bf[g][s + 1]));
                }
        }
        __syncthreads();
    }

    // ---------------- epilogue ----------------
    if (MODE == 1) {
        float* hb = g_h + (size_t)b * NPADT * 256;
#pragma unroll
        for (int i = 0; i < 2; i++)
#pragma unroll
            for (int rh = 0; rh < 2; rh++) {
                int m = warp_m0 + 16 * i + quad + rh * 8;
                float ps = 0.f, pq = 0.f;
#pragma unroll
                for (int j = 0; j < 8; j++) {
                    float v0 = d[i][j][rh * 2], v1 = d[i][j][rh * 2 + 1];
                    int n = warp_n0 + 8 * j + 2 * qt;
                    int pos = p0 + n;
                    hb[(size_t)pos * 256 + m0 + m] = v0;
                    hb[(size_t)(pos + 1) * 256 + m0 + m] = v1;
                    int r = pos / 82, q = pos - r * 82;
                    bool in0 = (pos < NPAD) && r >= 1 && r <= 80 && q >= 1 && q <= 80;
                    bool in1 = (pos + 1 < NPAD) && r >= 1 && r <= 80 && (q + 1) >= 1 && (q + 1) <= 80;
                    if (in0) { ps += v0; pq += v0 * v0; }
                    if (in1) { ps += v1; pq += v1 * v1; }
                }
                ps += __shfl_down_sync(0xffffffffu, ps, 2);
                pq += __shfl_down_sync(0xffffffffu, pq, 2);
                ps += __shfl_down_sync(0xffffffffu, ps, 1);
                pq += __shfl_down_sync(0xffffffffu, pq, 1);
                if (qt == 0) { atomicAdd(&ssum[m], ps); atomicAdd(&ssq[m], pq); }
            }
    } else {
        float* dst = g_y + (size_t)b * CC * PP;
#pragma unroll
        for (int i = 0; i < 2; i++)
#pragma unroll
            for (int rh = 0; rh < 2; rh++) {
                int m = warp_m0 + 16 * i + quad + rh * 8;
                float ps = 0.f, pq = 0.f;
#pragma unroll
                for (int j = 0; j < 8; j++) {
                    float v0 = d[i][j][rh * 2], v1 = d[i][j][rh * 2 + 1];
                    int n = warp_n0 + 8 * j + 2 * qt;
                    int pos = p0 + n;
                    int r = pos / 82, q = pos - r * 82;
                    bool in0 = (pos < NPAD) && r >= 1 && r <= 80 && q >= 1 && q <= 80;
                    bool in1 = (pos + 1 < NPAD) && r >= 1 && r <= 80 && (q + 1) >= 1 && (q + 1) <= 80;
                    if (in0) { dst[(size_t)m * PP + (r - 1) * 80 + (q - 1)] = v0; ps += v0; pq += v0 * v0; }
                    if (in1) { dst[(size_t)m * PP + (r - 1) * 80 + q] = v1; ps += v1; pq += v1 * v1; }
                }
                ps += __shfl_down_sync(0xffffffffu, ps, 2);
                pq += __shfl_down_sync(0xffffffffu, pq, 2);
                ps += __shfl_down_sync(0xffffffffu, ps, 1);
                pq += __shfl_down_sync(0xffffffffu, pq, 1);
                if (qt == 0) { atomicAdd(&ssum[m], ps); atomicAdd(&ssq[m], pq); }
            }
    }

    __syncthreads();
    if (tid < 128) {
        if (MODE == 1) {
            atomicAdd(&g_gn1_sum[b * NGG + ((m0 + tid) >> 5)], ssum[tid]);
            atomicAdd(&g_gn1_sq[b * NGG + ((m0 + tid) >> 5)], ssq[tid]);
        } else {
            atomicAdd(&g_gn2_sum[b * NGG + (tid >> 4)], ssum[tid]);
            atomicAdd(&g_gn2_sq[b * NGG + (tid >> 4)], ssq[tid]);
        }
    }
}

// ---------------- combine ----------------
__global__ __launch_bounds__(256) void k_combine(const float* __restrict__ x,
                                                 const float* __restrict__ weights,
                                                 const int* __restrict__ indices,
                                                 const float* __restrict__ g2,
                                                 const float* __restrict__ b2,
                                                 float* __restrict__ out) {
    const int blk = blockIdx.x;
    const int b = blk >> 7, c = blk & 127;
    const int idx = indices[b];
    const float wb = weights[b];
    const float sc = g_bn_scale[c], sh = g_bn_shift[c];

    float a2, c2;
    if (idx > 0) {
        int e = idx - 1;
        int g = c >> 4;
        float mean = g_gn2_mr[(b * NGG + g) * 2];
        float rstd = g_gn2_mr[(b * NGG + g) * 2 + 1];
        float ga = rstd * g2[e * CC + c];
        a2 = ga * wb;
        c2 = (b2[e * CC + c] - mean * ga) * wb;
    } else {
        a2 = wb;
        c2 = 0.f;
    }

    const size_t base = ((size_t)b * CC + c) * PP;
    const float4* sp = (const float4*)(g_s + base);
    const float4* rp = (idx > 0) ? (const float4*)(g_y + base) : (const float4*)(x + base);
    float4* op = (float4*)(out + base);

    for (int i = threadIdx.x; i < PP / 4; i += 256) {
        float4 sv = sp[i];
        float4 rv = rp[i];
        float4 o;
        float t;
        t = fmaf(sv.x, sc, sh); o.x = t * fast_sigmoid(t) + fmaf(rv.x, a2, c2);
        t = fmaf(sv.y, sc, sh); o.y = t * fast_sigmoid(t) + fmaf(rv.y, a2, c2);
        t = fmaf(sv.z, sc, sh); o.z = t * fast_sigmoid(t) + fmaf(rv.z, a2, c2);
        t = fmaf(sv.w, sc, sh); o.w = t * fast_sigmoid(t) + fmaf(rv.w, a2, c2);
        op[i] = o;
    }
}

// ---------------- launch ----------------
extern "C" void kernel_launch(void* const* d_in, const int* in_sizes, int n_in,
                              void* d_out, int out_size) {
    const float* x        = (const float*)d_in[0];
    const float* weights  = (const float*)d_in[1];
    const int*   indices  = (const int*)d_in[2];
    const float* shared_w = (const float*)d_in[3];
    const float* bn_gamma = (const float*)d_in[4];
    const float* bn_beta  = (const float*)d_in[5];
    const float* w1       = (const float*)d_in[6];
    const float* g1       = (const float*)d_in[7];
    const float* b1       = (const float*)d_in[8];
    const float* w2       = (const float*)d_in[9];
    const float* g2       = (const float*)d_in[10];
    const float* b2       = (const float*)d_in[11];
    float* out = (float*)d_out;

    cudaFuncSetAttribute(k_conv, cudaFuncAttributeMaxDynamicSharedMemorySize, SMEM_CONV);
    cudaFuncSetAttribute(k_mma<1>, cudaFuncAttributeMaxDynamicSharedMemorySize, SMEMB);
    cudaFuncSetAttribute(k_mma<2>, cudaFuncAttributeMaxDynamicSharedMemorySize, SMEMB);

    k_zero<<<1, 256>>>();
    k_zero_xp<<<dim3(28, BB), 256>>>();
    k_pack_x<<<dim3(200, BB), 256>>>(x);
    k_pack_w<<<1344, 256>>>(shared_w, w1, w2);

    k_conv<<<dim3(53, 1, BB), 256, SMEM_CONV>>>();        // conv3x3 + BN stats
    k_mma<1><<<dim3(53, 2, BB), 256, SMEMB>>>(indices);   // gemm1 + GN1 stats
    k_fin_bn<<<1, 128>>>(bn_gamma, bn_beta);
    k_fin_gn1<<<1, 128>>>();
    k_prep_h<<<dim3(848, BB), 256>>>(indices, g1, b1);
    k_mma<2><<<dim3(53, 1, BB), 256, SMEMB>>>(indices);   // gemm2 + GN2 stats
    k_fin_gn2<<<1, 128>>>();
    k_combine<<<BB * CC, 256>>>(x, weights, indices, g2, b2, out);
}

// round 9
// speedup vs baseline: 2.3819x; 1.2849x over previous
#include <cuda_runtime.h>
#include <cuda_bf16.h>
#include <cstdint>

// ---------------- shapes ----------------
#define BB    16
#define CC    128
#define HIDD  256
#define PP    6400
#define NGG   8
#define EPSV  1e-5f

#define NPAD  6724      // 82*82
#define NPADT 6784      // 53 tiles * 128
#define GUARD 128
#define XROWS 7040      // GUARD + NPADT + GUARD

// smem tile geometry: [128 rows][136 bf16] = 272 B/row (16B-aligned, conflict-free ldmatrix)
#define TROW   272
#define TILEB  34816    // 128*272
#define BUFB   69632    // A tile + B tile
#define SMEMB  139264   // double buffered (gemm1 path)

// conv halo-window smem layout
#define XW_ROWS 294     // rows p0-83 .. p0+210
#define XW_BYTES (XW_ROWS * TROW)      // 79968
#define WOFF     (2 * XW_BYTES)        // 159936
#define SMEM_CONV (WOFF + 2 * TILEB)   // 229568 (merged conv+gemm1 kernel uses this)

// gemm2 smem: 4 A tiles (hi/lo x kh0/kh1) + B_hi + B_lo
#define SMEM_G2 (6 * TILEB)            // 208896

// ---------------- device scratch (static; allocation-free) ----------------
__device__ __align__(16) float g_s[(size_t)BB * CC * PP];
__device__ __align__(16) float g_y[(size_t)BB * CC * PP];
__device__ __align__(16) float g_h[(size_t)BB * NPADT * HIDD];   // f32 [b][pos][256]

__device__ uint4 g_xp_hi[(size_t)BB * XROWS * 16];   // [b][row][128 ci] bf16, 256B rows
__device__ uint4 g_xp_lo[(size_t)BB * XROWS * 16];

__device__ uint4 g_wt_hi[9 * 128 * 16];              // [tap][oc][128 ci]
__device__ uint4 g_wt_lo[9 * 128 * 16];
__device__ uint4 g_w1_hi[3 * 256 * 16];              // [e][m256][k128]
__device__ uint4 g_w1_lo[3 * 256 * 16];
__device__ uint4 g_w2_hi[3 * 128 * 32];              // [e][oc128][k256]
__device__ uint4 g_w2_lo[3 * 128 * 32];

__device__ float g_bn_sum[CC], g_bn_sq[CC];
__device__ float g_bn_scale[CC], g_bn_shift[CC];
__device__ float g_gn1_sum[BB * NGG], g_gn1_sq[BB * NGG];
__device__ float g_gn1_mr[BB * NGG * 2];
__device__ float g_gn2_sum[BB * NGG], g_gn2_sq[BB * NGG];
__device__ float g_gn2_mr[BB * NGG * 2];

// ---------------- helpers ----------------
__device__ __forceinline__ uint32_t smem_u32(const void* p) {
    uint32_t a;
    asm("{ .reg .u64 t; cvta.to.shared.u64 t, %1; cvt.u32.u64 %0, t; }" : "=r"(a) : "l"(p));
    return a;
}

// FMA-only sigmoid (no MUFU)
__device__ __forceinline__ float fast_sigmoid(float t) {
    float z = -t * 1.442695041f;
    z = fminf(fmaxf(z, -60.f), 60.f);
    float fl = floorf(z);
    float f = z - fl;
    float p = 1.5403530e-4f;
    p = fmaf(p, f, 1.3333558e-3f);
    p = fmaf(p, f, 9.6181291e-3f);
    p = fmaf(p, f, 5.5504109e-2f);
    p = fmaf(p, f, 2.4022651e-1f);
    p = fmaf(p, f, 6.9314718e-1f);
    float two_f = fmaf(p, f, 1.0f);
    float ex = __int_as_float((127 + (int)fl) << 23) * two_f;   // exp(-t)
    float d = 1.f + ex;
    float r = __int_as_float(0x7EF311C3 - __float_as_int(d));
    r = r * (2.f - d * r);
    r = r * (2.f - d * r);
    r = r * (2.f - d * r);
    return r;
}

// stage one [128 rows][256B used] tile into smem [128][272B] via cp.async (16B ops)
__device__ __forceinline__ void stage_cp(uint32_t s_dst, const char* src, int rowStride, int tid) {
#pragma unroll
    for (int it = 0; it < 8; it++) {
        int idx = it * 256 + tid;          // 0..2047
        int r = idx >> 4, c = idx & 15;
        uint32_t d = s_dst + (uint32_t)(r * TROW + c * 16);
        const char* s = src + (size_t)r * rowStride + c * 16;
        asm volatile("cp.async.cg.shared.global [%0], [%1], 16;" :: "r"(d), "l"(s));
    }
}

// ---------------- small kernels ----------------
__global__ void k_zero() {
    int t = threadIdx.x;
    if (t < CC) { g_bn_sum[t] = 0.f; g_bn_sq[t] = 0.f; }
    if (t < BB * NGG) {
        g_gn1_sum[t] = 0.f; g_gn1_sq[t] = 0.f;
        g_gn2_sum[t] = 0.f; g_gn2_sq[t] = 0.f;
    }
}

__global__ void k_zero_xp() {
    int ro = blockIdx.x * 256 + threadIdx.x;
    if (ro >= XROWS) return;
    int b = blockIdx.y;
    int pos = ro - GUARD;
    bool interior = false;
    if (pos >= 0 && pos < NPAD) {
        int r = pos / 82, q = pos - r * 82;
        interior = (r >= 1 && r <= 80 && q >= 1 && q <= 80);
    }
    if (!interior) {
        uint4 z = make_uint4(0, 0, 0, 0);
        size_t base = ((size_t)b * XROWS + ro) * 16;
#pragma unroll
        for (int j = 0; j < 16; j++) { g_xp_hi[base + j] = z; g_xp_lo[base + j] = z; }
    }
}

__global__ __launch_bounds__(256) void k_pack_x(const float* __restrict__ x) {
    __shared__ float t[128 * 33];
    int tid = threadIdx.x, b = blockIdx.y, p0 = blockIdx.x * 32;
    const float* xb = x + (size_t)b * CC * PP;
#pragma unroll
    for (int i = 0; i < 16; i++) {
        int lin = i * 256 + tid;
        int c = lin >> 5, px = lin & 31;
        t[c * 33 + px] = xb[(size_t)c * PP + p0 + px];
    }
    __syncthreads();
    __nv_bfloat16* hiA = (__nv_bfloat16*)g_xp_hi;
    __nv_bfloat16* loA = (__nv_bfloat16*)g_xp_lo;
#pragma unroll
    for (int i = 0; i < 16; i++) {
        int lin = i * 256 + tid;
        int c = tid & 127, px = (lin >> 7) & 31;
        float v = t[c * 33 + px];
        int p = p0 + px;
        int r = p / 80, q = p - r * 80;
        int pos = (r + 1) * 82 + (q + 1);
        size_t a = ((size_t)b * XROWS + GUARD + pos) * 128 + c;
        __nv_bfloat16 hi = __float2bfloat16(v);
        hiA[a] = hi;
        loA[a] = __float2bfloat16(v - __bfloat162float(hi));
    }
}

__global__ void k_pack_w(const float* __restrict__ w,
                         const float* __restrict__ w1,
                         const float* __restrict__ w2) {
    int idx = blockIdx.x * 256 + threadIdx.x;   // 0..344063
    if (idx >= 344064) return;
    float v; __nv_bfloat16 *dh, *dl; int di;
    if (idx < 147456) {                          // conv: [t][oc][ci] <- w[oc][ci][t]
        int t = idx / 16384, rem = idx - t * 16384;
        int oc = rem >> 7, ci = rem & 127;
        v = w[((size_t)oc * 128 + ci) * 9 + t];
        dh = (__nv_bfloat16*)g_wt_hi; dl = (__nv_bfloat16*)g_wt_lo; di = idx;
    } else if (idx < 245760) {
        di = idx - 147456; v = w1[di];
        dh = (__nv_bfloat16*)g_w1_hi; dl = (__nv_bfloat16*)g_w1_lo;
    } else {
        di = idx - 245760; v = w2[di];
        dh = (__nv_bfloat16*)g_w2_hi; dl = (__nv_bfloat16*)g_w2_lo;
    }
    __nv_bfloat16 hi = __float2bfloat16(v);
    dh[di] = hi;
    dl[di] = __float2bfloat16(v - __bfloat162float(hi));
}

// fin_bn (tid<128) + fin_gn1 (tid>=128) in one launch
__global__ void k_fin1(const float* __restrict__ gamma, const float* __restrict__ beta) {
    int t = threadIdx.x;   // 256
    if (t < 128) {
        const float inv = 1.f / (float)(BB * PP);
        float m = g_bn_sum[t] * inv;
        float v = g_bn_sq[t] * inv - m * m;
        float sc = gamma[t] * rsqrtf(v + EPSV);
        g_bn_scale[t] = sc;
        g_bn_shift[t] = beta[t] - m * sc;
    } else {
        int u = t - 128;
        const float inv = 1.f / (float)((HIDD / NGG) * PP);
        float m = g_gn1_sum[u] * inv;
        float v = g_gn1_sq[u] * inv - m * m;
        g_gn1_mr[2 * u] = m;
        g_gn1_mr[2 * u + 1] = rsqrtf(v + EPSV);
    }
}

__global__ void k_fin_gn2() {
    int t = threadIdx.x;
    const float inv = 1.f / (float)((CC / NGG) * PP);
    float m = g_gn2_sum[t] * inv;
    float v = g_gn2_sq[t] * inv - m * m;
    g_gn2_mr[2 * t] = m;
    g_gn2_mr[2 * t + 1] = rsqrtf(v + EPSV);
}

// ============================================================================
// merged conv3x3 + gemm1 kernel. blockIdx.y == 0 -> conv; 1,2 -> gemm1 m-half.
// ============================================================================
__device__ __forceinline__ void conv_body(char* smem, const int tid, const int b, const int p0) {
    const int wid = tid >> 5, l = tid & 31;
    const uint32_t sbase = smem_u32(smem);
    const int warp_m0 = (wid & 3) * 32;
    const int warp_n0 = (wid >> 2) * 64;
    const int quad = l >> 2, qt = l & 3;

    uint32_t aoff[2], boffr[4];
    {
        int rowA = l & 15, colA = l >> 4;
        aoff[0] = (uint32_t)((warp_m0 + rowA) * TROW + colA * 16);
        aoff[1] = aoff[0] + 16 * TROW;
        int rowB = ((l >> 4) << 3) + (l & 7);
        int colB = (l >> 3) & 1;
#pragma unroll
        for (int g = 0; g < 4; g++)
            boffr[g] = (uint32_t)((warp_n0 + g * 16 + rowB) * TROW + colB * 16);
    }

    float d[2][8][4];
#pragma unroll
    for (int i = 0; i < 2; i++)
#pragma unroll
        for (int j = 0; j < 8; j++)
#pragma unroll
            for (int k = 0; k < 4; k++) d[i][j][k] = 0.f;

    // stage x halo windows (once) + weight tile 0
    {
        const size_t g0 = (size_t)b * XROWS + GUARD + p0 - 83;
        const char* xh = (const char*)g_xp_hi + g0 * 256;
        const char* xl = (const char*)g_xp_lo + g0 * 256;
        for (int i = tid; i < XW_ROWS * 16; i += 256) {
            int r = i >> 4, c = i & 15;
            uint32_t dof = (uint32_t)(r * TROW + c * 16);
            const size_t sof = (size_t)r * 256 + c * 16;
            asm volatile("cp.async.cg.shared.global [%0], [%1], 16;"
                         :: "r"(sbase + dof), "l"(xh + sof));
            asm volatile("cp.async.cg.shared.global [%0], [%1], 16;"
                         :: "r"(sbase + XW_BYTES + dof), "l"(xl + sof));
        }
        stage_cp(sbase + WOFF, (const char*)g_wt_hi, 256, tid);
        asm volatile("cp.async.commit_group;" ::: "memory");
    }

    for (int ti = 0; ti < 18; ti++) {
        if (ti < 17) {
            int ntap = (ti + 1) >> 1, nlo = (ti + 1) & 1;
            const char* ws = (const char*)(nlo ? g_wt_lo : g_wt_hi) + (size_t)ntap * 32768;
            stage_cp(sbase + WOFF + (uint32_t)(((ti + 1) & 1) * TILEB), ws, 256, tid);
            asm volatile("cp.async.commit_group;" ::: "memory");
            asm volatile("cp.async.wait_group 1;" ::: "memory");
        } else {
            asm volatile("cp.async.wait_group 0;" ::: "memory");
        }
        __syncthreads();

        const int tap = ti >> 1, islo = ti & 1;
        const int kh = tap / 3, kw = tap - kh * 3;
        const uint32_t winbase = (uint32_t)(((kh - 1) * 82 + (kw - 1) + 83) * TROW);
        const uint32_t sA = sbase + WOFF + (uint32_t)((ti & 1) * TILEB);
        const int npass = islo ? 1 : 2;

#pragma unroll
        for (int ks = 0; ks < 8; ks++) {
            uint32_t af[2][4];
#pragma unroll
            for (int i = 0; i < 2; i++)
                asm volatile("ldmatrix.sync.aligned.m8n8.x4.shared.b16 {%0,%1,%2,%3}, [%4];"
                    : "=r"(af[i][0]), "=r"(af[i][1]), "=r"(af[i][2]), "=r"(af[i][3])
                    : "r"(sA + aoff[i] + ks * 32));
            for (int ps = 0; ps < npass; ps++) {
                const uint32_t xwb = sbase + (ps ? XW_BYTES : 0u) + winbase;
                uint32_t bf[4][4];
#pragma unroll
                for (int g = 0; g < 4; g++)
                    asm volatile("ldmatrix.sync.aligned.m8n8.x4.shared.b16 {%0,%1,%2,%3}, [%4];"
                        : "=r"(bf[g][0]), "=r"(bf[g][1]), "=r"(bf[g][2]), "=r"(bf[g][3])
                        : "r"(xwb + boffr[g] + ks * 32));
#pragma unroll
                for (int i = 0; i < 2; i++)
#pragma unroll
                    for (int j = 0; j < 8; j++) {
                        int g = j >> 1, s = (j & 1) * 2;
                        asm volatile(
                            "mma.sync.aligned.m16n8k16.row.col.f32.bf16.bf16.f32 "
                            "{%0,%1,%2,%3}, {%4,%5,%6,%7}, {%8,%9}, {%0,%1,%2,%3};"
                            : "+f"(d[i][j][0]), "+f"(d[i][j][1]), "+f"(d[i][j][2]), "+f"(d[i][j][3])
                            : "r"(af[i][0]), "r"(af[i][1]), "r"(af[i][2]), "r"(af[i][3]),
                              "r"(bf[g][s]), "r"(bf[g][s + 1]));
                    }
            }
        }
        __syncthreads();
    }

    // epilogue: write g_s (interior only) + BN partial stats (alias dead wbuf)
    float* ssum = (float*)(smem + WOFF);
    float* ssq  = ssum + 128;
    if (tid < 128) { ssum[tid] = 0.f; ssq[tid] = 0.f; }
    __syncthreads();

    float* dst = g_s + (size_t)b * CC * PP;
#pragma unroll
    for (int i = 0; i < 2; i++)
#pragma unroll
        for (int rh = 0; rh < 2; rh++) {
            int m = warp_m0 + 16 * i + quad + rh * 8;
            float ps = 0.f, pq = 0.f;
#pragma unroll
            for (int j = 0; j < 8; j++) {
                float v0 = d[i][j][rh * 2], v1 = d[i][j][rh * 2 + 1];
                int n = warp_n0 + 8 * j + 2 * qt;
                int pos = p0 + n;
                int r = pos / 82, q = pos - r * 82;
                bool in0 = (pos < NPAD) && r >= 1 && r <= 80 && q >= 1 && q <= 80;
                bool in1 = (pos + 1 < NPAD) && r >= 1 && r <= 80 && (q + 1) >= 1 && (q + 1) <= 80;
                if (in0) { dst[(size_t)m * PP + (r - 1) * 80 + (q - 1)] = v0; ps += v0; pq += v0 * v0; }
                if (in1) { dst[(size_t)m * PP + (r - 1) * 80 + q] = v1; ps += v1; pq += v1 * v1; }
            }
            ps += __shfl_down_sync(0xffffffffu, ps, 2);
            pq += __shfl_down_sync(0xffffffffu, pq, 2);
            ps += __shfl_down_sync(0xffffffffu, ps, 1);
            pq += __shfl_down_sync(0xffffffffu, pq, 1);
            if (qt == 0) { atomicAdd(&ssum[m], ps); atomicAdd(&ssq[m], pq); }
        }

    __syncthreads();
    if (tid < 128) {
        atomicAdd(&g_bn_sum[tid], ssum[tid]);
        atomicAdd(&g_bn_sq[tid], ssq[tid]);
    }
}

__device__ __forceinline__ void gemm1_body(char* smem, const int tid, const int b, const int e,
                                           const int p0, const int m0) {
    __shared__ float ssum[128], ssq[128];
    const int wid = tid >> 5, l = tid & 31;
    if (tid < 128) { ssum[tid] = 0.f; ssq[tid] = 0.f; }

    const uint32_t sbase = smem_u32(smem);
    const int warp_m0 = (wid & 3) * 32;
    const int warp_n0 = (wid >> 2) * 64;
    const int quad = l >> 2, qt = l & 3;

    uint32_t aoff[2], boff[4];
    {
        int rowA = l & 15, colA = l >> 4;
        aoff[0] = (uint32_t)((warp_m0 + rowA) * TROW + colA * 16);
        aoff[1] = aoff[0] + 16 * TROW;
        int rowB = ((l >> 4) << 3) + (l & 7);
        int colB = (l >> 3) & 1;
#pragma unroll
        for (int g = 0; g < 4; g++)
            boff[g] = (uint32_t)((warp_n0 + g * 16 + rowB) * TROW + colB * 16);
    }

    float d[2][8][4];
#pragma unroll
    for (int i = 0; i < 2; i++)
#pragma unroll
        for (int j = 0; j < 8; j++)
#pragma unroll
            for (int k = 0; k < 4; k++) d[i][j][k] = 0.f;

    // chunk sources: part 0 = w1_hi x xh, 1 = w1_hi x xl, 2 = w1_lo x xh
    const char* bsx_hi = (const char*)g_xp_hi + ((size_t)b * XROWS + GUARD + p0) * 256;
    const char* bsx_lo = (const char*)g_xp_lo + ((size_t)b * XROWS + GUARD + p0) * 256;
    {
        const char* as = (const char*)g_w1_hi + (size_t)e * 65536 + (size_t)m0 * 256;
        stage_cp(sbase, as, 256, tid);
        stage_cp(sbase + TILEB, bsx_hi, 256, tid);
        asm volatile("cp.async.commit_group;" ::: "memory");
    }

    for (int c = 0; c < 3; c++) {
        if (c + 1 < 3) {
            const char* as = (const char*)(c + 1 == 2 ? g_w1_lo : g_w1_hi)
                           + (size_t)e * 65536 + (size_t)m0 * 256;
            const char* bs = (c + 1 == 1) ? bsx_lo : bsx_hi;
            uint32_t nb = sbase + (uint32_t)(((c + 1) & 1) * BUFB);
            stage_cp(nb, as, 256, tid);
            stage_cp(nb + TILEB, bs, 256, tid);
            asm volatile("cp.async.commit_group;" ::: "memory");
            asm volatile("cp.async.wait_group 1;" ::: "memory");
        } else {
            asm volatile("cp.async.wait_group 0;" ::: "memory");
        }
        __syncthreads();

        const uint32_t sA = sbase + (uint32_t)((c & 1) * BUFB);
        const uint32_t sB = sA + TILEB;

#pragma unroll
        for (int ks = 0; ks < 8; ks++) {
            uint32_t af[2][4], bf[4][4];
#pragma unroll
            for (int i = 0; i < 2; i++)
                asm volatile("ldmatrix.sync.aligned.m8n8.x4.shared.b16 {%0,%1,%2,%3}, [%4];"
                    : "=r"(af[i][0]), "=r"(af[i][1]), "=r"(af[i][2]), "=r"(af[i][3])
                    : "r"(sA + aoff[i] + ks * 32));
#pragma unroll
            for (int g = 0; g < 4; g++)
                asm volatile("ldmatrix.sync.aligned.m8n8.x4.shared.b16 {%0,%1,%2,%3}, [%4];"
                    : "=r"(bf[g][0]), "=r"(bf[g][1]), "=r"(bf[g][2]), "=r"(bf[g][3])
                    : "r"(sB + boff[g] + ks * 32));
#pragma unroll
            for (int i = 0; i < 2; i++)
#pragma unroll
                for (int j = 0; j < 8; j++) {
                    int g = j >> 1, s = (j & 1) * 2;
                    asm volatile(
                        "mma.sync.aligned.m16n8k16.row.col.f32.bf16.bf16.f32 "
                        "{%0,%1,%2,%3}, {%4,%5,%6,%7}, {%8,%9}, {%0,%1,%2,%3};"
                        : "+f"(d[i][j][0]), "+f"(d[i][j][1]), "+f"(d[i][j][2]), "+f"(d[i][j][3])
                        : "r"(af[i][0]), "r"(af[i][1]), "r"(af[i][2]), "r"(af[i][3]),
                          "r"(bf[g][s]), "r"(bf[g][s + 1]));
                }
        }
        __syncthreads();
    }

    // epilogue: write h f32 + GN1 stats (interior masked)
    float* hb = g_h + (size_t)b * NPADT * 256;
#pragma unroll
    for (int i = 0; i < 2; i++)
#pragma unroll
        for (int rh = 0; rh < 2; rh++) {
            int m = warp_m0 + 16 * i + quad + rh * 8;
            float ps = 0.f, pq = 0.f;
#pragma unroll
            for (int j = 0; j < 8; j++) {
                float v0 = d[i][j][rh * 2], v1 = d[i][j][rh * 2 + 1];
                int n = warp_n0 + 8 * j + 2 * qt;
                int pos = p0 + n;
                hb[(size_t)pos * 256 + m0 + m] = v0;
                hb[(size_t)(pos + 1) * 256 + m0 + m] = v1;
                int r = pos / 82, q = pos - r * 82;
                bool in0 = (pos < NPAD) && r >= 1 && r <= 80 && q >= 1 && q <= 80;
                bool in1 = (pos + 1 < NPAD) && r >= 1 && r <= 80 && (q + 1) >= 1 && (q + 1) <= 80;
                if (in0) { ps += v0; pq += v0 * v0; }
                if (in1) { ps += v1; pq += v1 * v1; }
            }
            ps += __shfl_down_sync(0xffffffffu, ps, 2);
            pq += __shfl_down_sync(0xffffffffu, pq, 2);
            ps += __shfl_down_sync(0xffffffffu, ps, 1);
            pq += __shfl_down_sync(0xffffffffu, pq, 1);
            if (qt == 0) { atomicAdd(&ssum[m], ps); atomicAdd(&ssq[m], pq); }
        }

    __syncthreads();
    if (tid < 128) {
        atomicAdd(&g_gn1_sum[b * NGG + ((m0 + tid) >> 5)], ssum[tid]);
        atomicAdd(&g_gn1_sq[b * NGG + ((m0 + tid) >> 5)], ssq[tid]);
    }
}

__global__ __launch_bounds__(256) void k_convg1(const int* __restrict__ indices) {
    extern __shared__ __align__(16) char smem[];
    const int tid = threadIdx.x;
    const int b = blockIdx.z;
    const int p0 = blockIdx.x * 128;
    if (blockIdx.y == 0) {
        conv_body(smem, tid, b, p0);
    } else {
        int id = indices[b];
        if (id == 0) return;
        gemm1_body(smem, tid, b, id - 1, p0, (blockIdx.y - 1) * 128);
    }
}

// ============================================================================
// k_gemm2: y = w2 @ silu(GN1(h)), with GN1-affine+SiLU+split fused into B staging
// smem: [Ahi_kh0][Alo_kh0][Ahi_kh1][Alo_kh1][Bhi][Blo]  (6 tiles)
// passes per kh: (Ahi,Bhi) (Ahi,Blo) (Alo,Bhi)
// ============================================================================
__global__ __launch_bounds__(256) void k_gemm2(const int* __restrict__ indices,
                                               const float* __restrict__ g1,
                                               const float* __restrict__ b1) {
    extern __shared__ __align__(16) char smem[];
    __shared__ float ssum[128], ssq[128];
    __shared__ float sa[256], sc[256];

    const int tid = threadIdx.x, wid = tid >> 5, l = tid & 31;
    const int b = blockIdx.z;
    int id = indices[b];
    if (id == 0) return;
    const int e = id - 1;
    const int p0 = blockIdx.x * 128;

    if (tid < 128) { ssum[tid] = 0.f; ssq[tid] = 0.f; }

    const uint32_t sbase = smem_u32(smem);
    const int warp_m0 = (wid & 3) * 32;
    const int warp_n0 = (wid >> 2) * 64;
    const int quad = l >> 2, qt = l & 3;

    uint32_t aoff[2], boff[4];
    {
        int rowA = l & 15, colA = l >> 4;
        aoff[0] = (uint32_t)((warp_m0 + rowA) * TROW + colA * 16);
        aoff[1] = aoff[0] + 16 * TROW;
        int rowB = ((l >> 4) << 3) + (l & 7);
        int colB = (l >> 3) & 1;
#pragma unroll
        for (int g = 0; g < 4; g++)
            boff[g] = (uint32_t)((warp_n0 + g * 16 + rowB) * TROW + colB * 16);
    }

    // stage all 4 A tiles (hi/lo x kh0/kh1)
    {
        const char* whi = (const char*)g_w2_hi + (size_t)e * 65536;
        const char* wlo = (const char*)g_w2_lo + (size_t)e * 65536;
        stage_cp(sbase, whi, 512, tid);                      // Ahi kh0
        stage_cp(sbase + TILEB, wlo, 512, tid);              // Alo kh0
        stage_cp(sbase + 2 * TILEB, whi + 256, 512, tid);    // Ahi kh1
        stage_cp(sbase + 3 * TILEB, wlo + 256, 512, tid);    // Alo kh1
        asm volatile("cp.async.commit_group;" ::: "memory");
    }

    // GN1 affine coefficients
    {
        int k = tid;   // 256
        int gg = k >> 5;
        float mean = g_gn1_mr[(b * NGG + gg) * 2];
        float rstd = g_gn1_mr[(b * NGG + gg) * 2 + 1];
        float a = rstd * g1[e * 256 + k];
        sa[k] = a;
        sc[k] = b1[e * 256 + k] - mean * a;
    }
    __syncthreads();   // sa/sc visible

    float d[2][8][4];
#pragma unroll
    for (int i = 0; i < 2; i++)
#pragma unroll
        for (int j = 0; j < 8; j++)
#pragma unroll
            for (int k = 0; k < 4; k++) d[i][j][k] = 0.f;

    const float* hb = g_h + (size_t)b * NPADT * 256;
    const uint32_t sBhi = sbase + 4 * TILEB;
    const uint32_t sBlo = sbase + 5 * TILEB;

    for (int kh = 0; kh < 2; kh++) {
        // build B_hi/B_lo from f32 h: affine + silu + split
#pragma unroll
        for (int it = 0; it < 16; it++) {
            int j = it * 256 + tid;        // 0..4095 float4 jobs
            int row = j >> 5, c4 = j & 31;
            float4 v = *(const float4*)(hb + (size_t)(p0 + row) * 256 + kh * 128 + c4 * 4);
            int k0 = kh * 128 + c4 * 4;
            float s0, s1, s2, s3, t;
            t = fmaf(v.x, sa[k0],     sc[k0]);     s0 = t * fast_sigmoid(t);
            t = fmaf(v.y, sa[k0 + 1], sc[k0 + 1]); s1 = t * fast_sigmoid(t);
            t = fmaf(v.z, sa[k0 + 2], sc[k0 + 2]); s2 = t * fast_sigmoid(t);
            t = fmaf(v.w, sa[k0 + 3], sc[k0 + 3]); s3 = t * fast_sigmoid(t);
            __nv_bfloat16 h0 = __float2bfloat16(s0), h1 = __float2bfloat16(s1);
            __nv_bfloat16 h2 = __float2bfloat16(s2), h3 = __float2bfloat16(s3);
            __nv_bfloat16 l0 = __float2bfloat16(s0 - __bfloat162float(h0));
            __nv_bfloat16 l1 = __float2bfloat16(s1 - __bfloat162float(h1));
            __nv_bfloat16 l2 = __float2bfloat16(s2 - __bfloat162float(h2));
            __nv_bfloat16 l3 = __float2bfloat16(s3 - __bfloat162float(h3));
            uint32_t hp0 = (uint32_t)*(uint16_t*)&h0 | ((uint32_t)*(uint16_t*)&h1 << 16);
            uint32_t hp1 = (uint32_t)*(uint16_t*)&h2 | ((uint32_t)*(uint16_t*)&h3 << 16);
            uint32_t lp0 = (uint32_t)*(uint16_t*)&l0 | ((uint32_t)*(uint16_t*)&l1 << 16);
            uint32_t lp1 = (uint32_t)*(uint16_t*)&l2 | ((uint32_t)*(uint16_t*)&l3 << 16);
            uint32_t off = (uint32_t)(row * TROW + c4 * 8);
            asm volatile("st.shared.v2.b32 [%0], {%1,%2};" :: "r"(sBhi + off), "r"(hp0), "r"(hp1));
            asm volatile("st.shared.v2.b32 [%0], {%1,%2};" :: "r"(sBlo + off), "r"(lp0), "r"(lp1));
        }
        if (kh == 0) { asm volatile("cp.async.wait_group 0;" ::: "memory"); }
        __syncthreads();

        const uint32_t sAhi = sbase + (uint32_t)(kh * 2 * TILEB);
        const uint32_t sAlo = sAhi + TILEB;

#pragma unroll
        for (int ks = 0; ks < 8; ks++) {
            uint32_t ah[2][4], al[2][4], bh[4][4], bl[4][4];
#pragma unroll
            for (int i = 0; i < 2; i++) {
                asm volatile("ldmatrix.sync.aligned.m8n8.x4.shared.b16 {%0,%1,%2,%3}, [%4];"
                    : "=r"(ah[i][0]), "=r"(ah[i][1]), "=r"(ah[i][2]), "=r"(ah[i][3])
                    : "r"(sAhi + aoff[i] + ks * 32));
                asm volatile("ldmatrix.sync.aligned.m8n8.x4.shared.b16 {%0,%1,%2,%3}, [%4];"
                    : "=r"(al[i][0]), "=r"(al[i][1]), "=r"(al[i][2]), "=r"(al[i][3])
                    : "r"(sAlo + aoff[i] + ks * 32));
            }
#pragma unroll
            for (int g = 0; g < 4; g++) {
                asm volatile("ldmatrix.sync.aligned.m8n8.x4.shared.b16 {%0,%1,%2,%3}, [%4];"
                    : "=r"(bh[g][0]), "=r"(bh[g][1]), "=r"(bh[g][2]), "=r"(bh[g][3])
                    : "r"(sBhi + boff[g] + ks * 32));
                asm volatile("ldmatrix.sync.aligned.m8n8.x4.shared.b16 {%0,%1,%2,%3}, [%4];"
                    : "=r"(bl[g][0]), "=r"(bl[g][1]), "=r"(bl[g][2]), "=r"(bl[g][3])
                    : "r"(sBlo + boff[g] + ks * 32));
            }
#pragma unroll
            for (int i = 0; i < 2; i++)
#pragma unroll
                for (int j = 0; j < 8; j++) {
                    int g = j >> 1, s = (j & 1) * 2;
                    // hh
                    asm volatile(
                        "mma.sync.aligned.m16n8k16.row.col.f32.bf16.bf16.f32 "
                        "{%0,%1,%2,%3}, {%4,%5,%6,%7}, {%8,%9}, {%0,%1,%2,%3};"
                        : "+f"(d[i][j][0]), "+f"(d[i][j][1]), "+f"(d[i][j][2]), "+f"(d[i][j][3])
                        : "r"(ah[i][0]), "r"(ah[i][1]), "r"(ah[i][2]), "r"(ah[i][3]),
                          "r"(bh[g][s]), "r"(bh[g][s + 1]));
                    // hl
                    asm volatile(
                        "mma.sync.aligned.m16n8k16.row.col.f32.bf16.bf16.f32 "
                        "{%0,%1,%2,%3}, {%4,%5,%6,%7}, {%8,%9}, {%0,%1,%2,%3};"
                        : "+f"(d[i][j][0]), "+f"(d[i][j][1]), "+f"(d[i][j][2]), "+f"(d[i][j][3])
                        : "r"(ah[i][0]), "r"(ah[i][1]), "r"(ah[i][2]), "r"(ah[i][3]),
                          "r"(bl[g][s]), "r"(bl[g][s + 1]));
                    // lh
                    asm volatile(
                        "mma.sync.aligned.m16n8k16.row.col.f32.bf16.bf16.f32 "
                        "{%0,%1,%2,%3}, {%4,%5,%6,%7}, {%8,%9}, {%0,%1,%2,%3};"
                        : "+f"(d[i][j][0]), "+f"(d[i][j][1]), "+f"(d[i][j][2]), "+f"(d[i][j][3])
                        : "r"(al[i][0]), "r"(al[i][1]), "r"(al[i][2]), "r"(al[i][3]),
                          "r"(bh[g][s]), "r"(bh[g][s + 1]));
                }
        }
        __syncthreads();
    }

    // epilogue: write g_y (interior only) + GN2 stats
    float* dst = g_y + (size_t)b * CC * PP;
#pragma unroll
    for (int i = 0; i < 2; i++)
#pragma unroll
        for (int rh = 0; rh < 2; rh++) {
            int m = warp_m0 + 16 * i + quad + rh * 8;
            float ps = 0.f, pq = 0.f;
#pragma unroll
            for (int j = 0; j < 8; j++) {
                float v0 = d[i][j][rh * 2], v1 = d[i][j][rh * 2 + 1];
                int n = warp_n0 + 8 * j + 2 * qt;
                int pos = p0 + n;
                int r = pos / 82, q = pos - r * 82;
                bool in0 = (pos < NPAD) && r >= 1 && r <= 80 && q >= 1 && q <= 80;
                bool in1 = (pos + 1 < NPAD) && r >= 1 && r <= 80 && (q + 1) >= 1 && (q + 1) <= 80;
                if (in0) { dst[(size_t)m * PP + (r - 1) * 80 + (q - 1)] = v0; ps += v0; pq += v0 * v0; }
                if (in1) { dst[(size_t)m * PP + (r - 1) * 80 + q] = v1; ps += v1; pq += v1 * v1; }
            }
            ps += __shfl_down_sync(0xffffffffu, ps, 2);
            pq += __shfl_down_sync(0xffffffffu, pq, 2);
            ps += __shfl_down_sync(0xffffffffu, ps, 1);
            pq += __shfl_down_sync(0xffffffffu, pq, 1);
            if (qt == 0) { atomicAdd(&ssum[m], ps); atomicAdd(&ssq[m], pq); }
        }

    __syncthreads();
    if (tid < 128) {
        atomicAdd(&g_gn2_sum[b * NGG + (tid >> 4)], ssum[tid]);
        atomicAdd(&g_gn2_sq[b * NGG + (tid >> 4)], ssq[tid]);
    }
}

// ---------------- combine ----------------
__global__ __launch_bounds__(256) void k_combine(const float* __restrict__ x,
                                                 const float* __restrict__ weights,
                                                 const int* __restrict__ indices,
                                                 const float* __restrict__ g2,
                                                 const float* __restrict__ b2,
                                                 float* __restrict__ out) {
    const int blk = blockIdx.x;
    const int b = blk >> 7, c = blk & 127;
    const int idx = indices[b];
    const float wb = weights[b];
    const float sc = g_bn_scale[c], sh = g_bn_shift[c];

    float a2, c2;
    if (idx > 0) {
        int e = idx - 1;
        int g = c >> 4;
        float mean = g_gn2_mr[(b * NGG + g) * 2];
        float rstd = g_gn2_mr[(b * NGG + g) * 2 + 1];
        float ga = rstd * g2[e * CC + c];
        a2 = ga * wb;
        c2 = (b2[e * CC + c] - mean * ga) * wb;
    } else {
        a2 = wb;
        c2 = 0.f;
    }

    const size_t base = ((size_t)b * CC + c) * PP;
    const float4* sp = (const float4*)(g_s + base);
    const float4* rp = (idx > 0) ? (const float4*)(g_y + base) : (const float4*)(x + base);
    float4* op = (float4*)(out + base);

    for (int i = threadIdx.x; i < PP / 4; i += 256) {
        float4 sv = sp[i];
        float4 rv = rp[i];
        float4 o;
        float t;
        t = fmaf(sv.x, sc, sh); o.x = t * fast_sigmoid(t) + fmaf(rv.x, a2, c2);
        t = fmaf(sv.y, sc, sh); o.y = t * fast_sigmoid(t) + fmaf(rv.y, a2, c2);
        t = fmaf(sv.z, sc, sh); o.z = t * fast_sigmoid(t) + fmaf(rv.z, a2, c2);
        t = fmaf(sv.w, sc, sh); o.w = t * fast_sigmoid(t) + fmaf(rv.w, a2, c2);
        op[i] = o;
    }
}

// ---------------- launch ----------------
extern "C" void kernel_launch(void* const* d_in, const int* in_sizes, int n_in,
                              void* d_out, int out_size) {
    const float* x        = (const float*)d_in[0];
    const float* weights  = (const float*)d_in[1];
    const int*   indices  = (const int*)d_in[2];
    const float* shared_w = (const float*)d_in[3];
    const float* bn_gamma = (const float*)d_in[4];
    const float* bn_beta  = (const float*)d_in[5];
    const float* w1       = (const float*)d_in[6];
    const float* g1       = (const float*)d_in[7];
    const float* b1       = (const float*)d_in[8];
    const float* w2       = (const float*)d_in[9];
    const float* g2       = (const float*)d_in[10];
    const float* b2       = (const float*)d_in[11];
    float* out = (float*)d_out;

    cudaFuncSetAttribute(k_convg1, cudaFuncAttributeMaxDynamicSharedMemorySize, SMEM_CONV);
    cudaFuncSetAttribute(k_gemm2, cudaFuncAttributeMaxDynamicSharedMemorySize, SMEM_G2);

    k_zero<<<1, 256>>>();
    k_zero_xp<<<dim3(28, BB), 256>>>();
    k_pack_x<<<dim3(200, BB), 256>>>(x);
    k_pack_w<<<1344, 256>>>(shared_w, w1, w2);

    k_convg1<<<dim3(53, 3, BB), 256, SMEM_CONV>>>(indices);  // conv + gemm1 merged
    k_fin1<<<1, 256>>>(bn_gamma, bn_beta);                   // BN + GN1 finalize
    k_gemm2<<<dim3(53, 1, BB), 256, SMEM_G2>>>(indices, g1, b1);
    k_fin_gn2<<<1, 128>>>();
    k_combine<<<BB * CC, 256>>>(x, weights, indices, g2, b2, out);
}

// round 10
// speedup vs baseline: 2.4890x; 1.0450x over previous
#include <cuda_runtime.h>
#include <cuda_bf16.h>
#include <cstdint>

// ---------------- shapes ----------------
#define BB    16
#define CC    128
#define HIDD  256
#define PP    6400
#define NGG   8
#define EPSV  1e-5f

#define NPAD  6724      // 82*82
#define NPADT 6784      // 53 tiles * 128
#define GUARD 128
#define XROWS 7040      // GUARD + NPADT + GUARD

// smem tile geometry: [128 rows][136 bf16] = 272 B/row (conflict-free ldmatrix)
#define TROW   272
#define TILEB  34816    // 128*272

// conv halo window: rows p0-83 .. p0+210
#define XW_ROWS 294
#define XW_BYTES (XW_ROWS * TROW)      // 79968
#define SMEM_CONV (2 * XW_BYTES)       // 159936 (xh + xl windows only)
#define SMEM_G2   (2 * TILEB)          // 69632  (Bhi + Blo)

// ---------------- device scratch (static; allocation-free) ----------------
__device__ __align__(16) float g_s[(size_t)BB * CC * PP];
__device__ __align__(16) float g_y[(size_t)BB * CC * PP];
__device__ __align__(16) float g_h[(size_t)BB * NPADT * HIDD];   // f32 [b][pos][256]

__device__ uint4 g_xp_hi[(size_t)BB * XROWS * 16];   // [b][row][128 ci] bf16, 256B rows
__device__ uint4 g_xp_lo[(size_t)BB * XROWS * 16];

// fragment-packed weights: [tile16][ks][lane] -> one uint4 = {a0,a1,a2,a3}
__device__ uint4 g_wfc[9 * 2 * 8 * 8 * 32];    // conv: [tap][part][mt8][ks8][lane]
__device__ uint4 g_wf1[3 * 2 * 16 * 8 * 32];   // w1:   [e][part][mt16][ks8][lane]
__device__ uint4 g_wf2[3 * 2 * 8 * 16 * 32];   // w2:   [e][part][mt8][ks16][lane]

__device__ float g_bn_sum[CC], g_bn_sq[CC];
__device__ float g_bn_scale[CC], g_bn_shift[CC];
__device__ float g_gn1_sum[BB * NGG], g_gn1_sq[BB * NGG];
__device__ float g_gn1_mr[BB * NGG * 2];
__device__ float g_gn2_sum[BB * NGG], g_gn2_sq[BB * NGG];
__device__ float g_gn2_mr[BB * NGG * 2];

// ---------------- helpers ----------------
__device__ __forceinline__ uint32_t smem_u32(const void* p) {
    uint32_t a;
    asm("{ .reg .u64 t; cvta.to.shared.u64 t, %1; cvt.u32.u64 %0, t; }" : "=r"(a) : "l"(p));
    return a;
}

__device__ __forceinline__ void mma16816(float* d, const uint32_t* a, uint32_t b0, uint32_t b1) {
    asm volatile(
        "mma.sync.aligned.m16n8k16.row.col.f32.bf16.bf16.f32 "
        "{%0,%1,%2,%3}, {%4,%5,%6,%7}, {%8,%9}, {%0,%1,%2,%3};"
        : "+f"(d[0]), "+f"(d[1]), "+f"(d[2]), "+f"(d[3])
        : "r"(a[0]), "r"(a[1]), "r"(a[2]), "r"(a[3]), "r"(b0), "r"(b1));
}

// FMA-only sigmoid (no MUFU)
__device__ __forceinline__ float fast_sigmoid(float t) {
    float z = -t * 1.442695041f;
    z = fminf(fmaxf(z, -60.f), 60.f);
    float fl = floorf(z);
    float f = z - fl;
    float p = 1.5403530e-4f;
    p = fmaf(p, f, 1.3333558e-3f);
    p = fmaf(p, f, 9.6181291e-3f);
    p = fmaf(p, f, 5.5504109e-2f);
    p = fmaf(p, f, 2.4022651e-1f);
    p = fmaf(p, f, 6.9314718e-1f);
    float two_f = fmaf(p, f, 1.0f);
    float ex = __int_as_float((127 + (int)fl) << 23) * two_f;   // exp(-t)
    float d = 1.f + ex;
    float r = __int_as_float(0x7EF311C3 - __float_as_int(d));
    r = r * (2.f - d * r);
    r = r * (2.f - d * r);
    r = r * (2.f - d * r);
    return r;
}

// stage one [128 rows][256B used] tile into smem [128][272B] via cp.async
__device__ __forceinline__ void stage_cp(uint32_t s_dst, const char* src, int rowStride, int tid) {
#pragma unroll
    for (int it = 0; it < 8; it++) {
        int idx = it * 256 + tid;
        int r = idx >> 4, c = idx & 15;
        uint32_t d = s_dst + (uint32_t)(r * TROW + c * 16);
        const char* s = src + (size_t)r * rowStride + c * 16;
        asm volatile("cp.async.cg.shared.global [%0], [%1], 16;" :: "r"(d), "l"(s));
    }
}

__device__ __forceinline__ uint32_t pack2(float a, float b, int part) {
    __nv_bfloat16 ha = __float2bfloat16(a), hb = __float2bfloat16(b);
    if (part) {
        ha = __float2bfloat16(a - __bfloat162float(ha));
        hb = __float2bfloat16(b - __bfloat162float(hb));
    }
    return (uint32_t)*(uint16_t*)&ha | ((uint32_t)*(uint16_t*)&hb << 16);
}

// ============================================================================
// k_prep: pack_x (3200 blocks) + zero_xp (448) + pack_w frag-order (336) + zero (1)
// ============================================================================
__global__ __launch_bounds__(256) void k_prep(const float* __restrict__ x,
                                              const float* __restrict__ w,
                                              const float* __restrict__ w1,
                                              const float* __restrict__ w2) {
    __shared__ float t[128 * 33];
    const int bi = blockIdx.x, tid = threadIdx.x;

    if (bi < 3200) {               // ---- pack_x ----
        int b = bi / 200, p0 = (bi - b * 200) * 32;
        const float* xb = x + (size_t)b * CC * PP;
#pragma unroll
        for (int i = 0; i < 16; i++) {
            int lin = i * 256 + tid;
            int c = lin >> 5, px = lin & 31;
            t[c * 33 + px] = xb[(size_t)c * PP + p0 + px];
        }
        __syncthreads();
        __nv_bfloat16* hiA = (__nv_bfloat16*)g_xp_hi;
        __nv_bfloat16* loA = (__nv_bfloat16*)g_xp_lo;
#pragma unroll
        for (int i = 0; i < 16; i++) {
            int lin = i * 256 + tid;
            int c = tid & 127, px = (lin >> 7) & 31;
            float v = t[c * 33 + px];
            int p = p0 + px;
            int r = p / 80, q = p - r * 80;
            int pos = (r + 1) * 82 + (q + 1);
            size_t a = ((size_t)b * XROWS + GUARD + pos) * 128 + c;
            __nv_bfloat16 hi = __float2bfloat16(v);
            hiA[a] = hi;
            loA[a] = __float2bfloat16(v - __bfloat162float(hi));
        }
    } else if (bi < 3648) {        // ---- zero_xp ----
        int zbi = bi - 3200;
        int b = zbi / 28;
        int ro = (zbi - b * 28) * 256 + tid;
        if (ro >= XROWS) return;
        int pos = ro - GUARD;
        bool interior = false;
        if (pos >= 0 && pos < NPAD) {
            int r = pos / 82, q = pos - r * 82;
            interior = (r >= 1 && r <= 80 && q >= 1 && q <= 80);
        }
        if (!interior) {
            uint4 z = make_uint4(0, 0, 0, 0);
            size_t base = ((size_t)b * XROWS + ro) * 16;
#pragma unroll
            for (int j = 0; j < 16; j++) { g_xp_hi[base + j] = z; g_xp_lo[base + j] = z; }
        }
    } else if (bi < 3984) {        // ---- pack_w (fragment order) ----
        int idx = (bi - 3648) * 256 + tid;   // 0..86015
        if (idx < 36864) {                   // conv weights
            int lane = idx & 31;
            int ks = (idx >> 5) & 7, mt = (idx >> 8) & 7;
            int part = (idx >> 11) & 1, tap = idx >> 12;
            int r0 = mt * 16 + (lane >> 2), r1 = r0 + 8;
            int k0 = ks * 16 + (lane & 3) * 2;
#define WCV(r, k) w[((size_t)(r) * 128 + (k)) * 9 + tap]
            uint4 o;
            o.x = pack2(WCV(r0, k0),     WCV(r0, k0 + 1), part);
            o.y = pack2(WCV(r1, k0),     WCV(r1, k0 + 1), part);
            o.z = pack2(WCV(r0, k0 + 8), WCV(r0, k0 + 9), part);
            o.w = pack2(WCV(r1, k0 + 8), WCV(r1, k0 + 9), part);
#undef WCV
            g_wfc[idx] = o;
        } else if (idx < 61440) {            // w1
            int j = idx - 36864;
            int lane = j & 31;
            int ks = (j >> 5) & 7, mt = (j >> 8) & 15;
            int part = (j >> 12) & 1, e = j >> 13;
            int r0 = mt * 16 + (lane >> 2), r1 = r0 + 8;
            int k0 = ks * 16 + (lane & 3) * 2;
            const float* wb = w1 + (size_t)e * 32768;
#define W1V(r, k) wb[(size_t)(r) * 128 + (k)]
            uint4 o;
            o.x = pack2(W1V(r0, k0),     W1V(r0, k0 + 1), part);
            o.y = pack2(W1V(r1, k0),     W1V(r1, k0 + 1), part);
            o.z = pack2(W1V(r0, k0 + 8), W1V(r0, k0 + 9), part);
            o.w = pack2(W1V(r1, k0 + 8), W1V(r1, k0 + 9), part);
#undef W1V
            g_wf1[j] = o;
        } else {                             // w2
            int j = idx - 61440;
            int lane = j & 31;
            int kst = (j >> 5) & 15, mt = (j >> 9) & 7;
            int part = (j >> 12) & 1, e = j >> 13;
            int r0 = mt * 16 + (lane >> 2), r1 = r0 + 8;
            int k0 = kst * 16 + (lane & 3) * 2;
            const float* wb = w2 + (size_t)e * 32768;
#define W2V(r, k) wb[(size_t)(r) * 256 + (k)]
            uint4 o;
            o.x = pack2(W2V(r0, k0),     W2V(r0, k0 + 1), part);
            o.y = pack2(W2V(r1, k0),     W2V(r1, k0 + 1), part);
            o.z = pack2(W2V(r0, k0 + 8), W2V(r0, k0 + 9), part);
            o.w = pack2(W2V(r1, k0 + 8), W2V(r1, k0 + 9), part);
#undef W2V
            g_wf2[j] = o;
        }
    } else {                       // ---- zero stats ----
        if (tid < CC) { g_bn_sum[tid] = 0.f; g_bn_sq[tid] = 0.f; }
        if (tid < BB * NGG) {
            g_gn1_sum[tid] = 0.f; g_gn1_sq[tid] = 0.f;
            g_gn2_sum[tid] = 0.f; g_gn2_sq[tid] = 0.f;
        }
    }
}

// fin_bn + fin_gn1
__global__ void k_fin1(const float* __restrict__ gamma, const float* __restrict__ beta) {
    int t = threadIdx.x;   // 256
    if (t < 128) {
        const float inv = 1.f / (float)(BB * PP);
        float m = g_bn_sum[t] * inv;
        float v = g_bn_sq[t] * inv - m * m;
        float sc = gamma[t] * rsqrtf(v + EPSV);
        g_bn_scale[t] = sc;
        g_bn_shift[t] = beta[t] - m * sc;
    } else {
        int u = t - 128;
        const float inv = 1.f / (float)((HIDD / NGG) * PP);
        float m = g_gn1_sum[u] * inv;
        float v = g_gn1_sq[u] * inv - m * m;
        g_gn1_mr[2 * u] = m;
        g_gn1_mr[2 * u + 1] = rsqrtf(v + EPSV);
    }
}

__global__ void k_fin_gn2() {
    int t = threadIdx.x;
    const float inv = 1.f / (float)((CC / NGG) * PP);
    float m = g_gn2_sum[t] * inv;
    float v = g_gn2_sq[t] * inv - m * m;
    g_gn2_mr[2 * t] = m;
    g_gn2_mr[2 * t + 1] = rsqrtf(v + EPSV);
}

// ============================================================================
// merged conv3x3 + gemm1. blockIdx.y==0 -> conv; 1,2 -> gemm1 m-half.
// Weights arrive as register fragments via LDG (frag-packed); no weight smem.
// ============================================================================
__device__ __forceinline__ void conv_body(char* smem, float* ssum, float* ssq,
                                          const int tid, const int b, const int p0) {
    const int wid = tid >> 5, l = tid & 31;
    const uint32_t sbase = smem_u32(smem);
    const int warp_m0 = (wid & 3) * 32;
    const int warp_n0 = (wid >> 2) * 64;
    const int quad = l >> 2, qt = l & 3;
    const int mtb = warp_m0 >> 4;

    uint32_t boffr[4];
    {
        int rowB = ((l >> 4) << 3) + (l & 7);
        int colB = (l >> 3) & 1;
#pragma unroll
        for (int g = 0; g < 4; g++)
            boffr[g] = (uint32_t)((warp_n0 + g * 16 + rowB) * TROW + colB * 16);
    }

    float d[2][8][4];
#pragma unroll
    for (int i = 0; i < 2; i++)
#pragma unroll
        for (int j = 0; j < 8; j++)
#pragma unroll
            for (int k = 0; k < 4; k++) d[i][j][k] = 0.f;

    // stage x halo windows (once)
    {
        const size_t g0 = (size_t)b * XROWS + GUARD + p0 - 83;
        const char* xh = (const char*)g_xp_hi + g0 * 256;
        const char* xl = (const char*)g_xp_lo + g0 * 256;
        for (int i = tid; i < XW_ROWS * 16; i += 256) {
            int r = i >> 4, c = i & 15;
            uint32_t dof = (uint32_t)(r * TROW + c * 16);
            const size_t sof = (size_t)r * 256 + c * 16;
            asm volatile("cp.async.cg.shared.global [%0], [%1], 16;"
                         :: "r"(sbase + dof), "l"(xh + sof));
            asm volatile("cp.async.cg.shared.global [%0], [%1], 16;"
                         :: "r"(sbase + XW_BYTES + dof), "l"(xl + sof));
        }
        asm volatile("cp.async.commit_group;" ::: "memory");
        asm volatile("cp.async.wait_group 0;" ::: "memory");
    }
    if (tid < 128) { ssum[tid] = 0.f; ssq[tid] = 0.f; }
    __syncthreads();

    // barrier-free mainloop: 9 taps x 8 ks
    for (int tap = 0; tap < 9; tap++) {
        const int kh = tap / 3, kw = tap - kh * 3;
        const uint32_t winbase = (uint32_t)(((kh - 1) * 82 + (kw - 1) + 83) * TROW);
        const uint32_t xhb = sbase + winbase;
        const uint32_t xlb = sbase + XW_BYTES + winbase;
        const uint4* wfh = g_wfc + (size_t)(tap * 2) * 2048 + l;
        const uint4* wfl = wfh + 2048;

#pragma unroll
        for (int ks = 0; ks < 8; ks++) {
            uint4 ah[2], al[2];
            ah[0] = wfh[(mtb * 8 + ks) * 32];
            ah[1] = wfh[((mtb + 1) * 8 + ks) * 32];
            al[0] = wfl[(mtb * 8 + ks) * 32];
            al[1] = wfl[((mtb + 1) * 8 + ks) * 32];

            uint32_t bh[4][4], bl[4][4];
#pragma unroll
            for (int g = 0; g < 4; g++) {
                asm volatile("ldmatrix.sync.aligned.m8n8.x4.shared.b16 {%0,%1,%2,%3}, [%4];"
                    : "=r"(bh[g][0]), "=r"(bh[g][1]), "=r"(bh[g][2]), "=r"(bh[g][3])
                    : "r"(xhb + boffr[g] + ks * 32));
                asm volatile("ldmatrix.sync.aligned.m8n8.x4.shared.b16 {%0,%1,%2,%3}, [%4];"
                    : "=r"(bl[g][0]), "=r"(bl[g][1]), "=r"(bl[g][2]), "=r"(bl[g][3])
                    : "r"(xlb + boffr[g] + ks * 32));
            }
#pragma unroll
            for (int i = 0; i < 2; i++) {
                const uint32_t* ahp = (const uint32_t*)&ah[i];
                const uint32_t* alp = (const uint32_t*)&al[i];
#pragma unroll
                for (int j = 0; j < 8; j++) {
                    int g = j >> 1, s = (j & 1) * 2;
                    mma16816(d[i][j], ahp, bh[g][s], bh[g][s + 1]);
                    mma16816(d[i][j], ahp, bl[g][s], bl[g][s + 1]);
                    mma16816(d[i][j], alp, bh[g][s], bh[g][s + 1]);
                }
            }
        }
    }

    // epilogue: write g_s (interior only) + BN partial stats
    float* dst = g_s + (size_t)b * CC * PP;
#pragma unroll
    for (int i = 0; i < 2; i++)
#pragma unroll
        for (int rh = 0; rh < 2; rh++) {
            int m = warp_m0 + 16 * i + quad + rh * 8;
            float ps = 0.f, pq = 0.f;
#pragma unroll
            for (int j = 0; j < 8; j++) {
                float v0 = d[i][j][rh * 2], v1 = d[i][j][rh * 2 + 1];
                int n = warp_n0 + 8 * j + 2 * qt;
                int pos = p0 + n;
                int r = pos / 82, q = pos - r * 82;
                bool in0 = (pos < NPAD) && r >= 1 && r <= 80 && q >= 1 && q <= 80;
                bool in1 = (pos + 1 < NPAD) && r >= 1 && r <= 80 && (q + 1) >= 1 && (q + 1) <= 80;
                if (in0) { dst[(size_t)m * PP + (r - 1) * 80 + (q - 1)] = v0; ps += v0; pq += v0 * v0; }
                if (in1) { dst[(size_t)m * PP + (r - 1) * 80 + q] = v1; ps += v1; pq += v1 * v1; }
            }
            ps += __shfl_down_sync(0xffffffffu, ps, 2);
            pq += __shfl_down_sync(0xffffffffu, pq, 2);
            ps += __shfl_down_sync(0xffffffffu, ps, 1);
            pq += __shfl_down_sync(0xffffffffu, pq, 1);
            if (qt == 0) { atomicAdd(&ssum[m], ps); atomicAdd(&ssq[m], pq); }
        }

    __syncthreads();
    if (tid < 128) {
        atomicAdd(&g_bn_sum[tid], ssum[tid]);
        atomicAdd(&g_bn_sq[tid], ssq[tid]);
    }
}

__device__ __forceinline__ void gemm1_body(char* smem, float* ssum, float* ssq,
                                           const int tid, const int b, const int e,
                                           const int p0, const int m0) {
    const int wid = tid >> 5, l = tid & 31;
    const uint32_t sbase = smem_u32(smem);
    const int warp_m0 = (wid & 3) * 32;
    const int warp_n0 = (wid >> 2) * 64;
    const int quad = l >> 2, qt = l & 3;
    const int mtb = (m0 >> 4) + (warp_m0 >> 4);

    uint32_t boff[4];
    {
        int rowB = ((l >> 4) << 3) + (l & 7);
        int colB = (l >> 3) & 1;
#pragma unroll
        for (int g = 0; g < 4; g++)
            boff[g] = (uint32_t)((warp_n0 + g * 16 + rowB) * TROW + colB * 16);
    }

    float d[2][8][4];
#pragma unroll
    for (int i = 0; i < 2; i++)
#pragma unroll
        for (int j = 0; j < 8; j++)
#pragma unroll
            for (int k = 0; k < 4; k++) d[i][j][k] = 0.f;

    // stage B tiles (xh, xl) once
    {
        const char* bsx_hi = (const char*)g_xp_hi + ((size_t)b * XROWS + GUARD + p0) * 256;
        const char* bsx_lo = (const char*)g_xp_lo + ((size_t)b * XROWS + GUARD + p0) * 256;
        stage_cp(sbase, bsx_hi, 256, tid);
        stage_cp(sbase + TILEB, bsx_lo, 256, tid);
        asm volatile("cp.async.commit_group;" ::: "memory");
        asm volatile("cp.async.wait_group 0;" ::: "memory");
    }
    if (tid < 128) { ssum[tid] = 0.f; ssq[tid] = 0.f; }
    __syncthreads();

    const uint4* wfh = g_wf1 + (size_t)(e * 2) * 4096 + l;
    const uint4* wfl = wfh + 4096;

#pragma unroll
    for (int ks = 0; ks < 8; ks++) {
        uint4 ah[2], al[2];
        ah[0] = wfh[(mtb * 8 + ks) * 32];
        ah[1] = wfh[((mtb + 1) * 8 + ks) * 32];
        al[0] = wfl[(mtb * 8 + ks) * 32];
        al[1] = wfl[((mtb + 1) * 8 + ks) * 32];

        uint32_t bh[4][4], bl[4][4];
#pragma unroll
        for (int g = 0; g < 4; g++) {
            asm volatile("ldmatrix.sync.aligned.m8n8.x4.shared.b16 {%0,%1,%2,%3}, [%4];"
                : "=r"(bh[g][0]), "=r"(bh[g][1]), "=r"(bh[g][2]), "=r"(bh[g][3])
                : "r"(sbase + boff[g] + ks * 32));
            asm volatile("ldmatrix.sync.aligned.m8n8.x4.shared.b16 {%0,%1,%2,%3}, [%4];"
                : "=r"(bl[g][0]), "=r"(bl[g][1]), "=r"(bl[g][2]), "=r"(bl[g][3])
                : "r"(sbase + TILEB + boff[g] + ks * 32));
        }
#pragma unroll
        for (int i = 0; i < 2; i++) {
            const uint32_t* ahp = (const uint32_t*)&ah[i];
            const uint32_t* alp = (const uint32_t*)&al[i];
#pragma unroll
            for (int j = 0; j < 8; j++) {
                int g = j >> 1, s = (j & 1) * 2;
                mma16816(d[i][j], ahp, bh[g][s], bh[g][s + 1]);
                mma16816(d[i][j], ahp, bl[g][s], bl[g][s + 1]);
                mma16816(d[i][j], alp, bh[g][s], bh[g][s + 1]);
            }
        }
    }

    // epilogue: write h f32 + GN1 stats (interior masked)
    float* hb = g_h + (size_t)b * NPADT * 256;
#pragma unroll
    for (int i = 0; i < 2; i++)
#pragma unroll
        for (int rh = 0; rh < 2; rh++) {
            int m = warp_m0 + 16 * i + quad + rh * 8;
            float ps = 0.f, pq = 0.f;
#pragma unroll
            for (int j = 0; j < 8; j++) {
                float v0 = d[i][j][rh * 2], v1 = d[i][j][rh * 2 + 1];
                int n = warp_n0 + 8 * j + 2 * qt;
                int pos = p0 + n;
                hb[(size_t)pos * 256 + m0 + m] = v0;
                hb[(size_t)(pos + 1) * 256 + m0 + m] = v1;
                int r = pos / 82, q = pos - r * 82;
                bool in0 = (pos < NPAD) && r >= 1 && r <= 80 && q >= 1 && q <= 80;
                bool in1 = (pos + 1 < NPAD) && r >= 1 && r <= 80 && (q + 1) >= 1 && (q + 1) <= 80;
                if (in0) { ps += v0; pq += v0 * v0; }
                if (in1) { ps += v1; pq += v1 * v1; }
            }
            ps += __shfl_down_sync(0xffffffffu, ps, 2);
            pq += __shfl_down_sync(0xffffffffu, pq, 2);
            ps += __shfl_down_sync(0xffffffffu, ps, 1);
            pq += __shfl_down_sync(0xffffffffu, pq, 1);
            if (qt == 0) { atomicAdd(&ssum[m], ps); atomicAdd(&ssq[m], pq); }
        }

    __syncthreads();
    if (tid < 128) {
        atomicAdd(&g_gn1_sum[b * NGG + ((m0 + tid) >> 5)], ssum[tid]);
        atomicAdd(&g_gn1_sq[b * NGG + ((m0 + tid) >> 5)], ssq[tid]);
    }
}

__global__ __launch_bounds__(256) void k_convg1(const int* __restrict__ indices) {
    extern __shared__ __align__(16) char smem[];
    __shared__ float ssum[128], ssq[128];
    const int tid = threadIdx.x;
    const int b = blockIdx.z;
    const int p0 = blockIdx.x * 128;
    if (blockIdx.y == 0) {
        conv_body(smem, ssum, ssq, tid, b, p0);
    } else {
        int id = indices[b];
        if (id == 0) return;
        gemm1_body(smem, ssum, ssq, tid, b, id - 1, p0, (blockIdx.y - 1) * 128);
    }
}

// ============================================================================
// k_gemm2: y = w2 @ silu(GN1(h)); A-frags via LDG; B built in smem from f32 h
// ============================================================================
__global__ __launch_bounds__(256) void k_gemm2(const int* __restrict__ indices,
                                               const float* __restrict__ g1,
                                               const float* __restrict__ b1) {
    extern __shared__ __align__(16) char smem[];
    __shared__ float ssum[128], ssq[128];
    __shared__ float sa[256], sc[256];

    const int tid = threadIdx.x, wid = tid >> 5, l = tid & 31;
    const int b = blockIdx.z;
    int id = indices[b];
    if (id == 0) return;
    const int e = id - 1;
    const int p0 = blockIdx.x * 128;

    if (tid < 128) { ssum[tid] = 0.f; ssq[tid] = 0.f; }

    const uint32_t sbase = smem_u32(smem);
    const int warp_m0 = (wid & 3) * 32;
    const int warp_n0 = (wid >> 2) * 64;
    const int quad = l >> 2, qt = l & 3;
    const int mtb = warp_m0 >> 4;

    uint32_t boff[4];
    {
        int rowB = ((l >> 4) << 3) + (l & 7);
        int colB = (l >> 3) & 1;
#pragma unroll
        for (int g = 0; g < 4; g++)
            boff[g] = (uint32_t)((warp_n0 + g * 16 + rowB) * TROW + colB * 16);
    }

    // GN1 affine coefficients
    {
        int k = tid;
        int gg = k >> 5;
        float mean = g_gn1_mr[(b * NGG + gg) * 2];
        float rstd = g_gn1_mr[(b * NGG + gg) * 2 + 1];
        float a = rstd * g1[e * 256 + k];
        sa[k] = a;
        sc[k] = b1[e * 256 + k] - mean * a;
    }
    __syncthreads();

    float d[2][8][4];
#pragma unroll
    for (int i = 0; i < 2; i++)
#pragma unroll
        for (int j = 0; j < 8; j++)
#pragma unroll
            for (int k = 0; k < 4; k++) d[i][j][k] = 0.f;

    const float* hb = g_h + (size_t)b * NPADT * 256;
    const uint32_t sBhi = sbase;
    const uint32_t sBlo = sbase + TILEB;
    const uint4* wfh = g_wf2 + (size_t)(e * 2) * 4096 + l;
    const uint4* wfl = wfh + 4096;

    for (int kh = 0; kh < 2; kh++) {
        // build B_hi/B_lo: affine + silu + split
#pragma unroll
        for (int it = 0; it < 16; it++) {
            int j = it * 256 + tid;
            int row = j >> 5, c4 = j & 31;
            float4 v = *(const float4*)(hb + (size_t)(p0 + row) * 256 + kh * 128 + c4 * 4);
            int k0 = kh * 128 + c4 * 4;
            float s0, s1, s2, s3, t;
            t = fmaf(v.x, sa[k0],     sc[k0]);     s0 = t * fast_sigmoid(t);
            t = fmaf(v.y, sa[k0 + 1], sc[k0 + 1]); s1 = t * fast_sigmoid(t);
            t = fmaf(v.z, sa[k0 + 2], sc[k0 + 2]); s2 = t * fast_sigmoid(t);
            t = fmaf(v.w, sa[k0 + 3], sc[k0 + 3]); s3 = t * fast_sigmoid(t);
            __nv_bfloat16 h0 = __float2bfloat16(s0), h1 = __float2bfloat16(s1);
            __nv_bfloat16 h2 = __float2bfloat16(s2), h3 = __float2bfloat16(s3);
            __nv_bfloat16 l0 = __float2bfloat16(s0 - __bfloat162float(h0));
            __nv_bfloat16 l1 = __float2bfloat16(s1 - __bfloat162float(h1));
            __nv_bfloat16 l2 = __float2bfloat16(s2 - __bfloat162float(h2));
            __nv_bfloat16 l3 = __float2bfloat16(s3 - __bfloat162float(h3));
            uint32_t hp0 = (uint32_t)*(uint16_t*)&h0 | ((uint32_t)*(uint16_t*)&h1 << 16);
            uint32_t hp1 = (uint32_t)*(uint16_t*)&h2 | ((uint32_t)*(uint16_t*)&h3 << 16);
            uint32_t lp0 = (uint32_t)*(uint16_t*)&l0 | ((uint32_t)*(uint16_t*)&l1 << 16);
            uint32_t lp1 = (uint32_t)*(uint16_t*)&l2 | ((uint32_t)*(uint16_t*)&l3 << 16);
            uint32_t off = (uint32_t)(row * TROW + c4 * 8);
            asm volatile("st.shared.v2.b32 [%0], {%1,%2};" :: "r"(sBhi + off), "r"(hp0), "r"(hp1));
            asm volatile("st.shared.v2.b32 [%0], {%1,%2};" :: "r"(sBlo + off), "r"(lp0), "r"(lp1));
        }
        __syncthreads();

#pragma unroll
        for (int ks = 0; ks < 8; ks++) {
            const int kstot = kh * 8 + ks;
            uint4 ah[2], al[2];
            ah[0] = wfh[(mtb * 16 + kstot) * 32];
            ah[1] = wfh[((mtb + 1) * 16 + kstot) * 32];
            al[0] = wfl[(mtb * 16 + kstot) * 32];
            al[1] = wfl[((mtb + 1) * 16 + kstot) * 32];

            uint32_t bh[4][4], bl[4][4];
#pragma unroll
            for (int g = 0; g < 4; g++) {
                asm volatile("ldmatrix.sync.aligned.m8n8.x4.shared.b16 {%0,%1,%2,%3}, [%4];"
                    : "=r"(bh[g][0]), "=r"(bh[g][1]), "=r"(bh[g][2]), "=r"(bh[g][3])
                    : "r"(sBhi + boff[g] + ks * 32));
                asm volatile("ldmatrix.sync.aligned.m8n8.x4.shared.b16 {%0,%1,%2,%3}, [%4];"
                    : "=r"(bl[g][0]), "=r"(bl[g][1]), "=r"(bl[g][2]), "=r"(bl[g][3])
                    : "r"(sBlo + boff[g] + ks * 32));
            }
#pragma unroll
            for (int i = 0; i < 2; i++) {
                const uint32_t* ahp = (const uint32_t*)&ah[i];
                const uint32_t* alp = (const uint32_t*)&al[i];
#pragma unroll
                for (int j = 0; j < 8; j++) {
                    int g = j >> 1, s = (j & 1) * 2;
                    mma16816(d[i][j], ahp, bh[g][s], bh[g][s + 1]);
                    mma16816(d[i][j], ahp, bl[g][s], bl[g][s + 1]);
                    mma16816(d[i][j], alp, bh[g][s], bh[g][s + 1]);
                }
            }
        }
        __syncthreads();
    }

    // epilogue: write g_y (interior only) + GN2 stats
    float* dst = g_y + (size_t)b * CC * PP;
#pragma unroll
    for (int i = 0; i < 2; i++)
#pragma unroll
        for (int rh = 0; rh < 2; rh++) {
            int m = warp_m0 + 16 * i + quad + rh * 8;
            float ps = 0.f, pq = 0.f;
#pragma unroll
            for (int j = 0; j < 8; j++) {
                float v0 = d[i][j][rh * 2], v1 = d[i][j][rh * 2 + 1];
                int n = warp_n0 + 8 * j + 2 * qt;
                int pos = p0 + n;
                int r = pos / 82, q = pos - r * 82;
                bool in0 = (pos < NPAD) && r >= 1 && r <= 80 && q >= 1 && q <= 80;
                bool in1 = (pos + 1 < NPAD) && r >= 1 && r <= 80 && (q + 1) >= 1 && (q + 1) <= 80;
                if (in0) { dst[(size_t)m * PP + (r - 1) * 80 + (q - 1)] = v0; ps += v0; pq += v0 * v0; }
                if (in1) { dst[(size_t)m * PP + (r - 1) * 80 + q] = v1; ps += v1; pq += v1 * v1; }
            }
            ps += __shfl_down_sync(0xffffffffu, ps, 2);
            pq += __shfl_down_sync(0xffffffffu, pq, 2);
            ps += __shfl_down_sync(0xffffffffu, ps, 1);
            pq += __shfl_down_sync(0xffffffffu, pq, 1);
            if (qt == 0) { atomicAdd(&ssum[m], ps); atomicAdd(&ssq[m], pq); }
        }

    __syncthreads();
    if (tid < 128) {
        atomicAdd(&g_gn2_sum[b * NGG + (tid >> 4)], ssum[tid]);
        atomicAdd(&g_gn2_sq[b * NGG + (tid >> 4)], ssq[tid]);
    }
}

// ---------------- combine ----------------
__global__ __launch_bounds__(256) void k_combine(const float* __restrict__ x,
                                                 const float* __restrict__ weights,
                                                 const int* __restrict__ indices,
                                                 const float* __restrict__ g2,
                                                 const float* __restrict__ b2,
                                                 float* __restrict__ out) {
    const int blk = blockIdx.x;
    const int b = blk >> 7, c = blk & 127;
    const int idx = indices[b];
    const float wb = weights[b];
    const float sc = g_bn_scale[c], sh = g_bn_shift[c];

    float a2, c2;
    if (idx > 0) {
        int e = idx - 1;
        int g = c >> 4;
        float mean = g_gn2_mr[(b * NGG + g) * 2];
        float rstd = g_gn2_mr[(b * NGG + g) * 2 + 1];
        float ga = rstd * g2[e * CC + c];
        a2 = ga * wb;
        c2 = (b2[e * CC + c] - mean * ga) * wb;
    } else {
        a2 = wb;
        c2 = 0.f;
    }

    const size_t base = ((size_t)b * CC + c) * PP;
    const float4* sp = (const float4*)(g_s + base);
    const float4* rp = (idx > 0) ? (const float4*)(g_y + base) : (const float4*)(x + base);
    float4* op = (float4*)(out + base);

    for (int i = threadIdx.x; i < PP / 4; i += 256) {
        float4 sv = sp[i];
        float4 rv = rp[i];
        float4 o;
        float t;
        t = fmaf(sv.x, sc, sh); o.x = t * fast_sigmoid(t) + fmaf(rv.x, a2, c2);
        t = fmaf(sv.y, sc, sh); o.y = t * fast_sigmoid(t) + fmaf(rv.y, a2, c2);
        t = fmaf(sv.z, sc, sh); o.z = t * fast_sigmoid(t) + fmaf(rv.z, a2, c2);
        t = fmaf(sv.w, sc, sh); o.w = t * fast_sigmoid(t) + fmaf(rv.w, a2, c2);
        op[i] = o;
    }
}

// ---------------- launch ----------------
extern "C" void kernel_launch(void* const* d_in, const int* in_sizes, int n_in,
                              void* d_out, int out_size) {
    const float* x        = (const float*)d_in[0];
    const float* weights  = (const float*)d_in[1];
    const int*   indices  = (const int*)d_in[2];
    const float* shared_w = (const float*)d_in[3];
    const float* bn_gamma = (const float*)d_in[4];
    const float* bn_beta  = (const float*)d_in[5];
    const float* w1       = (const float*)d_in[6];
    const float* g1       = (const float*)d_in[7];
    const float* b1       = (const float*)d_in[8];
    const float* w2       = (const float*)d_in[9];
    const float* g2       = (const float*)d_in[10];
    const float* b2       = (const float*)d_in[11];
    float* out = (float*)d_out;

    cudaFuncSetAttribute(k_convg1, cudaFuncAttributeMaxDynamicSharedMemorySize, SMEM_CONV);
    cudaFuncSetAttribute(k_gemm2, cudaFuncAttributeMaxDynamicSharedMemorySize, SMEM_G2);

    k_prep<<<3985, 256>>>(x, shared_w, w1, w2);
    k_convg1<<<dim3(53, 3, BB), 256, SMEM_CONV>>>(indices);   // conv + gemm1
    k_fin1<<<1, 256>>>(bn_gamma, bn_beta);
    k_gemm2<<<dim3(53, 1, BB), 256, SMEM_G2>>>(indices, g1, b1);
    k_fin_gn2<<<1, 128>>>();
    k_combine<<<BB * CC, 256>>>(x, weights, indices, g2, b2, out);
}

// round 13
// speedup vs baseline: 2.5582x; 1.0278x over previous
#include <cuda_runtime.h>
#include <cuda_bf16.h>
#include <cstdint>

// ---------------- shapes ----------------
#define BB    16
#define CC    128
#define HIDD  256
#define PP    6400
#define NGG   8
#define EPSV  1e-5f

#define NPAD  6724      // 82*82
#define NPADT 6784      // 53 tiles * 128
#define GUARD 128
#define XROWS 7040      // GUARD + NPADT + GUARD

// smem tile geometry: [128 rows][136 bf16] = 272 B/row (conflict-free ldmatrix)
#define TROW   272
#define TILEB  34816    // 128*272

// conv halo window: rows p0-83 .. p0+210
#define XW_ROWS 294
#define XW_BYTES (XW_ROWS * TROW)      // 79968
#define SMEM_CONV (2 * XW_BYTES)       // 159936 (xh + xl windows only)
#define SMEM_G2   (2 * TILEB)          // 69632  (Bhi + Blo)

#define NT 512          // threads per MMA CTA (16 warps, 4x4 warp grid)

// ---------------- device scratch (static; allocation-free) ----------------
__device__ __align__(16) float g_s[(size_t)BB * CC * PP];
__device__ __align__(16) float g_y[(size_t)BB * CC * PP];
__device__ __align__(16) float g_h[(size_t)BB * NPADT * HIDD];   // f32 [b][pos][256]

__device__ uint4 g_xp_hi[(size_t)BB * XROWS * 16];   // [b][row][128 ci] bf16, 256B rows
__device__ uint4 g_xp_lo[(size_t)BB * XROWS * 16];

// fragment-packed weights: [tile16][ks][lane] -> one uint4 = {a0,a1,a2,a3}
__device__ uint4 g_wfc[9 * 2 * 8 * 8 * 32];    // conv: [tap][part][mt8][ks8][lane]
__device__ uint4 g_wf1[3 * 2 * 16 * 8 * 32];   // w1:   [e][part][mt16][ks8][lane]
__device__ uint4 g_wf2[3 * 2 * 8 * 16 * 32];   // w2:   [e][part][mt8][ks16][lane]

__device__ float g_bn_sum[CC], g_bn_sq[CC];
__device__ float g_bn_scale[CC], g_bn_shift[CC];
__device__ float g_gn1_sum[BB * NGG], g_gn1_sq[BB * NGG];
__device__ float g_gn1_mr[BB * NGG * 2];
__device__ float g_gn2_sum[BB * NGG], g_gn2_sq[BB * NGG];
__device__ float g_gn2_mr[BB * NGG * 2];

// ---------------- helpers ----------------
__device__ __forceinline__ uint32_t smem_u32(const void* p) {
    uint32_t a;
    asm("{ .reg .u64 t; cvta.to.shared.u64 t, %1; cvt.u32.u64 %0, t; }" : "=r"(a) : "l"(p));
    return a;
}

__device__ __forceinline__ void mma16816(float* d, const uint32_t* a, uint32_t b0, uint32_t b1) {
    asm volatile(
        "mma.sync.aligned.m16n8k16.row.col.f32.bf16.bf16.f32 "
        "{%0,%1,%2,%3}, {%4,%5,%6,%7}, {%8,%9}, {%0,%1,%2,%3};"
        : "+f"(d[0]), "+f"(d[1]), "+f"(d[2]), "+f"(d[3])
        : "r"(a[0]), "r"(a[1]), "r"(a[2]), "r"(a[3]), "r"(b0), "r"(b1));
}

// FMA-only sigmoid (no MUFU)
__device__ __forceinline__ float fast_sigmoid(float t) {
    float z = -t * 1.442695041f;
    z = fminf(fmaxf(z, -60.f), 60.f);
    float fl = floorf(z);
    float f = z - fl;
    float p = 1.5403530e-4f;
    p = fmaf(p, f, 1.3333558e-3f);
    p = fmaf(p, f, 9.6181291e-3f);
    p = fmaf(p, f, 5.5504109e-2f);
    p = fmaf(p, f, 2.4022651e-1f);
    p = fmaf(p, f, 6.9314718e-1f);
    float two_f = fmaf(p, f, 1.0f);
    float ex = __int_as_float((127 + (int)fl) << 23) * two_f;   // exp(-t)
    float d = 1.f + ex;
    float r = __int_as_float(0x7EF311C3 - __float_as_int(d));
    r = r * (2.f - d * r);
    r = r * (2.f - d * r);
    r = r * (2.f - d * r);
    return r;
}

// stage one [128 rows][256B used] tile into smem [128][272B] via cp.async (NT threads)
__device__ __forceinline__ void stage_cp(uint32_t s_dst, const char* src, int rowStride, int tid) {
#pragma unroll
    for (int it = 0; it < 4; it++) {
        int idx = it * NT + tid;           // 0..2047
        int r = idx >> 4, c = idx & 15;
        uint32_t d = s_dst + (uint32_t)(r * TROW + c * 16);
        const char* s = src + (size_t)r * rowStride + c * 16;
        asm volatile("cp.async.cg.shared.global [%0], [%1], 16;" :: "r"(d), "l"(s));
    }
}

__device__ __forceinline__ uint32_t pack2(float a, float b, int part) {
    __nv_bfloat16 ha = __float2bfloat16(a), hb = __float2bfloat16(b);
    if (part) {
        ha = __float2bfloat16(a - __bfloat162float(ha));
        hb = __float2bfloat16(b - __bfloat162float(hb));
    }
    return (uint32_t)*(uint16_t*)&ha | ((uint32_t)*(uint16_t*)&hb << 16);
}

// ============================================================================
// k_prep: pack_x (3200 blocks) + zero_xp (448) + pack_w frag-order (336) + zero (1)
// ============================================================================
__global__ __launch_bounds__(256) void k_prep(const float* __restrict__ x,
                                              const float* __restrict__ w,
                                              const float* __restrict__ w1,
                                              const float* __restrict__ w2) {
    __shared__ float t[128 * 33];
    const int bi = blockIdx.x, tid = threadIdx.x;

    if (bi < 3200) {               // ---- pack_x ----
        int b = bi / 200, p0 = (bi - b * 200) * 32;
        const float* xb = x + (size_t)b * CC * PP;
#pragma unroll
        for (int i = 0; i < 16; i++) {
            int lin = i * 256 + tid;
            int c = lin >> 5, px = lin & 31;
            t[c * 33 + px] = xb[(size_t)c * PP + p0 + px];
        }
        __syncthreads();
        __nv_bfloat16* hiA = (__nv_bfloat16*)g_xp_hi;
        __nv_bfloat16* loA = (__nv_bfloat16*)g_xp_lo;
#pragma unroll
        for (int i = 0; i < 16; i++) {
            int lin = i * 256 + tid;
            int c = tid & 127, px = (lin >> 7) & 31;
            float v = t[c * 33 + px];
            int p = p0 + px;
            int r = p / 80, q = p - r * 80;
            int pos = (r + 1) * 82 + (q + 1);
            size_t a = ((size_t)b * XROWS + GUARD + pos) * 128 + c;
            __nv_bfloat16 hi = __float2bfloat16(v);
            hiA[a] = hi;
            loA[a] = __float2bfloat16(v - __bfloat162float(hi));
        }
    } else if (bi < 3648) {        // ---- zero_xp ----
        int zbi = bi - 3200;
        int b = zbi / 28;
        int ro = (zbi - b * 28) * 256 + tid;
        if (ro >= XROWS) return;
        int pos = ro - GUARD;
        bool interior = false;
        if (pos >= 0 && pos < NPAD) {
            int r = pos / 82, q = pos - r * 82;
            interior = (r >= 1 && r <= 80 && q >= 1 && q <= 80);
        }
        if (!interior) {
            uint4 z = make_uint4(0, 0, 0, 0);
            size_t base = ((size_t)b * XROWS + ro) * 16;
#pragma unroll
            for (int j = 0; j < 16; j++) { g_xp_hi[base + j] = z; g_xp_lo[base + j] = z; }
        }
    } else if (bi < 3984) {        // ---- pack_w (fragment order) ----
        int idx = (bi - 3648) * 256 + tid;   // 0..86015
        if (idx < 36864) {                   // conv weights
            int lane = idx & 31;
            int ks = (idx >> 5) & 7, mt = (idx >> 8) & 7;
            int part = (idx >> 11) & 1, tap = idx >> 12;
            int r0 = mt * 16 + (lane >> 2), r1 = r0 + 8;
            int k0 = ks * 16 + (lane & 3) * 2;
#define WCV(r, k) w[((size_t)(r) * 128 + (k)) * 9 + tap]
            uint4 o;
            o.x = pack2(WCV(r0, k0),     WCV(r0, k0 + 1), part);
            o.y = pack2(WCV(r1, k0),     WCV(r1, k0 + 1), part);
            o.z = pack2(WCV(r0, k0 + 8), WCV(r0, k0 + 9), part);
            o.w = pack2(WCV(r1, k0 + 8), WCV(r1, k0 + 9), part);
#undef WCV
            g_wfc[idx] = o;
        } else if (idx < 61440) {            // w1
            int j = idx - 36864;
            int lane = j & 31;
            int ks = (j >> 5) & 7, mt = (j >> 8) & 15;
            int part = (j >> 12) & 1, e = j >> 13;
            int r0 = mt * 16 + (lane >> 2), r1 = r0 + 8;
            int k0 = ks * 16 + (lane & 3) * 2;
            const float* wb = w1 + (size_t)e * 32768;
#define W1V(r, k) wb[(size_t)(r) * 128 + (k)]
            uint4 o;
            o.x = pack2(W1V(r0, k0),     W1V(r0, k0 + 1), part);
            o.y = pack2(W1V(r1, k0),     W1V(r1, k0 + 1), part);
            o.z = pack2(W1V(r0, k0 + 8), W1V(r0, k0 + 9), part);
            o.w = pack2(W1V(r1, k0 + 8), W1V(r1, k0 + 9), part);
#undef W1V
            g_wf1[j] = o;
        } else {                             // w2
            int j = idx - 61440;
            int lane = j & 31;
            int kst = (j >> 5) & 15, mt = (j >> 9) & 7;
            int part = (j >> 12) & 1, e = j >> 13;
            int r0 = mt * 16 + (lane >> 2), r1 = r0 + 8;
            int k0 = kst * 16 + (lane & 3) * 2;
            const float* wb = w2 + (size_t)e * 32768;
#define W2V(r, k) wb[(size_t)(r) * 256 + (k)]
            uint4 o;
            o.x = pack2(W2V(r0, k0),     W2V(r0, k0 + 1), part);
            o.y = pack2(W2V(r1, k0),     W2V(r1, k0 + 1), part);
            o.z = pack2(W2V(r0, k0 + 8), W2V(r0, k0 + 9), part);
            o.w = pack2(W2V(r1, k0 + 8), W2V(r1, k0 + 9), part);
#undef W2V
            g_wf2[j] = o;
        }
    } else {                       // ---- zero stats ----
        if (tid < CC) { g_bn_sum[tid] = 0.f; g_bn_sq[tid] = 0.f; }
        if (tid < BB * NGG) {
            g_gn1_sum[tid] = 0.f; g_gn1_sq[tid] = 0.f;
            g_gn2_sum[tid] = 0.f; g_gn2_sq[tid] = 0.f;
        }
    }
}

// fin_bn + fin_gn1
__global__ void k_fin1(const float* __restrict__ gamma, const float* __restrict__ beta) {
    int t = threadIdx.x;   // 256
    if (t < 128) {
        const float inv = 1.f / (float)(BB * PP);
        float m = g_bn_sum[t] * inv;
        float v = g_bn_sq[t] * inv - m * m;
        float sc = gamma[t] * rsqrtf(v + EPSV);
        g_bn_scale[t] = sc;
        g_bn_shift[t] = beta[t] - m * sc;
    } else {
        int u = t - 128;
        const float inv = 1.f / (float)((HIDD / NGG) * PP);
        float m = g_gn1_sum[u] * inv;
        float v = g_gn1_sq[u] * inv - m * m;
        g_gn1_mr[2 * u] = m;
        g_gn1_mr[2 * u + 1] = rsqrtf(v + EPSV);
    }
}

__global__ void k_fin_gn2() {
    int t = threadIdx.x;
    const float inv = 1.f / (float)((CC / NGG) * PP);
    float m = g_gn2_sum[t] * inv;
    float v = g_gn2_sq[t] * inv - m * m;
    g_gn2_mr[2 * t] = m;
    g_gn2_mr[2 * t + 1] = rsqrtf(v + EPSV);
}

// ============================================================================
// merged conv3x3 + gemm1, NT=512 threads, 4x4 warp grid, warp tile 32x32.
// ============================================================================
__device__ __forceinline__ void conv_body(char* smem, float* ssum, float* ssq,
                                          const int tid, const int b, const int p0) {
    const int wid = tid >> 5, l = tid & 31;
    const uint32_t sbase = smem_u32(smem);
    const int warp_m0 = (wid & 3) * 32;
    const int warp_n0 = (wid >> 2) * 32;
    const int quad = l >> 2, qt = l & 3;
    const int mtb = (wid & 3) * 2;

    uint32_t boffr[2];
    {
        int rowB = ((l >> 4) << 3) + (l & 7);
        int colB = (l >> 3) & 1;
#pragma unroll
        for (int g = 0; g < 2; g++)
            boffr[g] = (uint32_t)((warp_n0 + g * 16 + rowB) * TROW + colB * 16);
    }

    float d[2][4][4];
#pragma unroll
    for (int i = 0; i < 2; i++)
#pragma unroll
        for (int j = 0; j < 4; j++)
#pragma unroll
            for (int k = 0; k < 4; k++) d[i][j][k] = 0.f;

    // stage x halo windows (once)
    {
        const size_t g0 = (size_t)b * XROWS + GUARD + p0 - 83;
        const char* xh = (const char*)g_xp_hi + g0 * 256;
        const char* xl = (const char*)g_xp_lo + g0 * 256;
        for (int i = tid; i < XW_ROWS * 16; i += NT) {
            int r = i >> 4, c = i & 15;
            uint32_t dof = (uint32_t)(r * TROW + c * 16);
            const size_t sof = (size_t)r * 256 + c * 16;
            asm volatile("cp.async.cg.shared.global [%0], [%1], 16;"
                         :: "r"(sbase + dof), "l"(xh + sof));
            asm volatile("cp.async.cg.shared.global [%0], [%1], 16;"
                         :: "r"(sbase + XW_BYTES + dof), "l"(xl + sof));
        }
        asm volatile("cp.async.commit_group;" ::: "memory");
        asm volatile("cp.async.wait_group 0;" ::: "memory");
    }
    if (tid < 128) { ssum[tid] = 0.f; ssq[tid] = 0.f; }
    __syncthreads();

    // barrier-free mainloop: 9 taps x 8 ks
    for (int tap = 0; tap < 9; tap++) {
        const int kh = tap / 3, kw = tap - kh * 3;
        const uint32_t winbase = (uint32_t)(((kh - 1) * 82 + (kw - 1) + 83) * TROW);
        const uint32_t xhb = sbase + winbase;
        const uint32_t xlb = sbase + XW_BYTES + winbase;
        const uint4* wfh = g_wfc + (size_t)(tap * 2) * 2048 + l;
        const uint4* wfl = wfh + 2048;

#pragma unroll
        for (int ks = 0; ks < 8; ks++) {
            uint4 ah[2], al[2];
            ah[0] = wfh[(mtb * 8 + ks) * 32];
            ah[1] = wfh[((mtb + 1) * 8 + ks) * 32];
            al[0] = wfl[(mtb * 8 + ks) * 32];
            al[1] = wfl[((mtb + 1) * 8 + ks) * 32];

            uint32_t bh[2][4], bl[2][4];
#pragma unroll
            for (int g = 0; g < 2; g++) {
                asm volatile("ldmatrix.sync.aligned.m8n8.x4.shared.b16 {%0,%1,%2,%3}, [%4];"
                    : "=r"(bh[g][0]), "=r"(bh[g][1]), "=r"(bh[g][2]), "=r"(bh[g][3])
                    : "r"(xhb + boffr[g] + ks * 32));
                asm volatile("ldmatrix.sync.aligned.m8n8.x4.shared.b16 {%0,%1,%2,%3}, [%4];"
                    : "=r"(bl[g][0]), "=r"(bl[g][1]), "=r"(bl[g][2]), "=r"(bl[g][3])
                    : "r"(xlb + boffr[g] + ks * 32));
            }
#pragma unroll
            for (int i = 0; i < 2; i++) {
                const uint32_t* ahp = (const uint32_t*)&ah[i];
                const uint32_t* alp = (const uint32_t*)&al[i];
#pragma unroll
                for (int j = 0; j < 4; j++) {
                    int g = j >> 1, s = (j & 1) * 2;
                    mma16816(d[i][j], ahp, bh[g][s], bh[g][s + 1]);
                    mma16816(d[i][j], ahp, bl[g][s], bl[g][s + 1]);
                    mma16816(d[i][j], alp, bh[g][s], bh[g][s + 1]);
                }
            }
        }
    }

    // epilogue: write g_s (interior only) + BN partial stats
    float* dst = g_s + (size_t)b * CC * PP;
#pragma unroll
    for (int i = 0; i < 2; i++)
#pragma unroll
        for (int rh = 0; rh < 2; rh++) {
            int m = warp_m0 + 16 * i + quad + rh * 8;
            float ps = 0.f, pq = 0.f;
#pragma unroll
            for (int j = 0; j < 4; j++) {
                float v0 = d[i][j][rh * 2], v1 = d[i][j][rh * 2 + 1];
                int n = warp_n0 + 8 * j + 2 * qt;
                int pos = p0 + n;
                int r = pos / 82, q = pos - r * 82;
                bool in0 = (pos < NPAD) && r >= 1 && r <= 80 && q >= 1 && q <= 80;
                bool in1 = (pos + 1 < NPAD) && r >= 1 && r <= 80 && (q + 1) >= 1 && (q + 1) <= 80;
                if (in0) { dst[(size_t)m * PP + (r - 1) * 80 + (q - 1)] = v0; ps += v0; pq += v0 * v0; }
                if (in1) { dst[(size_t)m * PP + (r - 1) * 80 + q] = v1; ps += v1; pq += v1 * v1; }
            }
            ps += __shfl_down_sync(0xffffffffu, ps, 2);
            pq += __shfl_down_sync(0xffffffffu, pq, 2);
            ps += __shfl_down_sync(0xffffffffu, ps, 1);
            pq += __shfl_down_sync(0xffffffffu, pq, 1);
            if (qt == 0) { atomicAdd(&ssum[m], ps); atomicAdd(&ssq[m], pq); }
        }

    __syncthreads();
    if (tid < 128) {
        atomicAdd(&g_bn_sum[tid], ssum[tid]);
        atomicAdd(&g_bn_sq[tid], ssq[tid]);
    }
}

__device__ __forceinline__ void gemm1_body(char* smem, float* ssum, float* ssq,
                                           const int tid, const int b, const int e,
                                           const int p0, const int m0) {
    const int wid = tid >> 5, l = tid & 31;
    const uint32_t sbase = smem_u32(smem);
    const int warp_m0 = (wid & 3) * 32;
    const int warp_n0 = (wid >> 2) * 32;
    const int quad = l >> 2, qt = l & 3;
    const int mtb = (m0 >> 4) + (wid & 3) * 2;

    uint32_t boff[2];
    {
        int rowB = ((l >> 4) << 3) + (l & 7);
        int colB = (l >> 3) & 1;
#pragma unroll
        for (int g = 0; g < 2; g++)
            boff[g] = (uint32_t)((warp_n0 + g * 16 + rowB) * TROW + colB * 16);
    }

    float d[2][4][4];
#pragma unroll
    for (int i = 0; i < 2; i++)
#pragma unroll
        for (int j = 0; j < 4; j++)
#pragma unroll
            for (int k = 0; k < 4; k++) d[i][j][k] = 0.f;

    // stage B tiles (xh, xl) once
    {
        const char* bsx_hi = (const char*)g_xp_hi + ((size_t)b * XROWS + GUARD + p0) * 256;
        const char* bsx_lo = (const char*)g_xp_lo + ((size_t)b * XROWS + GUARD + p0) * 256;
        stage_cp(sbase, bsx_hi, 256, tid);
        stage_cp(sbase + TILEB, bsx_lo, 256, tid);
        asm volatile("cp.async.commit_group;" ::: "memory");
        asm volatile("cp.async.wait_group 0;" ::: "memory");
    }
    if (tid < 128) { ssum[tid] = 0.f; ssq[tid] = 0.f; }
    __syncthreads();

    const uint4* wfh = g_wf1 + (size_t)(e * 2) * 4096 + l;
    const uint4* wfl = wfh + 4096;

#pragma unroll
    for (int ks = 0; ks < 8; ks++) {
        uint4 ah[2], al[2];
        ah[0] = wfh[(mtb * 8 + ks) * 32];
        ah[1] = wfh[((mtb + 1) * 8 + ks) * 32];
        al[0] = wfl[(mtb * 8 + ks) * 32];
        al[1] = wfl[((mtb + 1) * 8 + ks) * 32];

        uint32_t bh[2][4], bl[2][4];
#pragma unroll
        for (int g = 0; g < 2; g++) {
            asm volatile("ldmatrix.sync.aligned.m8n8.x4.shared.b16 {%0,%1,%2,%3}, [%4];"
                : "=r"(bh[g][0]), "=r"(bh[g][1]), "=r"(bh[g][2]), "=r"(bh[g][3])
                : "r"(sbase + boff[g] + ks * 32));
            asm volatile("ldmatrix.sync.aligned.m8n8.x4.shared.b16 {%0,%1,%2,%3}, [%4];"
                : "=r"(bl[g][0]), "=r"(bl[g][1]), "=r"(bl[g][2]), "=r"(bl[g][3])
                : "r"(sbase + TILEB + boff[g] + ks * 32));
        }
#pragma unroll
        for (int i = 0; i < 2; i++) {
            const uint32_t* ahp = (const uint32_t*)&ah[i];
            const uint32_t* alp = (const uint32_t*)&al[i];
#pragma unroll
            for (int j = 0; j < 4; j++) {
                int g = j >> 1, s = (j & 1) * 2;
                mma16816(d[i][j], ahp, bh[g][s], bh[g][s + 1]);
                mma16816(d[i][j], ahp, bl[g][s], bl[g][s + 1]);
                mma16816(d[i][j], alp, bh[g][s], bh[g][s + 1]);
            }
        }
    }

    // epilogue: write h f32 + GN1 stats (interior masked)
    float* hb = g_h + (size_t)b * NPADT * 256;
#pragma unroll
    for (int i = 0; i < 2; i++)
#pragma unroll
        for (int rh = 0; rh < 2; rh++) {
            int m = warp_m0 + 16 * i + quad + rh * 8;
            float ps = 0.f, pq = 0.f;
#pragma unroll
            for (int j = 0; j < 4; j++) {
                float v0 = d[i][j][rh * 2], v1 = d[i][j][rh * 2 + 1];
                int n = warp_n0 + 8 * j + 2 * qt;
                int pos = p0 + n;
                hb[(size_t)pos * 256 + m0 + m] = v0;
                hb[(size_t)(pos + 1) * 256 + m0 + m] = v1;
                int r = pos / 82, q = pos - r * 82;
                bool in0 = (pos < NPAD) && r >= 1 && r <= 80 && q >= 1 && q <= 80;
                bool in1 = (pos + 1 < NPAD) && r >= 1 && r <= 80 && (q + 1) >= 1 && (q + 1) <= 80;
                if (in0) { ps += v0; pq += v0 * v0; }
                if (in1) { ps += v1; pq += v1 * v1; }
            }
            ps += __shfl_down_sync(0xffffffffu, ps, 2);
            pq += __shfl_down_sync(0xffffffffu, pq, 2);
            ps += __shfl_down_sync(0xffffffffu, ps, 1);
            pq += __shfl_down_sync(0xffffffffu, pq, 1);
            if (qt == 0) { atomicAdd(&ssum[m], ps); atomicAdd(&ssq[m], pq); }
        }

    __syncthreads();
    if (tid < 128) {
        atomicAdd(&g_gn1_sum[b * NGG + ((m0 + tid) >> 5)], ssum[tid]);
        atomicAdd(&g_gn1_sq[b * NGG + ((m0 + tid) >> 5)], ssq[tid]);
    }
}

__global__ __launch_bounds__(NT) void k_convg1(const int* __restrict__ indices) {
    extern __shared__ __align__(16) char smem[];
    __shared__ float ssum[128], ssq[128];
    const int tid = threadIdx.x;
    const int b = blockIdx.z;
    const int p0 = blockIdx.x * 128;
    if (blockIdx.y == 0) {
        conv_body(smem, ssum, ssq, tid, b, p0);
    } else {
        int id = indices[b];
        if (id == 0) return;
        gemm1_body(smem, ssum, ssq, tid, b, id - 1, p0, (blockIdx.y - 1) * 128);
    }
}

// ============================================================================
// k_gemm2: y = w2 @ silu(GN1(h)); A-frags via LDG; B built in smem from f32 h
// ============================================================================
__global__ __launch_bounds__(NT) void k_gemm2(const int* __restrict__ indices,
                                              const float* __restrict__ g1,
                                              const float* __restrict__ b1) {
    extern __shared__ __align__(16) char smem[];
    __shared__ float ssum[128], ssq[128];
    __shared__ float sa[256], sc[256];

    const int tid = threadIdx.x, wid = tid >> 5, l = tid & 31;
    const int b = blockIdx.z;
    int id = indices[b];
    if (id == 0) return;
    const int e = id - 1;
    const int p0 = blockIdx.x * 128;

    if (tid < 128) { ssum[tid] = 0.f; ssq[tid] = 0.f; }

    const uint32_t sbase = smem_u32(smem);
    const int warp_m0 = (wid & 3) * 32;
    const int warp_n0 = (wid >> 2) * 32;
    const int quad = l >> 2, qt = l & 3;
    const int mtb = (wid & 3) * 2;

    uint32_t boff[2];
    {
        int rowB = ((l >> 4) << 3) + (l & 7);
        int colB = (l >> 3) & 1;
#pragma unroll
        for (int g = 0; g < 2; g++)
            boff[g] = (uint32_t)((warp_n0 + g * 16 + rowB) * TROW + colB * 16);
    }

    // GN1 affine coefficients
    if (tid < 256) {
        int k = tid;
        int gg = k >> 5;
        float mean = g_gn1_mr[(b * NGG + gg) * 2];
        float rstd = g_gn1_mr[(b * NGG + gg) * 2 + 1];
        float a = rstd * g1[e * 256 + k];
        sa[k] = a;
        sc[k] = b1[e * 256 + k] - mean * a;
    }
    __syncthreads();

    float d[2][4][4];
#pragma unroll
    for (int i = 0; i < 2; i++)
#pragma unroll
        for (int j = 0; j < 4; j++)
#pragma unroll
            for (int k = 0; k < 4; k++) d[i][j][k] = 0.f;

    const float* hb = g_h + (size_t)b * NPADT * 256;
    const uint32_t sBhi = sbase;
    const uint32_t sBlo = sbase + TILEB;
    const uint4* wfh = g_wf2 + (size_t)(e * 2) * 4096 + l;
    const uint4* wfl = wfh + 4096;

    for (int kh = 0; kh < 2; kh++) {
        // build B_hi/B_lo: affine + silu + split
#pragma unroll
        for (int it = 0; it < 8; it++) {
            int j = it * NT + tid;         // 0..4095 float4 jobs
            int row = j >> 5, c4 = j & 31;
            float4 v = *(const float4*)(hb + (size_t)(p0 + row) * 256 + kh * 128 + c4 * 4);
            int k0 = kh * 128 + c4 * 4;
            float s0, s1, s2, s3, t;
            t = fmaf(v.x, sa[k0],     sc[k0]);     s0 = t * fast_sigmoid(t);
            t = fmaf(v.y, sa[k0 + 1], sc[k0 + 1]); s1 = t * fast_sigmoid(t);
            t = fmaf(v.z, sa[k0 + 2], sc[k0 + 2]); s2 = t * fast_sigmoid(t);
            t = fmaf(v.w, sa[k0 + 3], sc[k0 + 3]); s3 = t * fast_sigmoid(t);
            __nv_bfloat16 h0 = __float2bfloat16(s0), h1 = __float2bfloat16(s1);
            __nv_bfloat16 h2 = __float2bfloat16(s2), h3 = __float2bfloat16(s3);
            __nv_bfloat16 l0 = __float2bfloat16(s0 - __bfloat162float(h0));
            __nv_bfloat16 l1 = __float2bfloat16(s1 - __bfloat162float(h1));
            __nv_bfloat16 l2 = __float2bfloat16(s2 - __bfloat162float(h2));
            __nv_bfloat16 l3 = __float2bfloat16(s3 - __bfloat162float(h3));
            uint32_t hp0 = (uint32_t)*(uint16_t*)&h0 | ((uint32_t)*(uint16_t*)&h1 << 16);
            uint32_t hp1 = (uint32_t)*(uint16_t*)&h2 | ((uint32_t)*(uint16_t*)&h3 << 16);
            uint32_t lp0 = (uint32_t)*(uint16_t*)&l0 | ((uint32_t)*(uint16_t*)&l1 << 16);
            uint32_t lp1 = (uint32_t)*(uint16_t*)&l2 | ((uint32_t)*(uint16_t*)&l3 << 16);
            uint32_t off = (uint32_t)(row * TROW + c4 * 8);
            asm volatile("st.shared.v2.b32 [%0], {%1,%2};" :: "r"(sBhi + off), "r"(hp0), "r"(hp1));
            asm volatile("st.shared.v2.b32 [%0], {%1,%2};" :: "r"(sBlo + off), "r"(lp0), "r"(lp1));
        }
        __syncthreads();

#pragma unroll
        for (int ks = 0; ks < 8; ks++) {
            const int kstot = kh * 8 + ks;
            uint4 ah[2], al[2];
            ah[0] = wfh[(mtb * 16 + kstot) * 32];
            ah[1] = wfh[((mtb + 1) * 16 + kstot) * 32];
            al[0] = wfl[(mtb * 16 + kstot) * 32];
            al[1] = wfl[((mtb + 1) * 16 + kstot) * 32];

            uint32_t bh[2][4], bl[2][4];
#pragma unroll
            for (int g = 0; g < 2; g++) {
                asm volatile("ldmatrix.sync.aligned.m8n8.x4.shared.b16 {%0,%1,%2,%3}, [%4];"
                    : "=r"(bh[g][0]), "=r"(bh[g][1]), "=r"(bh[g][2]), "=r"(bh[g][3])
                    : "r"(sBhi + boff[g] + ks * 32));
                asm volatile("ldmatrix.sync.aligned.m8n8.x4.shared.b16 {%0,%1,%2,%3}, [%4];"
                    : "=r"(bl[g][0]), "=r"(bl[g][1]), "=r"(bl[g][2]), "=r"(bl[g][3])
                    : "r"(sBlo + boff[g] + ks * 32));
            }
#pragma unroll
            for (int i = 0; i < 2; i++) {
                const uint32_t* ahp = (const uint32_t*)&ah[i];
                const uint32_t* alp = (const uint32_t*)&al[i];
#pragma unroll
                for (int j = 0; j < 4; j++) {
                    int g = j >> 1, s = (j & 1) * 2;
                    mma16816(d[i][j], ahp, bh[g][s], bh[g][s + 1]);
                    mma16816(d[i][j], ahp, bl[g][s], bl[g][s + 1]);
                    mma16816(d[i][j], alp, bh[g][s], bh[g][s + 1]);
                }
            }
        }
        __syncthreads();
    }

    // epilogue: write g_y (interior only) + GN2 stats
    float* dst = g_y + (size_t)b * CC * PP;
#pragma unroll
    for (int i = 0; i < 2; i++)
#pragma unroll
        for (int rh = 0; rh < 2; rh++) {
            int m = warp_m0 + 16 * i + quad + rh * 8;
            float ps = 0.f, pq = 0.f;
#pragma unroll
            for (int j = 0; j < 4; j++) {
                float v0 = d[i][j][rh * 2], v1 = d[i][j][rh * 2 + 1];
                int n = warp_n0 + 8 * j + 2 * qt;
                int pos = p0 + n;
                int r = pos / 82, q = pos - r * 82;
                bool in0 = (pos < NPAD) && r >= 1 && r <= 80 && q >= 1 && q <= 80;
                bool in1 = (pos + 1 < NPAD) && r >= 1 && r <= 80 && (q + 1) >= 1 && (q + 1) <= 80;
                if (in0) { dst[(size_t)m * PP + (r - 1) * 80 + (q - 1)] = v0; ps += v0; pq += v0 * v0; }
                if (in1) { dst[(size_t)m * PP + (r - 1) * 80 + q] = v1; ps += v1; pq += v1 * v1; }
            }
            ps += __shfl_down_sync(0xffffffffu, ps, 2);
            pq += __shfl_down_sync(0xffffffffu, pq, 2);
            ps += __shfl_down_sync(0xffffffffu, ps, 1);
            pq += __shfl_down_sync(0xffffffffu, pq, 1);
            if (qt == 0) { atomicAdd(&ssum[m], ps); atomicAdd(&ssq[m], pq); }
        }

    __syncthreads();
    if (tid < 128) {
        atomicAdd(&g_gn2_sum[b * NGG + (tid >> 4)], ssum[tid]);
        atomicAdd(&g_gn2_sq[b * NGG + (tid >> 4)], ssq[tid]);
    }
}

// ---------------- combine ----------------
__global__ __launch_bounds__(256) void k_combine(const float* __restrict__ x,
                                                 const float* __restrict__ weights,
                                                 const int* __restrict__ indices,
                                                 const float* __restrict__ g2,
                                                 const float* __restrict__ b2,
                                                 float* __restrict__ out) {
    const int blk = blockIdx.x;
    const int b = blk >> 7, c = blk & 127;
    const int idx = indices[b];
    const float wb = weights[b];
    const float sc = g_bn_scale[c], sh = g_bn_shift[c];

    float a2, c2;
    if (idx > 0) {
        int e = idx - 1;
        int g = c >> 4;
        float mean = g_gn2_mr[(b * NGG + g) * 2];
        float rstd = g_gn2_mr[(b * NGG + g) * 2 + 1];
        float ga = rstd * g2[e * CC + c];
        a2 = ga * wb;
        c2 = (b2[e * CC + c] - mean * ga) * wb;
    } else {
        a2 = wb;
        c2 = 0.f;
    }

    const size_t base = ((size_t)b * CC + c) * PP;
    const float4* sp = (const float4*)(g_s + base);
    const float4* rp = (idx > 0) ? (const float4*)(g_y + base) : (const float4*)(x + base);
    float4* op = (float4*)(out + base);

    for (int i = threadIdx.x; i < PP / 4; i += 256) {
        float4 sv = sp[i];
        float4 rv = rp[i];
        float4 o;
        float t;
        t = fmaf(sv.x, sc, sh); o.x = t * fast_sigmoid(t) + fmaf(rv.x, a2, c2);
        t = fmaf(sv.y, sc, sh); o.y = t * fast_sigmoid(t) + fmaf(rv.y, a2, c2);
        t = fmaf(sv.z, sc, sh); o.z = t * fast_sigmoid(t) + fmaf(rv.z, a2, c2);
        t = fmaf(sv.w, sc, sh); o.w = t * fast_sigmoid(t) + fmaf(rv.w, a2, c2);
        op[i] = o;
    }
}

// ---------------- launch ----------------
extern "C" void kernel_launch(void* const* d_in, const int* in_sizes, int n_in,
                              void* d_out, int out_size) {
    const float* x        = (const float*)d_in[0];
    const float* weights  = (const float*)d_in[1];
    const int*   indices  = (const int*)d_in[2];
    const float* shared_w = (const float*)d_in[3];
    const float* bn_gamma = (const float*)d_in[4];
    const float* bn_beta  = (const float*)d_in[5];
    const float* w1       = (const float*)d_in[6];
    const float* g1       = (const float*)d_in[7];
    const float* b1       = (const float*)d_in[8];
    const float* w2       = (const float*)d_in[9];
    const float* g2       = (const float*)d_in[10];
    const float* b2       = (const float*)d_in[11];
    float* out = (float*)d_out;

    cudaFuncSetAttribute(k_convg1, cudaFuncAttributeMaxDynamicSharedMemorySize, SMEM_CONV);
    cudaFuncSetAttribute(k_gemm2, cudaFuncAttributeMaxDynamicSharedMemorySize, SMEM_G2);

    k_prep<<<3985, 256>>>(x, shared_w, w1, w2);
    k_convg1<<<dim3(53, 3, BB), NT, SMEM_CONV>>>(indices);    // conv + gemm1
    k_fin1<<<1, 256>>>(bn_gamma, bn_beta);
    k_gemm2<<<dim3(53, 1, BB), NT, SMEM_G2>>>(indices, g1, b1);
    k_fin_gn2<<<1, 128>>>();
    k_combine<<<BB * CC, 256>>>(x, weights, indices, g2, b2, out);
}